// round 6
// baseline (speedup 1.0000x reference)
#include <cuda_runtime.h>
#include <cuda_bf16.h>
#include <cuda_fp16.h>
#include <math.h>
#include <stdint.h>

typedef unsigned long long u64;

#define B_   4
#define T_   2048
#define C_   2048
#define NH   16
#define NKV  4
#define HD   128
#define KVD  (NKV*HD)   // 512
#define M_   (B_*T_)    // 8192

// ---------------- scratch (__device__ globals; no allocs allowed) ----------
__device__ float g_q[(size_t)M_ * C_];
__device__ float g_k[(size_t)M_ * KVD];
__device__ float g_v[(size_t)M_ * KVD];

__device__ __nv_bfloat16 s_xh[(size_t)M_ * C_],  s_xl[(size_t)M_ * C_];
__device__ __nv_bfloat16 s_yh[(size_t)M_ * C_],  s_yl[(size_t)M_ * C_];
__device__ __nv_bfloat16 s_wqh[(size_t)C_ * C_], s_wql[(size_t)C_ * C_];
__device__ __nv_bfloat16 s_wkh[(size_t)KVD * C_], s_wkl[(size_t)KVD * C_];
__device__ __nv_bfloat16 s_wvh[(size_t)KVD * C_], s_wvl[(size_t)KVD * C_];
__device__ __nv_bfloat16 s_woh[(size_t)C_ * C_], s_wol[(size_t)C_ * C_];

// ---------------- helpers ---------------------------------------------------
__device__ __forceinline__ uint32_t smem_u32(const void* p) {
    uint32_t a;
    asm("{ .reg .u64 t; cvta.to.shared.u64 t, %1; cvt.u32.u64 %0, t; }"
        : "=r"(a) : "l"(p));
    return a;
}
__device__ __forceinline__ void ldsm4(uint32_t* r, uint32_t addr) {
    asm volatile("ldmatrix.sync.aligned.m8n8.x4.shared.b16 {%0,%1,%2,%3}, [%4];"
                 : "=r"(r[0]), "=r"(r[1]), "=r"(r[2]), "=r"(r[3]) : "r"(addr));
}
__device__ __forceinline__ void ldsm4t(uint32_t* r, uint32_t addr) {
    asm volatile("ldmatrix.sync.aligned.m8n8.x4.trans.shared.b16 {%0,%1,%2,%3}, [%4];"
                 : "=r"(r[0]), "=r"(r[1]), "=r"(r[2]), "=r"(r[3]) : "r"(addr));
}
__device__ __forceinline__ void mma16816(float* c, const uint32_t* a,
                                         const uint32_t* b) {
    asm volatile(
        "mma.sync.aligned.m16n8k16.row.col.f32.bf16.bf16.f32 "
        "{%0,%1,%2,%3}, {%4,%5,%6,%7}, {%8,%9}, {%0,%1,%2,%3};"
        : "+f"(c[0]), "+f"(c[1]), "+f"(c[2]), "+f"(c[3])
        : "r"(a[0]), "r"(a[1]), "r"(a[2]), "r"(a[3]), "r"(b[0]), "r"(b[1]));
}
__device__ __forceinline__ void mma16816h(float* c, const uint32_t* a,
                                          const uint32_t* b) {
    asm volatile(
        "mma.sync.aligned.m16n8k16.row.col.f32.f16.f16.f32 "
        "{%0,%1,%2,%3}, {%4,%5,%6,%7}, {%8,%9}, {%0,%1,%2,%3};"
        : "+f"(c[0]), "+f"(c[1]), "+f"(c[2]), "+f"(c[3])
        : "r"(a[0]), "r"(a[1]), "r"(a[2]), "r"(a[3]), "r"(b[0]), "r"(b[1]));
}
__device__ __forceinline__ void cpa16(uint32_t dst, const void* src) {
    asm volatile("cp.async.cg.shared.global [%0], [%1], 16;"
                 :: "r"(dst), "l"(src));
}
__device__ __forceinline__ void cp_commit() {
    asm volatile("cp.async.commit_group;");
}
__device__ __forceinline__ void cp_wait0() {
    asm volatile("cp.async.wait_group 0;");
}
__device__ __forceinline__ void cp_wait1() {
    asm volatile("cp.async.wait_group 1;");
}

// ---------------------------------------------------------------------------
// split: fp32 -> (bf16 hi, bf16 lo), vectorized x4
// ---------------------------------------------------------------------------
__global__ void split_kernel(const float* __restrict__ X,
                             __nv_bfloat16* __restrict__ H,
                             __nv_bfloat16* __restrict__ L, int n4)
{
    int i = blockIdx.x * blockDim.x + threadIdx.x;
    if (i >= n4) return;
    float4 v = ((const float4*)X)[i];
    float vv[4] = {v.x, v.y, v.z, v.w};
    __nv_bfloat162 h0, h1, l0, l1;
    __nv_bfloat16 h[4], l[4];
#pragma unroll
    for (int j = 0; j < 4; j++) {
        h[j] = __float2bfloat16(vv[j]);
        l[j] = __float2bfloat16(vv[j] - __bfloat162float(h[j]));
    }
    h0.x = h[0]; h0.y = h[1]; h1.x = h[2]; h1.y = h[3];
    l0.x = l[0]; l0.y = l[1]; l1.x = l[2]; l1.y = l[3];
    ((__nv_bfloat162*)H)[2 * i]     = h0;
    ((__nv_bfloat162*)H)[2 * i + 1] = h1;
    ((__nv_bfloat162*)L)[2 * i]     = l0;
    ((__nv_bfloat162*)L)[2 * i + 1] = l1;
}

// ---------------------------------------------------------------------------
// transpose + split: W[K,N] fp32 -> Th/Tl [N,K] bf16
// ---------------------------------------------------------------------------
__global__ void transpose_split_kernel(const float* __restrict__ W,
                                       __nv_bfloat16* __restrict__ Th,
                                       __nv_bfloat16* __restrict__ Tl,
                                       int K, int N)
{
    __shared__ float t[32][33];
    int n0 = blockIdx.x * 32, k0 = blockIdx.y * 32;
    int tx = threadIdx.x, ty = threadIdx.y;  // 32 x 8
#pragma unroll
    for (int j = 0; j < 4; j++)
        t[ty + 8 * j][tx] = W[(size_t)(k0 + ty + 8 * j) * N + n0 + tx];
    __syncthreads();
#pragma unroll
    for (int j = 0; j < 4; j++) {
        float v = t[tx][ty + 8 * j];
        __nv_bfloat16 h = __float2bfloat16(v);
        __nv_bfloat16 l = __float2bfloat16(v - __bfloat162float(h));
        size_t o = (size_t)(n0 + ty + 8 * j) * K + k0 + tx;
        Th[o] = h;
        Tl[o] = l;
    }
}

// ---------------------------------------------------------------------------
// bf16-split GEMM via mma.sync, 2-stage cp.async pipeline.
// C[M,N] = A[M,K] @ W[K,N]; A split (Ah/Al [M,K]); W split+T (Bh/Bl [N,K]).
// CTA 128x128, BK=32, 8 warps (2m x 4n), warp tile 64x32.
// Dynamic smem: 2 stages x (Ah,Al,Bh,Bl) x 128row x 40-elem stride = 80 KB.
// ---------------------------------------------------------------------------
#define SAS 40
#define GBUF  (128 * SAS * 2)      // bytes per tile buffer (10240)
#define GSTG  (4 * GBUF)           // bytes per stage (40960)
#define GEMM_SMEM (2 * GSTG)       // 81920

extern __shared__ char dynsm[];

__global__ __launch_bounds__(256) void gemm_mma(
    const __nv_bfloat16* __restrict__ Ah, const __nv_bfloat16* __restrict__ Al,
    const __nv_bfloat16* __restrict__ Bh, const __nv_bfloat16* __restrict__ Bl,
    float* __restrict__ C, int N, int K)
{
    const int tid = threadIdx.x;
    const int lane = tid & 31, wid = tid >> 5;
    const int wm = wid & 1, wn = wid >> 1;
    const int m0 = blockIdx.y * 128, n0 = blockIdx.x * 128;

    const uint32_t usm = smem_u32(dynsm);

    // ---- loader mapping: thread -> row(tid>>1), 16-elem half(tid&1) ----
    const int ldrow = tid >> 1, ldhalf = tid & 1;
    const __nv_bfloat16* gAh = Ah + (size_t)(m0 + ldrow) * K + ldhalf * 16;
    const __nv_bfloat16* gAl = Al + (size_t)(m0 + ldrow) * K + ldhalf * 16;
    const __nv_bfloat16* gBh = Bh + (size_t)(n0 + ldrow) * K + ldhalf * 16;
    const __nv_bfloat16* gBl = Bl + (size_t)(n0 + ldrow) * K + ldhalf * 16;
    const uint32_t dst0 = usm + (ldrow * SAS + ldhalf * 16) * 2;

    // ---- ldmatrix per-thread offsets (within one tile buffer) ----
    const int mid = lane >> 3, rin = lane & 7;
    const uint32_t aoff =
        ((wm * 64 + (mid & 1) * 8 + rin) * SAS + (mid >> 1) * 8) * 2;
    const uint32_t boff =
        ((wn * 32 + (mid >> 1) * 8 + rin) * SAS + (mid & 1) * 8) * 2;

    float acc[4][4][4];
#pragma unroll
    for (int mt = 0; mt < 4; mt++)
#pragma unroll
        for (int nt = 0; nt < 4; nt++)
#pragma unroll
            for (int j = 0; j < 4; j++) acc[mt][nt][j] = 0.0f;

#define GLOAD_ASYNC(stg, k0)                                             \
    {                                                                    \
        uint32_t d = dst0 + (stg) * GSTG;                                \
        cpa16(d,                 gAh + (k0));                            \
        cpa16(d + 16,            gAh + (k0) + 8);                        \
        cpa16(d + GBUF,          gAl + (k0));                            \
        cpa16(d + GBUF + 16,     gAl + (k0) + 8);                        \
        cpa16(d + 2 * GBUF,      gBh + (k0));                            \
        cpa16(d + 2 * GBUF + 16, gBh + (k0) + 8);                        \
        cpa16(d + 3 * GBUF,      gBl + (k0));                            \
        cpa16(d + 3 * GBUF + 16, gBl + (k0) + 8);                        \
        cp_commit();                                                     \
    }

    GLOAD_ASYNC(0, 0);

    const int nch = K / 32;
    for (int ch = 0; ch < nch; ch++) {
        const bool more = (ch + 1 < nch);
        if (more) GLOAD_ASYNC((ch + 1) & 1, (ch + 1) * 32);
        if (more) cp_wait1(); else cp_wait0();
        __syncthreads();

        const uint32_t sb = usm + (ch & 1) * GSTG;
        const uint32_t uAh = sb + aoff,           uAl = sb + GBUF + aoff;
        const uint32_t uBh = sb + 2 * GBUF + boff, uBl = sb + 3 * GBUF + boff;

#pragma unroll
        for (int ks = 0; ks < 2; ks++) {
            uint32_t fah[4][4], fal[4][4], fbh[2][4], fbl[2][4];
#pragma unroll
            for (int mt = 0; mt < 4; mt++) {
                ldsm4(fah[mt], uAh + mt * (16 * SAS * 2) + ks * 32);
                ldsm4(fal[mt], uAl + mt * (16 * SAS * 2) + ks * 32);
            }
#pragma unroll
            for (int np = 0; np < 2; np++) {
                ldsm4(fbh[np], uBh + np * (16 * SAS * 2) + ks * 32);
                ldsm4(fbl[np], uBl + np * (16 * SAS * 2) + ks * 32);
            }
#pragma unroll
            for (int mt = 0; mt < 4; mt++)
#pragma unroll
                for (int nt = 0; nt < 4; nt++) {
                    const uint32_t* b_h = &fbh[nt >> 1][(nt & 1) * 2];
                    const uint32_t* b_l = &fbl[nt >> 1][(nt & 1) * 2];
                    mma16816(acc[mt][nt], fah[mt], b_h);
                    mma16816(acc[mt][nt], fal[mt], b_h);
                    mma16816(acc[mt][nt], fah[mt], b_l);
                }
        }
        __syncthreads();
    }
#undef GLOAD_ASYNC

    const int g = lane >> 2, tg = lane & 3;
#pragma unroll
    for (int mt = 0; mt < 4; mt++) {
        const int mrow = m0 + wm * 64 + mt * 16 + g;
#pragma unroll
        for (int nt = 0; nt < 4; nt++) {
            const int ncol = n0 + wn * 32 + nt * 8 + tg * 2;
            float2 v0 = {acc[mt][nt][0], acc[mt][nt][1]};
            float2 v1 = {acc[mt][nt][2], acc[mt][nt][3]};
            *(float2*)(C + (size_t)mrow * N + ncol)       = v0;
            *(float2*)(C + (size_t)(mrow + 8) * N + ncol) = v1;
        }
    }
}

// ---------------------------------------------------------------------------
// RoPE (matches reference)
// ---------------------------------------------------------------------------
__global__ void rope_kernel(float* __restrict__ X, const int* __restrict__ posp,
                            int nheads, int total)
{
    int idx = blockIdx.x * blockDim.x + threadIdx.x;
    if (idx >= total) return;
    int p   = idx & 63;
    int h   = (idx >> 6) % nheads;
    int row = idx / (64 * nheads);
    int t   = row % T_;
    float pos = (float)(posp[0] + t);

    float* base = X + (size_t)row * (nheads * HD) + h * HD;
    float x1 = base[p];
    float x2 = base[p + 64];

    const float LN1E4 = 9.210340371976184f;
    float e1 = (float)(2 * (p >> 1)) * (1.0f / 128.0f);
    float e2 = e1 + 0.5f;
    float f1 = __expf(-e1 * LN1E4);
    float f2 = __expf(-e2 * LN1E4);
    float a1 = pos * f1;
    float a2 = pos * f2;

    base[p]      = x1 * cosf(a1) - x2 * sinf(a1);
    base[p + 64] = x2 * cosf(a2) + x1 * sinf(a2);
}

// ---------------------------------------------------------------------------
// Flash attention on mma.sync (unchanged from R5 — proven)
// ---------------------------------------------------------------------------
#define SKP 136
#define FL_SMEM (3 * 64 * SKP * 2)

__global__ __launch_bounds__(256) void flash_mma(
    const float* __restrict__ Q, const float* __restrict__ Kg,
    const float* __restrict__ Vg,
    __nv_bfloat16* __restrict__ Yh, __nv_bfloat16* __restrict__ Yl)
{
    __nv_bfloat16* sKh = (__nv_bfloat16*)dynsm;
    __nv_bfloat16* sKl = sKh + 64 * SKP;
    __half*        sVh = (__half*)(sKl + 64 * SKP);

    const int tid = threadIdx.x, lane = tid & 31, w = tid >> 5;
    const int qb = blockIdx.x, h = blockIdx.y, b = blockIdx.z;
    const int kvh = h >> 2;
    const int g = lane >> 2, tg = lane & 3;
    const int mid = lane >> 3, rin = lane & 7;
    const int qrow0 = qb * 128 + w * 16;

    uint32_t qh[8][4], ql[8][4];
    {
        const float* Qb = Q + ((size_t)b * T_ + qrow0) * C_ + h * HD;
#pragma unroll
        for (int kc = 0; kc < 8; kc++) {
#pragma unroll
            for (int fr = 0; fr < 4; fr++) {
                int r = g + (fr & 1) * 8;
                int c = kc * 16 + tg * 2 + (fr >> 1) * 8;
                float2 v = *(const float2*)(Qb + (size_t)r * C_ + c);
                __nv_bfloat162 hi = __float22bfloat162_rn(v);
                float2 hf = __bfloat1622float2(hi);
                __nv_bfloat162 lo = __float22bfloat162_rn(
                    make_float2(v.x - hf.x, v.y - hf.y));
                qh[kc][fr] = *reinterpret_cast<uint32_t*>(&hi);
                ql[kc][fr] = *reinterpret_cast<uint32_t*>(&lo);
            }
        }
    }

    float o[16][4];
#pragma unroll
    for (int nt = 0; nt < 16; nt++)
#pragma unroll
        for (int j = 0; j < 4; j++) o[nt][j] = 0.0f;
    float m0 = -INFINITY, m1 = -INFINITY, l0 = 0.0f, l1 = 0.0f;

    const float cscale = 0.08838834764831845f;
    const int rg0 = qrow0 + g, rg1 = rg0 + 8;
    const int ktmax = 2 * qb + 2;

    const float* Kt0 = Kg + (size_t)b * T_ * KVD + kvh * HD;
    const float* Vt0 = Vg + (size_t)b * T_ * KVD + kvh * HD;

    const uint32_t uKh = smem_u32(sKh), uKl = smem_u32(sKl), uVh = smem_u32(sVh);
    const uint32_t kfrag = (((mid >> 1) * 8 + rin) * SKP + (mid & 1) * 8) * 2;
    const uint32_t vfrag = (((mid & 1) * 8 + rin) * SKP + (mid >> 1) * 8) * 2;

    for (int kt = 0; kt < ktmax; kt++) {
        __syncthreads();
        {
            const float* Kt = Kt0 + (size_t)kt * 64 * KVD;
            const float* Vt = Vt0 + (size_t)kt * 64 * KVD;
#pragma unroll
            for (int it = 0; it < 8; it++) {
                int i = tid + it * 256;
                int r = i >> 5, c4 = (i & 31) << 2;
                float4 kv = *(const float4*)(Kt + (size_t)r * KVD + c4);
                __nv_bfloat162 h0 = __float22bfloat162_rn(make_float2(kv.x, kv.y));
                __nv_bfloat162 h1 = __float22bfloat162_rn(make_float2(kv.z, kv.w));
                float2 f0 = __bfloat1622float2(h0), f1 = __bfloat1622float2(h1);
                __nv_bfloat162 l0v = __float22bfloat162_rn(
                    make_float2(kv.x - f0.x, kv.y - f0.y));
                __nv_bfloat162 l1v = __float22bfloat162_rn(
                    make_float2(kv.z - f1.x, kv.w - f1.y));
                *(uint32_t*)(sKh + r * SKP + c4)     = *(uint32_t*)&h0;
                *(uint32_t*)(sKh + r * SKP + c4 + 2) = *(uint32_t*)&h1;
                *(uint32_t*)(sKl + r * SKP + c4)     = *(uint32_t*)&l0v;
                *(uint32_t*)(sKl + r * SKP + c4 + 2) = *(uint32_t*)&l1v;
                float4 vv = *(const float4*)(Vt + (size_t)r * KVD + c4);
                __half2 v0 = __floats2half2_rn(vv.x, vv.y);
                __half2 v1 = __floats2half2_rn(vv.z, vv.w);
                *(uint32_t*)(sVh + r * SKP + c4)     = *(uint32_t*)&v0;
                *(uint32_t*)(sVh + r * SKP + c4 + 2) = *(uint32_t*)&v1;
            }
        }
        __syncthreads();

        if (kt * 64 > qrow0 + 15) continue;
        const bool needmask = (kt * 64 + 63 > qrow0);

        float s[8][4];
#pragma unroll
        for (int nt = 0; nt < 8; nt++)
#pragma unroll
            for (int j = 0; j < 4; j++) s[nt][j] = 0.0f;

#pragma unroll
        for (int kc = 0; kc < 8; kc++) {
            uint32_t bt[4][4];
#pragma unroll
            for (int nt2 = 0; nt2 < 4; nt2++)
                ldsm4(bt[nt2], uKh + kfrag + (nt2 * 16 * SKP + kc * 16) * 2);
#pragma unroll
            for (int nt = 0; nt < 8; nt++) {
                const uint32_t* bb = &bt[nt >> 1][(nt & 1) * 2];
                mma16816(s[nt], qh[kc], bb);
                mma16816(s[nt], ql[kc], bb);
            }
#pragma unroll
            for (int nt2 = 0; nt2 < 4; nt2++)
                ldsm4(bt[nt2], uKl + kfrag + (nt2 * 16 * SKP + kc * 16) * 2);
#pragma unroll
            for (int nt = 0; nt < 8; nt++)
                mma16816(s[nt], qh[kc], &bt[nt >> 1][(nt & 1) * 2]);
        }

#pragma unroll
        for (int nt = 0; nt < 8; nt++) {
#pragma unroll
            for (int j = 0; j < 4; j++) s[nt][j] *= cscale;
            if (needmask) {
                int c0 = kt * 64 + nt * 8 + tg * 2;
                if (c0 > rg0)     s[nt][0] = -1e30f;
                if (c0 + 1 > rg0) s[nt][1] = -1e30f;
                if (c0 > rg1)     s[nt][2] = -1e30f;
                if (c0 + 1 > rg1) s[nt][3] = -1e30f;
            }
        }

        float mn0 = m0, mn1 = m1;
#pragma unroll
        for (int nt = 0; nt < 8; nt++) {
            mn0 = fmaxf(mn0, fmaxf(s[nt][0], s[nt][1]));
            mn1 = fmaxf(mn1, fmaxf(s[nt][2], s[nt][3]));
        }
        mn0 = fmaxf(mn0, __shfl_xor_sync(0xffffffffu, mn0, 1));
        mn0 = fmaxf(mn0, __shfl_xor_sync(0xffffffffu, mn0, 2));
        mn1 = fmaxf(mn1, __shfl_xor_sync(0xffffffffu, mn1, 1));
        mn1 = fmaxf(mn1, __shfl_xor_sync(0xffffffffu, mn1, 2));
        float fac0 = __expf(m0 - mn0), fac1 = __expf(m1 - mn1);
        m0 = mn0; m1 = mn1;

        uint32_t pa[4][4];
        float ps0 = 0.0f, ps1 = 0.0f;
#pragma unroll
        for (int kk = 0; kk < 4; kk++) {
            int nt = 2 * kk;
            float p00 = __expf(s[nt][0] - m0),     p01 = __expf(s[nt][1] - m0);
            float p02 = __expf(s[nt][2] - m1),     p03 = __expf(s[nt][3] - m1);
            float p10 = __expf(s[nt + 1][0] - m0), p11 = __expf(s[nt + 1][1] - m0);
            float p12 = __expf(s[nt + 1][2] - m1), p13 = __expf(s[nt + 1][3] - m1);
            ps0 += p00 + p01 + p10 + p11;
            ps1 += p02 + p03 + p12 + p13;
            __half2 a0 = __floats2half2_rn(p00, p01);
            __half2 a1 = __floats2half2_rn(p02, p03);
            __half2 a2 = __floats2half2_rn(p10, p11);
            __half2 a3 = __floats2half2_rn(p12, p13);
            pa[kk][0] = *(uint32_t*)&a0;
            pa[kk][1] = *(uint32_t*)&a1;
            pa[kk][2] = *(uint32_t*)&a2;
            pa[kk][3] = *(uint32_t*)&a3;
        }
        l0 = l0 * fac0 + ps0;
        l1 = l1 * fac1 + ps1;

#pragma unroll
        for (int nt = 0; nt < 16; nt++) {
            o[nt][0] *= fac0; o[nt][1] *= fac0;
            o[nt][2] *= fac1; o[nt][3] *= fac1;
        }

#pragma unroll
        for (int kk = 0; kk < 4; kk++) {
            uint32_t vb[8][4];
#pragma unroll
            for (int np = 0; np < 8; np++)
                ldsm4t(vb[np], uVh + vfrag + (kk * 16 * SKP + np * 16) * 2);
#pragma unroll
            for (int nt = 0; nt < 16; nt++)
                mma16816h(o[nt], pa[kk], &vb[nt >> 1][(nt & 1) * 2]);
        }
    }

    l0 += __shfl_xor_sync(0xffffffffu, l0, 1);
    l0 += __shfl_xor_sync(0xffffffffu, l0, 2);
    l1 += __shfl_xor_sync(0xffffffffu, l1, 1);
    l1 += __shfl_xor_sync(0xffffffffu, l1, 2);
    float inv0 = 1.0f / l0, inv1 = 1.0f / l1;

    size_t row0 = (size_t)b * T_ + rg0;
    size_t row1 = (size_t)b * T_ + rg1;
#pragma unroll
    for (int nt = 0; nt < 16; nt++) {
        int col = h * HD + nt * 8 + tg * 2;
        float2 v0 = {o[nt][0] * inv0, o[nt][1] * inv0};
        float2 v1 = {o[nt][2] * inv1, o[nt][3] * inv1};
        __nv_bfloat162 h0 = __float22bfloat162_rn(v0);
        __nv_bfloat162 h1 = __float22bfloat162_rn(v1);
        float2 f0 = __bfloat1622float2(h0), f1 = __bfloat1622float2(h1);
        __nv_bfloat162 e0 = __float22bfloat162_rn(make_float2(v0.x - f0.x, v0.y - f0.y));
        __nv_bfloat162 e1 = __float22bfloat162_rn(make_float2(v1.x - f1.x, v1.y - f1.y));
        *(uint32_t*)(Yh + row0 * C_ + col) = *(uint32_t*)&h0;
        *(uint32_t*)(Yh + row1 * C_ + col) = *(uint32_t*)&h1;
        *(uint32_t*)(Yl + row0 * C_ + col) = *(uint32_t*)&e0;
        *(uint32_t*)(Yl + row1 * C_ + col) = *(uint32_t*)&e1;
    }
}

// ---------------------------------------------------------------------------
extern "C" void kernel_launch(void* const* d_in, const int* in_sizes, int n_in,
                              void* d_out, int out_size)
{
    const float* x  = (const float*)d_in[0];
    const float* Wq = (const float*)d_in[1];
    const float* Wk = (const float*)d_in[2];
    const float* Wv = (const float*)d_in[3];
    const float* Wo = (const float*)d_in[4];
    const int*  pos = (const int*)d_in[5];
    float* out = (float*)d_out;

    float *q, *k, *v;
    cudaGetSymbolAddress((void**)&q, g_q);
    cudaGetSymbolAddress((void**)&k, g_k);
    cudaGetSymbolAddress((void**)&v, g_v);
    __nv_bfloat16 *xh, *xl, *yh, *yl, *wqh, *wql, *wkh, *wkl, *wvh, *wvl, *woh, *wol;
    cudaGetSymbolAddress((void**)&xh, s_xh);   cudaGetSymbolAddress((void**)&xl, s_xl);
    cudaGetSymbolAddress((void**)&yh, s_yh);   cudaGetSymbolAddress((void**)&yl, s_yl);
    cudaGetSymbolAddress((void**)&wqh, s_wqh); cudaGetSymbolAddress((void**)&wql, s_wql);
    cudaGetSymbolAddress((void**)&wkh, s_wkh); cudaGetSymbolAddress((void**)&wkl, s_wkl);
    cudaGetSymbolAddress((void**)&wvh, s_wvh); cudaGetSymbolAddress((void**)&wvl, s_wvl);
    cudaGetSymbolAddress((void**)&woh, s_woh); cudaGetSymbolAddress((void**)&wol, s_wol);

    cudaFuncSetAttribute(gemm_mma, cudaFuncAttributeMaxDynamicSharedMemorySize,
                         GEMM_SMEM);
    cudaFuncSetAttribute(flash_mma, cudaFuncAttributeMaxDynamicSharedMemorySize,
                         FL_SMEM);

    // split x
    {
        int n4 = M_ * C_ / 4;
        split_kernel<<<(n4 + 255) / 256, 256>>>(x, xh, xl, n4);
    }
    // transpose+split weights
    transpose_split_kernel<<<dim3(C_ / 32,  C_ / 32), dim3(32, 8)>>>(Wq, wqh, wql, C_, C_);
    transpose_split_kernel<<<dim3(KVD / 32, C_ / 32), dim3(32, 8)>>>(Wk, wkh, wkl, C_, KVD);
    transpose_split_kernel<<<dim3(KVD / 32, C_ / 32), dim3(32, 8)>>>(Wv, wvh, wvl, C_, KVD);
    transpose_split_kernel<<<dim3(C_ / 32,  C_ / 32), dim3(32, 8)>>>(Wo, woh, wol, C_, C_);

    // projections (tensor cores, cp.async pipelined)
    gemm_mma<<<dim3(C_ / 128,  M_ / 128), 256, GEMM_SMEM>>>(xh, xl, wqh, wql, q, C_,  C_);
    gemm_mma<<<dim3(KVD / 128, M_ / 128), 256, GEMM_SMEM>>>(xh, xl, wkh, wkl, k, KVD, C_);
    gemm_mma<<<dim3(KVD / 128, M_ / 128), 256, GEMM_SMEM>>>(xh, xl, wvh, wvl, v, KVD, C_);

    // RoPE
    int qp = M_ * NH * 64;
    rope_kernel<<<(qp + 255) / 256, 256>>>(q, pos, NH, qp);
    int kp = M_ * NKV * 64;
    rope_kernel<<<(kp + 255) / 256, 256>>>(k, pos, NKV, kp);

    // attention (tensor cores), writes bf16 hi/lo splits directly
    flash_mma<<<dim3(T_ / 128, NH, B_), 256, FL_SMEM>>>(q, k, v, yh, yl);

    // output projection
    gemm_mma<<<dim3(C_ / 128, M_ / 128), 256, GEMM_SMEM>>>(yh, yl, woh, wol, out, C_, C_);
}

// round 7
// speedup vs baseline: 1.0503x; 1.0503x over previous
#include <cuda_runtime.h>
#include <cuda_bf16.h>
#include <cuda_fp16.h>
#include <math.h>
#include <stdint.h>

typedef unsigned long long u64;

#define B_   4
#define T_   2048
#define C_   2048
#define NH   16
#define NKV  4
#define HD   128
#define KVD  (NKV*HD)   // 512
#define M_   (B_*T_)    // 8192

// ---------------- scratch (__device__ globals; no allocs allowed) ----------
__device__ float g_q[(size_t)M_ * C_];
__device__ float g_k[(size_t)M_ * KVD];
__device__ float g_v[(size_t)M_ * KVD];

__device__ __nv_bfloat16 s_qh[(size_t)M_ * C_],  s_ql[(size_t)M_ * C_];
__device__ __nv_bfloat16 s_kh[(size_t)M_ * KVD], s_kl[(size_t)M_ * KVD];
__device__ __half        s_vh[(size_t)M_ * KVD];

__device__ __nv_bfloat16 s_xh[(size_t)M_ * C_],  s_xl[(size_t)M_ * C_];
__device__ __nv_bfloat16 s_yh[(size_t)M_ * C_],  s_yl[(size_t)M_ * C_];
__device__ __nv_bfloat16 s_wqh[(size_t)C_ * C_], s_wql[(size_t)C_ * C_];
__device__ __nv_bfloat16 s_wkh[(size_t)KVD * C_], s_wkl[(size_t)KVD * C_];
__device__ __nv_bfloat16 s_wvh[(size_t)KVD * C_], s_wvl[(size_t)KVD * C_];
__device__ __nv_bfloat16 s_woh[(size_t)C_ * C_], s_wol[(size_t)C_ * C_];

// ---------------- helpers ---------------------------------------------------
__device__ __forceinline__ uint32_t smem_u32(const void* p) {
    uint32_t a;
    asm("{ .reg .u64 t; cvta.to.shared.u64 t, %1; cvt.u32.u64 %0, t; }"
        : "=r"(a) : "l"(p));
    return a;
}
__device__ __forceinline__ void ldsm4(uint32_t* r, uint32_t addr) {
    asm volatile("ldmatrix.sync.aligned.m8n8.x4.shared.b16 {%0,%1,%2,%3}, [%4];"
                 : "=r"(r[0]), "=r"(r[1]), "=r"(r[2]), "=r"(r[3]) : "r"(addr));
}
__device__ __forceinline__ void ldsm4t(uint32_t* r, uint32_t addr) {
    asm volatile("ldmatrix.sync.aligned.m8n8.x4.trans.shared.b16 {%0,%1,%2,%3}, [%4];"
                 : "=r"(r[0]), "=r"(r[1]), "=r"(r[2]), "=r"(r[3]) : "r"(addr));
}
__device__ __forceinline__ void mma16816(float* c, const uint32_t* a,
                                         const uint32_t* b) {
    asm volatile(
        "mma.sync.aligned.m16n8k16.row.col.f32.bf16.bf16.f32 "
        "{%0,%1,%2,%3}, {%4,%5,%6,%7}, {%8,%9}, {%0,%1,%2,%3};"
        : "+f"(c[0]), "+f"(c[1]), "+f"(c[2]), "+f"(c[3])
        : "r"(a[0]), "r"(a[1]), "r"(a[2]), "r"(a[3]), "r"(b[0]), "r"(b[1]));
}
__device__ __forceinline__ void mma16816h(float* c, const uint32_t* a,
                                          const uint32_t* b) {
    asm volatile(
        "mma.sync.aligned.m16n8k16.row.col.f32.f16.f16.f32 "
        "{%0,%1,%2,%3}, {%4,%5,%6,%7}, {%8,%9}, {%0,%1,%2,%3};"
        : "+f"(c[0]), "+f"(c[1]), "+f"(c[2]), "+f"(c[3])
        : "r"(a[0]), "r"(a[1]), "r"(a[2]), "r"(a[3]), "r"(b[0]), "r"(b[1]));
}

// ---------------------------------------------------------------------------
// split: fp32 -> (bf16 hi, bf16 lo), vectorized x4
// ---------------------------------------------------------------------------
__global__ void split_kernel(const float* __restrict__ X,
                             __nv_bfloat16* __restrict__ H,
                             __nv_bfloat16* __restrict__ L, int n4)
{
    int i = blockIdx.x * blockDim.x + threadIdx.x;
    if (i >= n4) return;
    float4 v = ((const float4*)X)[i];
    float vv[4] = {v.x, v.y, v.z, v.w};
    __nv_bfloat162 h0, h1, l0, l1;
    __nv_bfloat16 h[4], l[4];
#pragma unroll
    for (int j = 0; j < 4; j++) {
        h[j] = __float2bfloat16(vv[j]);
        l[j] = __float2bfloat16(vv[j] - __bfloat162float(h[j]));
    }
    h0.x = h[0]; h0.y = h[1]; h1.x = h[2]; h1.y = h[3];
    l0.x = l[0]; l0.y = l[1]; l1.x = l[2]; l1.y = l[3];
    ((__nv_bfloat162*)H)[2 * i]     = h0;
    ((__nv_bfloat162*)H)[2 * i + 1] = h1;
    ((__nv_bfloat162*)L)[2 * i]     = l0;
    ((__nv_bfloat162*)L)[2 * i + 1] = l1;
}

// ---------------------------------------------------------------------------
// fp32 -> fp16, vectorized x4
// ---------------------------------------------------------------------------
__global__ void half_kernel(const float* __restrict__ X,
                            __half* __restrict__ H, int n4)
{
    int i = blockIdx.x * blockDim.x + threadIdx.x;
    if (i >= n4) return;
    float4 v = ((const float4*)X)[i];
    __half2 h0 = __floats2half2_rn(v.x, v.y);
    __half2 h1 = __floats2half2_rn(v.z, v.w);
    ((__half2*)H)[2 * i]     = h0;
    ((__half2*)H)[2 * i + 1] = h1;
}

// ---------------------------------------------------------------------------
// transpose + split: W[K,N] fp32 -> Th/Tl [N,K] bf16
// ---------------------------------------------------------------------------
__global__ void transpose_split_kernel(const float* __restrict__ W,
                                       __nv_bfloat16* __restrict__ Th,
                                       __nv_bfloat16* __restrict__ Tl,
                                       int K, int N)
{
    __shared__ float t[32][33];
    int n0 = blockIdx.x * 32, k0 = blockIdx.y * 32;
    int tx = threadIdx.x, ty = threadIdx.y;  // 32 x 8
#pragma unroll
    for (int j = 0; j < 4; j++)
        t[ty + 8 * j][tx] = W[(size_t)(k0 + ty + 8 * j) * N + n0 + tx];
    __syncthreads();
#pragma unroll
    for (int j = 0; j < 4; j++) {
        float v = t[tx][ty + 8 * j];
        __nv_bfloat16 h = __float2bfloat16(v);
        __nv_bfloat16 l = __float2bfloat16(v - __bfloat162float(h));
        size_t o = (size_t)(n0 + ty + 8 * j) * K + k0 + tx;
        Th[o] = h;
        Tl[o] = l;
    }
}

// ---------------------------------------------------------------------------
// bf16-split GEMM via mma.sync (register-prefetch version — R4, proven fastest)
// ---------------------------------------------------------------------------
#define SAS 40

__global__ __launch_bounds__(256) void gemm_mma(
    const __nv_bfloat16* __restrict__ Ah, const __nv_bfloat16* __restrict__ Al,
    const __nv_bfloat16* __restrict__ Bh, const __nv_bfloat16* __restrict__ Bl,
    float* __restrict__ C, int N, int K)
{
    __shared__ __nv_bfloat16 sAh[128 * SAS], sAl[128 * SAS];
    __shared__ __nv_bfloat16 sBh[128 * SAS], sBl[128 * SAS];

    const int tid = threadIdx.x;
    const int lane = tid & 31, wid = tid >> 5;
    const int wm = wid & 1, wn = wid >> 1;
    const int m0 = blockIdx.y * 128, n0 = blockIdx.x * 128;

    const int ldrow = tid >> 1, ldhalf = tid & 1;
    const __nv_bfloat16* gAh = Ah + (size_t)(m0 + ldrow) * K + ldhalf * 16;
    const __nv_bfloat16* gAl = Al + (size_t)(m0 + ldrow) * K + ldhalf * 16;
    const __nv_bfloat16* gBh = Bh + (size_t)(n0 + ldrow) * K + ldhalf * 16;
    const __nv_bfloat16* gBl = Bl + (size_t)(n0 + ldrow) * K + ldhalf * 16;
    char* stAh = (char*)sAh + (ldrow * SAS + ldhalf * 16) * 2;
    char* stAl = (char*)sAl + (ldrow * SAS + ldhalf * 16) * 2;
    char* stBh = (char*)sBh + (ldrow * SAS + ldhalf * 16) * 2;
    char* stBl = (char*)sBl + (ldrow * SAS + ldhalf * 16) * 2;

    const int mid = lane >> 3, rin = lane & 7;
    const uint32_t aoff =
        ((wm * 64 + (mid & 1) * 8 + rin) * SAS + (mid >> 1) * 8) * 2;
    const uint32_t boff =
        ((wn * 32 + (mid >> 1) * 8 + rin) * SAS + (mid & 1) * 8) * 2;
    const uint32_t uAh = smem_u32(sAh) + aoff, uAl = smem_u32(sAl) + aoff;
    const uint32_t uBh = smem_u32(sBh) + boff, uBl = smem_u32(sBl) + boff;

    float acc[4][4][4];
#pragma unroll
    for (int mt = 0; mt < 4; mt++)
#pragma unroll
        for (int nt = 0; nt < 4; nt++)
#pragma unroll
            for (int j = 0; j < 4; j++) acc[mt][nt][j] = 0.0f;

    uint4 rah[2], ral[2], rbh[2], rbl[2];

#define GLOAD(k0)                                            \
    {                                                        \
        rah[0] = *(const uint4*)(gAh + (k0));                \
        rah[1] = *(const uint4*)(gAh + (k0) + 8);            \
        ral[0] = *(const uint4*)(gAl + (k0));                \
        ral[1] = *(const uint4*)(gAl + (k0) + 8);            \
        rbh[0] = *(const uint4*)(gBh + (k0));                \
        rbh[1] = *(const uint4*)(gBh + (k0) + 8);            \
        rbl[0] = *(const uint4*)(gBl + (k0));                \
        rbl[1] = *(const uint4*)(gBl + (k0) + 8);            \
    }
#define SSTORE()                                             \
    {                                                        \
        *(uint4*)(stAh) = rah[0]; *(uint4*)(stAh + 16) = rah[1]; \
        *(uint4*)(stAl) = ral[0]; *(uint4*)(stAl + 16) = ral[1]; \
        *(uint4*)(stBh) = rbh[0]; *(uint4*)(stBh + 16) = rbh[1]; \
        *(uint4*)(stBl) = rbl[0]; *(uint4*)(stBl + 16) = rbl[1]; \
    }

    GLOAD(0);
    SSTORE();
    __syncthreads();

    const int nch = K / 32;
    for (int ch = 0; ch < nch; ch++) {
        const bool more = (ch + 1 < nch);
        if (more) GLOAD((ch + 1) * 32);

#pragma unroll
        for (int ks = 0; ks < 2; ks++) {
            uint32_t fah[4][4], fal[4][4], fbh[2][4], fbl[2][4];
#pragma unroll
            for (int mt = 0; mt < 4; mt++) {
                ldsm4(fah[mt], uAh + mt * (16 * SAS * 2) + ks * 32);
                ldsm4(fal[mt], uAl + mt * (16 * SAS * 2) + ks * 32);
            }
#pragma unroll
            for (int np = 0; np < 2; np++) {
                ldsm4(fbh[np], uBh + np * (16 * SAS * 2) + ks * 32);
                ldsm4(fbl[np], uBl + np * (16 * SAS * 2) + ks * 32);
            }
#pragma unroll
            for (int mt = 0; mt < 4; mt++)
#pragma unroll
                for (int nt = 0; nt < 4; nt++) {
                    const uint32_t* b_h = &fbh[nt >> 1][(nt & 1) * 2];
                    const uint32_t* b_l = &fbl[nt >> 1][(nt & 1) * 2];
                    mma16816(acc[mt][nt], fah[mt], b_h);
                    mma16816(acc[mt][nt], fal[mt], b_h);
                    mma16816(acc[mt][nt], fah[mt], b_l);
                }
        }
        __syncthreads();
        if (more) SSTORE();
        __syncthreads();
    }

    const int g = lane >> 2, tg = lane & 3;
#pragma unroll
    for (int mt = 0; mt < 4; mt++) {
        const int mrow = m0 + wm * 64 + mt * 16 + g;
#pragma unroll
        for (int nt = 0; nt < 4; nt++) {
            const int ncol = n0 + wn * 32 + nt * 8 + tg * 2;
            float2 v0 = {acc[mt][nt][0], acc[mt][nt][1]};
            float2 v1 = {acc[mt][nt][2], acc[mt][nt][3]};
            *(float2*)(C + (size_t)mrow * N + ncol)       = v0;
            *(float2*)(C + (size_t)(mrow + 8) * N + ncol) = v1;
        }
    }
#undef GLOAD
#undef SSTORE
}

// ---------------------------------------------------------------------------
// RoPE + split: fp32 X -> bf16 hi/lo with rotation applied (matches reference)
// ---------------------------------------------------------------------------
__global__ void rope_split_kernel(const float* __restrict__ X,
                                  __nv_bfloat16* __restrict__ H,
                                  __nv_bfloat16* __restrict__ L,
                                  const int* __restrict__ posp,
                                  int nheads, int total)
{
    int idx = blockIdx.x * blockDim.x + threadIdx.x;
    if (idx >= total) return;
    int p   = idx & 63;
    int h   = (idx >> 6) % nheads;
    int row = idx / (64 * nheads);
    int t   = row % T_;
    float pos = (float)(posp[0] + t);

    size_t base = (size_t)row * (nheads * HD) + h * HD;
    float x1 = X[base + p];
    float x2 = X[base + p + 64];

    const float LN1E4 = 9.210340371976184f;
    float e1 = (float)(2 * (p >> 1)) * (1.0f / 128.0f);
    float e2 = e1 + 0.5f;
    float f1 = __expf(-e1 * LN1E4);
    float f2 = __expf(-e2 * LN1E4);
    float a1 = pos * f1;
    float a2 = pos * f2;

    float o1 = x1 * cosf(a1) - x2 * sinf(a1);
    float o2 = x2 * cosf(a2) + x1 * sinf(a2);

    __nv_bfloat16 h1 = __float2bfloat16(o1);
    __nv_bfloat16 l1 = __float2bfloat16(o1 - __bfloat162float(h1));
    __nv_bfloat16 h2 = __float2bfloat16(o2);
    __nv_bfloat16 l2 = __float2bfloat16(o2 - __bfloat162float(h2));
    H[base + p]      = h1;  L[base + p]      = l1;
    H[base + p + 64] = h2;  L[base + p + 64] = l2;
}

// ---------------------------------------------------------------------------
// Flash attention on mma.sync — pre-split inputs (no in-kernel conversion).
// Qh/Ql bf16 [M,C]; Kh/Kl bf16 [M,KVD]; Vh fp16 [M,KVD].
// CTA: 128 q-rows; 8 warps x 16 rows; K tiles of 64.
// ---------------------------------------------------------------------------
#define SKP 136
#define FL_SMEM (3 * 64 * SKP * 2)

extern __shared__ char dynsm[];

__global__ __launch_bounds__(256) void flash_mma(
    const __nv_bfloat16* __restrict__ Qh, const __nv_bfloat16* __restrict__ Ql,
    const __nv_bfloat16* __restrict__ Khg, const __nv_bfloat16* __restrict__ Klg,
    const __half* __restrict__ Vhg,
    __nv_bfloat16* __restrict__ Yh, __nv_bfloat16* __restrict__ Yl)
{
    __nv_bfloat16* sKh = (__nv_bfloat16*)dynsm;
    __nv_bfloat16* sKl = sKh + 64 * SKP;
    __half*        sVh = (__half*)(sKl + 64 * SKP);

    const int tid = threadIdx.x, lane = tid & 31, w = tid >> 5;
    const int qb = blockIdx.x, h = blockIdx.y, b = blockIdx.z;
    const int kvh = h >> 2;
    const int g = lane >> 2, tg = lane & 3;
    const int mid = lane >> 3, rin = lane & 7;
    const int qrow0 = qb * 128 + w * 16;

    // ---- resident Q fragments: direct bf16 loads ----
    uint32_t qh[8][4], ql[8][4];
    {
        const __nv_bfloat16* Qhb = Qh + ((size_t)b * T_ + qrow0) * C_ + h * HD;
        const __nv_bfloat16* Qlb = Ql + ((size_t)b * T_ + qrow0) * C_ + h * HD;
#pragma unroll
        for (int kc = 0; kc < 8; kc++) {
#pragma unroll
            for (int fr = 0; fr < 4; fr++) {
                int r = g + (fr & 1) * 8;
                int c = kc * 16 + tg * 2 + (fr >> 1) * 8;
                qh[kc][fr] = *(const uint32_t*)(Qhb + (size_t)r * C_ + c);
                ql[kc][fr] = *(const uint32_t*)(Qlb + (size_t)r * C_ + c);
            }
        }
    }

    float o[16][4];
#pragma unroll
    for (int nt = 0; nt < 16; nt++)
#pragma unroll
        for (int j = 0; j < 4; j++) o[nt][j] = 0.0f;
    float m0 = -INFINITY, m1 = -INFINITY, l0 = 0.0f, l1 = 0.0f;

    const float cscale = 0.08838834764831845f;
    const int rg0 = qrow0 + g, rg1 = rg0 + 8;
    const int ktmax = 2 * qb + 2;

    const __nv_bfloat16* Kh0 = Khg + (size_t)b * T_ * KVD + kvh * HD;
    const __nv_bfloat16* Kl0 = Klg + (size_t)b * T_ * KVD + kvh * HD;
    const __half*        Vh0 = Vhg + (size_t)b * T_ * KVD + kvh * HD;

    const uint32_t uKh = smem_u32(sKh), uKl = smem_u32(sKl), uVh = smem_u32(sVh);
    const uint32_t kfrag = (((mid >> 1) * 8 + rin) * SKP + (mid & 1) * 8) * 2;
    const uint32_t vfrag = (((mid & 1) * 8 + rin) * SKP + (mid >> 1) * 8) * 2;

    for (int kt = 0; kt < ktmax; kt++) {
        __syncthreads();
        // ---- copy pre-converted K/V tiles (64 rows x 128 cols, 16B chunks) ----
        {
            const __nv_bfloat16* Kht = Kh0 + (size_t)kt * 64 * KVD;
            const __nv_bfloat16* Klt = Kl0 + (size_t)kt * 64 * KVD;
            const __half*        Vht = Vh0 + (size_t)kt * 64 * KVD;
#pragma unroll
            for (int it = 0; it < 4; it++) {
                int i = tid + it * 256;
                int r = i >> 4, c8 = (i & 15) << 3;
                *(uint4*)(sKh + r * SKP + c8) = *(const uint4*)(Kht + (size_t)r * KVD + c8);
                *(uint4*)(sKl + r * SKP + c8) = *(const uint4*)(Klt + (size_t)r * KVD + c8);
                *(uint4*)(sVh + r * SKP + c8) = *(const uint4*)(Vht + (size_t)r * KVD + c8);
            }
        }
        __syncthreads();

        if (kt * 64 > qrow0 + 15) continue;
        const bool needmask = (kt * 64 + 63 > qrow0);

        // ---- S = Q K^T (3-pass bf16 split) ----
        float s[8][4];
#pragma unroll
        for (int nt = 0; nt < 8; nt++)
#pragma unroll
            for (int j = 0; j < 4; j++) s[nt][j] = 0.0f;

#pragma unroll
        for (int kc = 0; kc < 8; kc++) {
            uint32_t bt[4][4];
#pragma unroll
            for (int nt2 = 0; nt2 < 4; nt2++)
                ldsm4(bt[nt2], uKh + kfrag + (nt2 * 16 * SKP + kc * 16) * 2);
#pragma unroll
            for (int nt = 0; nt < 8; nt++) {
                const uint32_t* bb = &bt[nt >> 1][(nt & 1) * 2];
                mma16816(s[nt], qh[kc], bb);
                mma16816(s[nt], ql[kc], bb);
            }
#pragma unroll
            for (int nt2 = 0; nt2 < 4; nt2++)
                ldsm4(bt[nt2], uKl + kfrag + (nt2 * 16 * SKP + kc * 16) * 2);
#pragma unroll
            for (int nt = 0; nt < 8; nt++)
                mma16816(s[nt], qh[kc], &bt[nt >> 1][(nt & 1) * 2]);
        }

#pragma unroll
        for (int nt = 0; nt < 8; nt++) {
#pragma unroll
            for (int j = 0; j < 4; j++) s[nt][j] *= cscale;
            if (needmask) {
                int c0 = kt * 64 + nt * 8 + tg * 2;
                if (c0 > rg0)     s[nt][0] = -1e30f;
                if (c0 + 1 > rg0) s[nt][1] = -1e30f;
                if (c0 > rg1)     s[nt][2] = -1e30f;
                if (c0 + 1 > rg1) s[nt][3] = -1e30f;
            }
        }

        float mn0 = m0, mn1 = m1;
#pragma unroll
        for (int nt = 0; nt < 8; nt++) {
            mn0 = fmaxf(mn0, fmaxf(s[nt][0], s[nt][1]));
            mn1 = fmaxf(mn1, fmaxf(s[nt][2], s[nt][3]));
        }
        mn0 = fmaxf(mn0, __shfl_xor_sync(0xffffffffu, mn0, 1));
        mn0 = fmaxf(mn0, __shfl_xor_sync(0xffffffffu, mn0, 2));
        mn1 = fmaxf(mn1, __shfl_xor_sync(0xffffffffu, mn1, 1));
        mn1 = fmaxf(mn1, __shfl_xor_sync(0xffffffffu, mn1, 2));
        float fac0 = __expf(m0 - mn0), fac1 = __expf(m1 - mn1);
        m0 = mn0; m1 = mn1;

        uint32_t pa[4][4];
        float ps0 = 0.0f, ps1 = 0.0f;
#pragma unroll
        for (int kk = 0; kk < 4; kk++) {
            int nt = 2 * kk;
            float p00 = __expf(s[nt][0] - m0),     p01 = __expf(s[nt][1] - m0);
            float p02 = __expf(s[nt][2] - m1),     p03 = __expf(s[nt][3] - m1);
            float p10 = __expf(s[nt + 1][0] - m0), p11 = __expf(s[nt + 1][1] - m0);
            float p12 = __expf(s[nt + 1][2] - m1), p13 = __expf(s[nt + 1][3] - m1);
            ps0 += p00 + p01 + p10 + p11;
            ps1 += p02 + p03 + p12 + p13;
            __half2 a0 = __floats2half2_rn(p00, p01);
            __half2 a1 = __floats2half2_rn(p02, p03);
            __half2 a2 = __floats2half2_rn(p10, p11);
            __half2 a3 = __floats2half2_rn(p12, p13);
            pa[kk][0] = *(uint32_t*)&a0;
            pa[kk][1] = *(uint32_t*)&a1;
            pa[kk][2] = *(uint32_t*)&a2;
            pa[kk][3] = *(uint32_t*)&a3;
        }
        l0 = l0 * fac0 + ps0;
        l1 = l1 * fac1 + ps1;

#pragma unroll
        for (int nt = 0; nt < 16; nt++) {
            o[nt][0] *= fac0; o[nt][1] *= fac0;
            o[nt][2] *= fac1; o[nt][3] *= fac1;
        }

#pragma unroll
        for (int kk = 0; kk < 4; kk++) {
            uint32_t vb[8][4];
#pragma unroll
            for (int np = 0; np < 8; np++)
                ldsm4t(vb[np], uVh + vfrag + (kk * 16 * SKP + np * 16) * 2);
#pragma unroll
            for (int nt = 0; nt < 16; nt++)
                mma16816h(o[nt], pa[kk], &vb[nt >> 1][(nt & 1) * 2]);
        }
    }

    l0 += __shfl_xor_sync(0xffffffffu, l0, 1);
    l0 += __shfl_xor_sync(0xffffffffu, l0, 2);
    l1 += __shfl_xor_sync(0xffffffffu, l1, 1);
    l1 += __shfl_xor_sync(0xffffffffu, l1, 2);
    float inv0 = 1.0f / l0, inv1 = 1.0f / l1;

    size_t row0 = (size_t)b * T_ + rg0;
    size_t row1 = (size_t)b * T_ + rg1;
#pragma unroll
    for (int nt = 0; nt < 16; nt++) {
        int col = h * HD + nt * 8 + tg * 2;
        float2 v0 = {o[nt][0] * inv0, o[nt][1] * inv0};
        float2 v1 = {o[nt][2] * inv1, o[nt][3] * inv1};
        __nv_bfloat162 h0 = __float22bfloat162_rn(v0);
        __nv_bfloat162 h1 = __float22bfloat162_rn(v1);
        float2 f0 = __bfloat1622float2(h0), f1 = __bfloat1622float2(h1);
        __nv_bfloat162 e0 = __float22bfloat162_rn(make_float2(v0.x - f0.x, v0.y - f0.y));
        __nv_bfloat162 e1 = __float22bfloat162_rn(make_float2(v1.x - f1.x, v1.y - f1.y));
        *(uint32_t*)(Yh + row0 * C_ + col) = *(uint32_t*)&h0;
        *(uint32_t*)(Yh + row1 * C_ + col) = *(uint32_t*)&h1;
        *(uint32_t*)(Yl + row0 * C_ + col) = *(uint32_t*)&e0;
        *(uint32_t*)(Yl + row1 * C_ + col) = *(uint32_t*)&e1;
    }
}

// ---------------------------------------------------------------------------
extern "C" void kernel_launch(void* const* d_in, const int* in_sizes, int n_in,
                              void* d_out, int out_size)
{
    const float* x  = (const float*)d_in[0];
    const float* Wq = (const float*)d_in[1];
    const float* Wk = (const float*)d_in[2];
    const float* Wv = (const float*)d_in[3];
    const float* Wo = (const float*)d_in[4];
    const int*  pos = (const int*)d_in[5];
    float* out = (float*)d_out;

    float *q, *k, *v;
    cudaGetSymbolAddress((void**)&q, g_q);
    cudaGetSymbolAddress((void**)&k, g_k);
    cudaGetSymbolAddress((void**)&v, g_v);
    __nv_bfloat16 *qh, *ql, *kh, *kl;
    __half *vh;
    cudaGetSymbolAddress((void**)&qh, s_qh); cudaGetSymbolAddress((void**)&ql, s_ql);
    cudaGetSymbolAddress((void**)&kh, s_kh); cudaGetSymbolAddress((void**)&kl, s_kl);
    cudaGetSymbolAddress((void**)&vh, s_vh);
    __nv_bfloat16 *xh, *xl, *yh, *yl, *wqh, *wql, *wkh, *wkl, *wvh, *wvl, *woh, *wol;
    cudaGetSymbolAddress((void**)&xh, s_xh);   cudaGetSymbolAddress((void**)&xl, s_xl);
    cudaGetSymbolAddress((void**)&yh, s_yh);   cudaGetSymbolAddress((void**)&yl, s_yl);
    cudaGetSymbolAddress((void**)&wqh, s_wqh); cudaGetSymbolAddress((void**)&wql, s_wql);
    cudaGetSymbolAddress((void**)&wkh, s_wkh); cudaGetSymbolAddress((void**)&wkl, s_wkl);
    cudaGetSymbolAddress((void**)&wvh, s_wvh); cudaGetSymbolAddress((void**)&wvl, s_wvl);
    cudaGetSymbolAddress((void**)&woh, s_woh); cudaGetSymbolAddress((void**)&wol, s_wol);

    cudaFuncSetAttribute(flash_mma, cudaFuncAttributeMaxDynamicSharedMemorySize,
                         FL_SMEM);

    // split x
    {
        int n4 = M_ * C_ / 4;
        split_kernel<<<(n4 + 255) / 256, 256>>>(x, xh, xl, n4);
    }
    // transpose+split weights
    transpose_split_kernel<<<dim3(C_ / 32,  C_ / 32), dim3(32, 8)>>>(Wq, wqh, wql, C_, C_);
    transpose_split_kernel<<<dim3(KVD / 32, C_ / 32), dim3(32, 8)>>>(Wk, wkh, wkl, C_, KVD);
    transpose_split_kernel<<<dim3(KVD / 32, C_ / 32), dim3(32, 8)>>>(Wv, wvh, wvl, C_, KVD);
    transpose_split_kernel<<<dim3(C_ / 32,  C_ / 32), dim3(32, 8)>>>(Wo, woh, wol, C_, C_);

    // projections (tensor cores)
    gemm_mma<<<dim3(C_ / 128,  M_ / 128), 256>>>(xh, xl, wqh, wql, q, C_,  C_);
    gemm_mma<<<dim3(KVD / 128, M_ / 128), 256>>>(xh, xl, wkh, wkl, k, KVD, C_);
    gemm_mma<<<dim3(KVD / 128, M_ / 128), 256>>>(xh, xl, wvh, wvl, v, KVD, C_);

    // RoPE + split q, k; convert v to fp16
    int qp = M_ * NH * 64;
    rope_split_kernel<<<(qp + 255) / 256, 256>>>(q, qh, ql, pos, NH, qp);
    int kp = M_ * NKV * 64;
    rope_split_kernel<<<(kp + 255) / 256, 256>>>(k, kh, kl, pos, NKV, kp);
    {
        int n4 = M_ * KVD / 4;
        half_kernel<<<(n4 + 255) / 256, 256>>>(v, vh, n4);
    }

    // attention (tensor cores), pre-split inputs, writes bf16 hi/lo splits
    flash_mma<<<dim3(T_ / 128, NH, B_), 256, FL_SMEM>>>(qh, ql, kh, kl, vh, yh, yl);

    // output projection
    gemm_mma<<<dim3(C_ / 128, M_ / 128), 256>>>(yh, yl, woh, wol, out, C_, C_);
}

// round 8
// speedup vs baseline: 1.4222x; 1.3541x over previous
#include <cuda_runtime.h>
#include <cuda_fp16.h>
#include <math.h>
#include <stdint.h>

#define B_   4
#define T_   2048
#define C_   2048
#define NH   16
#define NKV  4
#define HD   128
#define KVD  (NKV*HD)   // 512
#define M_   (B_*T_)    // 8192

// ---------------- scratch (__device__ globals; no allocs allowed) ----------
__device__ float g_q[(size_t)M_ * C_];
__device__ float g_k[(size_t)M_ * KVD];
__device__ float g_v[(size_t)M_ * KVD];

__device__ __half s_qh[(size_t)M_ * C_],  s_ql[(size_t)M_ * C_];
__device__ __half s_kh[(size_t)M_ * KVD], s_kdummy[(size_t)M_ * KVD];
__device__ __half s_vh[(size_t)M_ * KVD];

__device__ __half s_xh[(size_t)M_ * C_],  s_xl[(size_t)M_ * C_];
__device__ __half s_yh[(size_t)M_ * C_],  s_yl[(size_t)M_ * C_];
__device__ __half s_wqh[(size_t)C_ * C_];
__device__ __half s_wkh[(size_t)KVD * C_];
__device__ __half s_wvh[(size_t)KVD * C_];
__device__ __half s_woh[(size_t)C_ * C_];

// ---------------- helpers ---------------------------------------------------
__device__ __forceinline__ uint32_t smem_u32(const void* p) {
    uint32_t a;
    asm("{ .reg .u64 t; cvta.to.shared.u64 t, %1; cvt.u32.u64 %0, t; }"
        : "=r"(a) : "l"(p));
    return a;
}
__device__ __forceinline__ void ldsm4(uint32_t* r, uint32_t addr) {
    asm volatile("ldmatrix.sync.aligned.m8n8.x4.shared.b16 {%0,%1,%2,%3}, [%4];"
                 : "=r"(r[0]), "=r"(r[1]), "=r"(r[2]), "=r"(r[3]) : "r"(addr));
}
__device__ __forceinline__ void ldsm4t(uint32_t* r, uint32_t addr) {
    asm volatile("ldmatrix.sync.aligned.m8n8.x4.trans.shared.b16 {%0,%1,%2,%3}, [%4];"
                 : "=r"(r[0]), "=r"(r[1]), "=r"(r[2]), "=r"(r[3]) : "r"(addr));
}
__device__ __forceinline__ void mma16816h(float* c, const uint32_t* a,
                                          const uint32_t* b) {
    asm volatile(
        "mma.sync.aligned.m16n8k16.row.col.f32.f16.f16.f32 "
        "{%0,%1,%2,%3}, {%4,%5,%6,%7}, {%8,%9}, {%0,%1,%2,%3};"
        : "+f"(c[0]), "+f"(c[1]), "+f"(c[2]), "+f"(c[3])
        : "r"(a[0]), "r"(a[1]), "r"(a[2]), "r"(a[3]), "r"(b[0]), "r"(b[1]));
}

// ---------------------------------------------------------------------------
// split: fp32 -> (fp16 hi, fp16 lo), vectorized x4
// ---------------------------------------------------------------------------
__global__ void split_kernel(const float* __restrict__ X,
                             __half* __restrict__ H,
                             __half* __restrict__ L, int n4)
{
    int i = blockIdx.x * blockDim.x + threadIdx.x;
    if (i >= n4) return;
    float4 v = ((const float4*)X)[i];
    float vv[4] = {v.x, v.y, v.z, v.w};
    __half h[4], l[4];
#pragma unroll
    for (int j = 0; j < 4; j++) {
        h[j] = __float2half(vv[j]);
        l[j] = __float2half(vv[j] - __half2float(h[j]));
    }
    __half2 h0 = {h[0], h[1]}, h1 = {h[2], h[3]};
    __half2 l0 = {l[0], l[1]}, l1 = {l[2], l[3]};
    ((__half2*)H)[2 * i]     = h0;
    ((__half2*)H)[2 * i + 1] = h1;
    ((__half2*)L)[2 * i]     = l0;
    ((__half2*)L)[2 * i + 1] = l1;
}

// ---------------------------------------------------------------------------
// fp32 -> fp16, vectorized x4
// ---------------------------------------------------------------------------
__global__ void half_kernel(const float* __restrict__ X,
                            __half* __restrict__ H, int n4)
{
    int i = blockIdx.x * blockDim.x + threadIdx.x;
    if (i >= n4) return;
    float4 v = ((const float4*)X)[i];
    __half2 h0 = __floats2half2_rn(v.x, v.y);
    __half2 h1 = __floats2half2_rn(v.z, v.w);
    ((__half2*)H)[2 * i]     = h0;
    ((__half2*)H)[2 * i + 1] = h1;
}

// ---------------------------------------------------------------------------
// transpose: W[K,N] fp32 -> Th [N,K] fp16 (hi only — 2-pass scheme)
// ---------------------------------------------------------------------------
__global__ void transpose_half_kernel(const float* __restrict__ W,
                                      __half* __restrict__ Th, int K, int N)
{
    __shared__ float t[32][33];
    int n0 = blockIdx.x * 32, k0 = blockIdx.y * 32;
    int tx = threadIdx.x, ty = threadIdx.y;  // 32 x 8
#pragma unroll
    for (int j = 0; j < 4; j++)
        t[ty + 8 * j][tx] = W[(size_t)(k0 + ty + 8 * j) * N + n0 + tx];
    __syncthreads();
#pragma unroll
    for (int j = 0; j < 4; j++)
        Th[(size_t)(n0 + ty + 8 * j) * K + k0 + tx] =
            __float2half(t[tx][ty + 8 * j]);
}

// ---------------------------------------------------------------------------
// fp16 2-pass GEMM via mma.sync: C[M,N] = A[M,K] @ W[K,N].
// A split (Ah/Al fp16 [M,K]); B = W^T hi-only (Bh fp16 [N,K]).
// Error: uncorrected B rounding ~2^-12.5 rms. CTA 128x128, BK=32, 8 warps.
// ---------------------------------------------------------------------------
#define SAS 40

__global__ __launch_bounds__(256) void gemm_mma(
    const __half* __restrict__ Ah, const __half* __restrict__ Al,
    const __half* __restrict__ Bh,
    float* __restrict__ C, int N, int K)
{
    __shared__ __half sAh[128 * SAS], sAl[128 * SAS], sBh[128 * SAS];

    const int tid = threadIdx.x;
    const int lane = tid & 31, wid = tid >> 5;
    const int wm = wid & 1, wn = wid >> 1;
    const int m0 = blockIdx.y * 128, n0 = blockIdx.x * 128;

    const int ldrow = tid >> 1, ldhalf = tid & 1;
    const __half* gAh = Ah + (size_t)(m0 + ldrow) * K + ldhalf * 16;
    const __half* gAl = Al + (size_t)(m0 + ldrow) * K + ldhalf * 16;
    const __half* gBh = Bh + (size_t)(n0 + ldrow) * K + ldhalf * 16;
    char* stAh = (char*)sAh + (ldrow * SAS + ldhalf * 16) * 2;
    char* stAl = (char*)sAl + (ldrow * SAS + ldhalf * 16) * 2;
    char* stBh = (char*)sBh + (ldrow * SAS + ldhalf * 16) * 2;

    const int mid = lane >> 3, rin = lane & 7;
    const uint32_t aoff =
        ((wm * 64 + (mid & 1) * 8 + rin) * SAS + (mid >> 1) * 8) * 2;
    const uint32_t boff =
        ((wn * 32 + (mid >> 1) * 8 + rin) * SAS + (mid & 1) * 8) * 2;
    const uint32_t uAh = smem_u32(sAh) + aoff, uAl = smem_u32(sAl) + aoff;
    const uint32_t uBh = smem_u32(sBh) + boff;

    float acc[4][4][4];
#pragma unroll
    for (int mt = 0; mt < 4; mt++)
#pragma unroll
        for (int nt = 0; nt < 4; nt++)
#pragma unroll
            for (int j = 0; j < 4; j++) acc[mt][nt][j] = 0.0f;

    uint4 rah[2], ral[2], rbh[2];

#define GLOAD(k0)                                            \
    {                                                        \
        rah[0] = *(const uint4*)(gAh + (k0));                \
        rah[1] = *(const uint4*)(gAh + (k0) + 8);            \
        ral[0] = *(const uint4*)(gAl + (k0));                \
        ral[1] = *(const uint4*)(gAl + (k0) + 8);            \
        rbh[0] = *(const uint4*)(gBh + (k0));                \
        rbh[1] = *(const uint4*)(gBh + (k0) + 8);            \
    }
#define SSTORE()                                             \
    {                                                        \
        *(uint4*)(stAh) = rah[0]; *(uint4*)(stAh + 16) = rah[1]; \
        *(uint4*)(stAl) = ral[0]; *(uint4*)(stAl + 16) = ral[1]; \
        *(uint4*)(stBh) = rbh[0]; *(uint4*)(stBh + 16) = rbh[1]; \
    }

    GLOAD(0);
    SSTORE();
    __syncthreads();

    const int nch = K / 32;
    for (int ch = 0; ch < nch; ch++) {
        const bool more = (ch + 1 < nch);
        if (more) GLOAD((ch + 1) * 32);

#pragma unroll
        for (int ks = 0; ks < 2; ks++) {
            uint32_t fah[4][4], fal[4][4], fbh[2][4];
#pragma unroll
            for (int mt = 0; mt < 4; mt++) {
                ldsm4(fah[mt], uAh + mt * (16 * SAS * 2) + ks * 32);
                ldsm4(fal[mt], uAl + mt * (16 * SAS * 2) + ks * 32);
            }
#pragma unroll
            for (int np = 0; np < 2; np++)
                ldsm4(fbh[np], uBh + np * (16 * SAS * 2) + ks * 32);
#pragma unroll
            for (int mt = 0; mt < 4; mt++)
#pragma unroll
                for (int nt = 0; nt < 4; nt++) {
                    const uint32_t* b_h = &fbh[nt >> 1][(nt & 1) * 2];
                    mma16816h(acc[mt][nt], fah[mt], b_h);
                    mma16816h(acc[mt][nt], fal[mt], b_h);
                }
        }
        __syncthreads();
        if (more) SSTORE();
        __syncthreads();
    }

    const int g = lane >> 2, tg = lane & 3;
#pragma unroll
    for (int mt = 0; mt < 4; mt++) {
        const int mrow = m0 + wm * 64 + mt * 16 + g;
#pragma unroll
        for (int nt = 0; nt < 4; nt++) {
            const int ncol = n0 + wn * 32 + nt * 8 + tg * 2;
            float2 v0 = {acc[mt][nt][0], acc[mt][nt][1]};
            float2 v1 = {acc[mt][nt][2], acc[mt][nt][3]};
            *(float2*)(C + (size_t)mrow * N + ncol)       = v0;
            *(float2*)(C + (size_t)(mrow + 8) * N + ncol) = v1;
        }
    }
#undef GLOAD
#undef SSTORE
}

// ---------------------------------------------------------------------------
// RoPE + fp16 hi/lo split (matches reference math in fp32, then splits)
// ---------------------------------------------------------------------------
__global__ void rope_split_kernel(const float* __restrict__ X,
                                  __half* __restrict__ H,
                                  __half* __restrict__ L,
                                  const int* __restrict__ posp,
                                  int nheads, int total)
{
    int idx = blockIdx.x * blockDim.x + threadIdx.x;
    if (idx >= total) return;
    int p   = idx & 63;
    int h   = (idx >> 6) % nheads;
    int row = idx / (64 * nheads);
    int t   = row % T_;
    float pos = (float)(posp[0] + t);

    size_t base = (size_t)row * (nheads * HD) + h * HD;
    float x1 = X[base + p];
    float x2 = X[base + p + 64];

    const float LN1E4 = 9.210340371976184f;
    float e1 = (float)(2 * (p >> 1)) * (1.0f / 128.0f);
    float e2 = e1 + 0.5f;
    float f1 = __expf(-e1 * LN1E4);
    float f2 = __expf(-e2 * LN1E4);
    float a1 = pos * f1;
    float a2 = pos * f2;

    float o1 = x1 * cosf(a1) - x2 * sinf(a1);
    float o2 = x2 * cosf(a2) + x1 * sinf(a2);

    __half h1 = __float2half(o1);
    __half l1 = __float2half(o1 - __half2float(h1));
    __half h2 = __float2half(o2);
    __half l2 = __float2half(o2 - __half2float(h2));
    H[base + p]      = h1;  L[base + p]      = l1;
    H[base + p + 64] = h2;  L[base + p + 64] = l2;
}

// ---------------------------------------------------------------------------
// Flash attention on mma.sync, fp16 2-pass QK (Qh,Ql vs Kh), fp16 PV.
// CTA: 128 q-rows; 8 warps x 16 rows; K tiles of 64. Smem: Kh + Vh (34 KB).
// ---------------------------------------------------------------------------
#define SKP 136
#define FL_SMEM (2 * 64 * SKP * 2)

extern __shared__ char dynsm[];

__global__ __launch_bounds__(256) void flash_mma(
    const __half* __restrict__ Qh, const __half* __restrict__ Ql,
    const __half* __restrict__ Khg, const __half* __restrict__ Vhg,
    __half* __restrict__ Yh, __half* __restrict__ Yl)
{
    __half* sKh = (__half*)dynsm;
    __half* sVh = sKh + 64 * SKP;

    const int tid = threadIdx.x, lane = tid & 31, w = tid >> 5;
    const int qb = blockIdx.x, h = blockIdx.y, b = blockIdx.z;
    const int kvh = h >> 2;
    const int g = lane >> 2, tg = lane & 3;
    const int mid = lane >> 3, rin = lane & 7;
    const int qrow0 = qb * 128 + w * 16;

    uint32_t qh[8][4], ql[8][4];
    {
        const __half* Qhb = Qh + ((size_t)b * T_ + qrow0) * C_ + h * HD;
        const __half* Qlb = Ql + ((size_t)b * T_ + qrow0) * C_ + h * HD;
#pragma unroll
        for (int kc = 0; kc < 8; kc++) {
#pragma unroll
            for (int fr = 0; fr < 4; fr++) {
                int r = g + (fr & 1) * 8;
                int c = kc * 16 + tg * 2 + (fr >> 1) * 8;
                qh[kc][fr] = *(const uint32_t*)(Qhb + (size_t)r * C_ + c);
                ql[kc][fr] = *(const uint32_t*)(Qlb + (size_t)r * C_ + c);
            }
        }
    }

    float o[16][4];
#pragma unroll
    for (int nt = 0; nt < 16; nt++)
#pragma unroll
        for (int j = 0; j < 4; j++) o[nt][j] = 0.0f;
    float m0 = -INFINITY, m1 = -INFINITY, l0 = 0.0f, l1 = 0.0f;

    const float cscale = 0.08838834764831845f;
    const int rg0 = qrow0 + g, rg1 = rg0 + 8;
    const int ktmax = 2 * qb + 2;

    const __half* Kh0 = Khg + (size_t)b * T_ * KVD + kvh * HD;
    const __half* Vh0 = Vhg + (size_t)b * T_ * KVD + kvh * HD;

    const uint32_t uKh = smem_u32(sKh), uVh = smem_u32(sVh);
    const uint32_t kfrag = (((mid >> 1) * 8 + rin) * SKP + (mid & 1) * 8) * 2;
    const uint32_t vfrag = (((mid & 1) * 8 + rin) * SKP + (mid >> 1) * 8) * 2;

    for (int kt = 0; kt < ktmax; kt++) {
        __syncthreads();
        {
            const __half* Kht = Kh0 + (size_t)kt * 64 * KVD;
            const __half* Vht = Vh0 + (size_t)kt * 64 * KVD;
#pragma unroll
            for (int it = 0; it < 4; it++) {
                int i = tid + it * 256;
                int r = i >> 4, c8 = (i & 15) << 3;
                *(uint4*)(sKh + r * SKP + c8) = *(const uint4*)(Kht + (size_t)r * KVD + c8);
                *(uint4*)(sVh + r * SKP + c8) = *(const uint4*)(Vht + (size_t)r * KVD + c8);
            }
        }
        __syncthreads();

        if (kt * 64 > qrow0 + 15) continue;
        const bool needmask = (kt * 64 + 63 > qrow0);

        float s[8][4];
#pragma unroll
        for (int nt = 0; nt < 8; nt++)
#pragma unroll
            for (int j = 0; j < 4; j++) s[nt][j] = 0.0f;

#pragma unroll
        for (int kc = 0; kc < 8; kc++) {
            uint32_t bt[4][4];
#pragma unroll
            for (int nt2 = 0; nt2 < 4; nt2++)
                ldsm4(bt[nt2], uKh + kfrag + (nt2 * 16 * SKP + kc * 16) * 2);
#pragma unroll
            for (int nt = 0; nt < 8; nt++) {
                const uint32_t* bb = &bt[nt >> 1][(nt & 1) * 2];
                mma16816h(s[nt], qh[kc], bb);
                mma16816h(s[nt], ql[kc], bb);
            }
        }

#pragma unroll
        for (int nt = 0; nt < 8; nt++) {
#pragma unroll
            for (int j = 0; j < 4; j++) s[nt][j] *= cscale;
            if (needmask) {
                int c0 = kt * 64 + nt * 8 + tg * 2;
                if (c0 > rg0)     s[nt][0] = -1e30f;
                if (c0 + 1 > rg0) s[nt][1] = -1e30f;
                if (c0 > rg1)     s[nt][2] = -1e30f;
                if (c0 + 1 > rg1) s[nt][3] = -1e30f;
            }
        }

        float mn0 = m0, mn1 = m1;
#pragma unroll
        for (int nt = 0; nt < 8; nt++) {
            mn0 = fmaxf(mn0, fmaxf(s[nt][0], s[nt][1]));
            mn1 = fmaxf(mn1, fmaxf(s[nt][2], s[nt][3]));
        }
        mn0 = fmaxf(mn0, __shfl_xor_sync(0xffffffffu, mn0, 1));
        mn0 = fmaxf(mn0, __shfl_xor_sync(0xffffffffu, mn0, 2));
        mn1 = fmaxf(mn1, __shfl_xor_sync(0xffffffffu, mn1, 1));
        mn1 = fmaxf(mn1, __shfl_xor_sync(0xffffffffu, mn1, 2));
        float fac0 = __expf(m0 - mn0), fac1 = __expf(m1 - mn1);
        m0 = mn0; m1 = mn1;

        uint32_t pa[4][4];
        float ps0 = 0.0f, ps1 = 0.0f;
#pragma unroll
        for (int kk = 0; kk < 4; kk++) {
            int nt = 2 * kk;
            float p00 = __expf(s[nt][0] - m0),     p01 = __expf(s[nt][1] - m0);
            float p02 = __expf(s[nt][2] - m1),     p03 = __expf(s[nt][3] - m1);
            float p10 = __expf(s[nt + 1][0] - m0), p11 = __expf(s[nt + 1][1] - m0);
            float p12 = __expf(s[nt + 1][2] - m1), p13 = __expf(s[nt + 1][3] - m1);
            ps0 += p00 + p01 + p10 + p11;
            ps1 += p02 + p03 + p12 + p13;
            __half2 a0 = __floats2half2_rn(p00, p01);
            __half2 a1 = __floats2half2_rn(p02, p03);
            __half2 a2 = __floats2half2_rn(p10, p11);
            __half2 a3 = __floats2half2_rn(p12, p13);
            pa[kk][0] = *(uint32_t*)&a0;
            pa[kk][1] = *(uint32_t*)&a1;
            pa[kk][2] = *(uint32_t*)&a2;
            pa[kk][3] = *(uint32_t*)&a3;
        }
        l0 = l0 * fac0 + ps0;
        l1 = l1 * fac1 + ps1;

#pragma unroll
        for (int nt = 0; nt < 16; nt++) {
            o[nt][0] *= fac0; o[nt][1] *= fac0;
            o[nt][2] *= fac1; o[nt][3] *= fac1;
        }

#pragma unroll
        for (int kk = 0; kk < 4; kk++) {
            uint32_t vb[8][4];
#pragma unroll
            for (int np = 0; np < 8; np++)
                ldsm4t(vb[np], uVh + vfrag + (kk * 16 * SKP + np * 16) * 2);
#pragma unroll
            for (int nt = 0; nt < 16; nt++)
                mma16816h(o[nt], pa[kk], &vb[nt >> 1][(nt & 1) * 2]);
        }
    }

    l0 += __shfl_xor_sync(0xffffffffu, l0, 1);
    l0 += __shfl_xor_sync(0xffffffffu, l0, 2);
    l1 += __shfl_xor_sync(0xffffffffu, l1, 1);
    l1 += __shfl_xor_sync(0xffffffffu, l1, 2);
    float inv0 = 1.0f / l0, inv1 = 1.0f / l1;

    size_t row0 = (size_t)b * T_ + rg0;
    size_t row1 = (size_t)b * T_ + rg1;
#pragma unroll
    for (int nt = 0; nt < 16; nt++) {
        int col = h * HD + nt * 8 + tg * 2;
        float2 v0 = {o[nt][0] * inv0, o[nt][1] * inv0};
        float2 v1 = {o[nt][2] * inv1, o[nt][3] * inv1};
        __half2 h0 = __floats2half2_rn(v0.x, v0.y);
        __half2 h1 = __floats2half2_rn(v1.x, v1.y);
        float2 f0 = __half22float2(h0), f1 = __half22float2(h1);
        __half2 e0 = __floats2half2_rn(v0.x - f0.x, v0.y - f0.y);
        __half2 e1 = __floats2half2_rn(v1.x - f1.x, v1.y - f1.y);
        *(uint32_t*)(Yh + row0 * C_ + col) = *(uint32_t*)&h0;
        *(uint32_t*)(Yh + row1 * C_ + col) = *(uint32_t*)&h1;
        *(uint32_t*)(Yl + row0 * C_ + col) = *(uint32_t*)&e0;
        *(uint32_t*)(Yl + row1 * C_ + col) = *(uint32_t*)&e1;
    }
}

// ---------------------------------------------------------------------------
extern "C" void kernel_launch(void* const* d_in, const int* in_sizes, int n_in,
                              void* d_out, int out_size)
{
    const float* x  = (const float*)d_in[0];
    const float* Wq = (const float*)d_in[1];
    const float* Wk = (const float*)d_in[2];
    const float* Wv = (const float*)d_in[3];
    const float* Wo = (const float*)d_in[4];
    const int*  pos = (const int*)d_in[5];
    float* out = (float*)d_out;

    float *q, *k, *v;
    cudaGetSymbolAddress((void**)&q, g_q);
    cudaGetSymbolAddress((void**)&k, g_k);
    cudaGetSymbolAddress((void**)&v, g_v);
    __half *qh, *ql, *kh, *kd, *vh;
    cudaGetSymbolAddress((void**)&qh, s_qh); cudaGetSymbolAddress((void**)&ql, s_ql);
    cudaGetSymbolAddress((void**)&kh, s_kh); cudaGetSymbolAddress((void**)&kd, s_kdummy);
    cudaGetSymbolAddress((void**)&vh, s_vh);
    __half *xh, *xl, *yh, *yl, *wqh, *wkh, *wvh, *woh;
    cudaGetSymbolAddress((void**)&xh, s_xh);   cudaGetSymbolAddress((void**)&xl, s_xl);
    cudaGetSymbolAddress((void**)&yh, s_yh);   cudaGetSymbolAddress((void**)&yl, s_yl);
    cudaGetSymbolAddress((void**)&wqh, s_wqh);
    cudaGetSymbolAddress((void**)&wkh, s_wkh);
    cudaGetSymbolAddress((void**)&wvh, s_wvh);
    cudaGetSymbolAddress((void**)&woh, s_woh);

    cudaFuncSetAttribute(flash_mma, cudaFuncAttributeMaxDynamicSharedMemorySize,
                         FL_SMEM);

    // split x (fp16 hi/lo)
    {
        int n4 = M_ * C_ / 4;
        split_kernel<<<(n4 + 255) / 256, 256>>>(x, xh, xl, n4);
    }
    // transpose weights (fp16 hi only)
    transpose_half_kernel<<<dim3(C_ / 32,  C_ / 32), dim3(32, 8)>>>(Wq, wqh, C_, C_);
    transpose_half_kernel<<<dim3(KVD / 32, C_ / 32), dim3(32, 8)>>>(Wk, wkh, C_, KVD);
    transpose_half_kernel<<<dim3(KVD / 32, C_ / 32), dim3(32, 8)>>>(Wv, wvh, C_, KVD);
    transpose_half_kernel<<<dim3(C_ / 32,  C_ / 32), dim3(32, 8)>>>(Wo, woh, C_, C_);

    // projections (fp16 2-pass tensor-core GEMMs)
    gemm_mma<<<dim3(C_ / 128,  M_ / 128), 256>>>(xh, xl, wqh, q, C_,  C_);
    gemm_mma<<<dim3(KVD / 128, M_ / 128), 256>>>(xh, xl, wkh, k, KVD, C_);
    gemm_mma<<<dim3(KVD / 128, M_ / 128), 256>>>(xh, xl, wvh, v, KVD, C_);

    // RoPE + split q (hi/lo used), k (hi used; lo to dummy); v -> fp16
    int qp = M_ * NH * 64;
    rope_split_kernel<<<(qp + 255) / 256, 256>>>(q, qh, ql, pos, NH, qp);
    int kp = M_ * NKV * 64;
    rope_split_kernel<<<(kp + 255) / 256, 256>>>(k, kh, kd, pos, NKV, kp);
    {
        int n4 = M_ * KVD / 4;
        half_kernel<<<(n4 + 255) / 256, 256>>>(v, vh, n4);
    }

    // attention (fp16 2-pass QK, fp16 PV), writes fp16 hi/lo y
    flash_mma<<<dim3(T_ / 128, NH, B_), 256, FL_SMEM>>>(qh, ql, kh, vh, yh, yl);

    // output projection
    gemm_mma<<<dim3(C_ / 128, M_ / 128), 256>>>(yh, yl, woh, out, C_, C_);
}

// round 9
// speedup vs baseline: 1.4731x; 1.0358x over previous
#include <cuda_runtime.h>
#include <cuda_fp16.h>
#include <math.h>
#include <stdint.h>

#define B_   4
#define T_   2048
#define C_   2048
#define NH   16
#define NKV  4
#define HD   128
#define KVD  (NKV*HD)   // 512
#define M_   (B_*T_)    // 8192

// ---------------- scratch (__device__ globals; no allocs allowed) ----------
__device__ __half s_qh[(size_t)M_ * C_],  s_ql[(size_t)M_ * C_];
__device__ __half s_kh[(size_t)M_ * KVD];
__device__ __half s_vh[(size_t)M_ * KVD];

__device__ __half s_xh[(size_t)M_ * C_],  s_xl[(size_t)M_ * C_];
__device__ __half s_yh[(size_t)M_ * C_],  s_yl[(size_t)M_ * C_];
__device__ __half s_wqh[(size_t)C_ * C_];
__device__ __half s_wkh[(size_t)KVD * C_];
__device__ __half s_wvh[(size_t)KVD * C_];
__device__ __half s_woh[(size_t)C_ * C_];

// ---------------- helpers ---------------------------------------------------
__device__ __forceinline__ uint32_t smem_u32(const void* p) {
    uint32_t a;
    asm("{ .reg .u64 t; cvta.to.shared.u64 t, %1; cvt.u32.u64 %0, t; }"
        : "=r"(a) : "l"(p));
    return a;
}
__device__ __forceinline__ void ldsm4(uint32_t* r, uint32_t addr) {
    asm volatile("ldmatrix.sync.aligned.m8n8.x4.shared.b16 {%0,%1,%2,%3}, [%4];"
                 : "=r"(r[0]), "=r"(r[1]), "=r"(r[2]), "=r"(r[3]) : "r"(addr));
}
__device__ __forceinline__ void ldsm4t(uint32_t* r, uint32_t addr) {
    asm volatile("ldmatrix.sync.aligned.m8n8.x4.trans.shared.b16 {%0,%1,%2,%3}, [%4];"
                 : "=r"(r[0]), "=r"(r[1]), "=r"(r[2]), "=r"(r[3]) : "r"(addr));
}
__device__ __forceinline__ void mma16816h(float* c, const uint32_t* a,
                                          const uint32_t* b) {
    asm volatile(
        "mma.sync.aligned.m16n8k16.row.col.f32.f16.f16.f32 "
        "{%0,%1,%2,%3}, {%4,%5,%6,%7}, {%8,%9}, {%0,%1,%2,%3};"
        : "+f"(c[0]), "+f"(c[1]), "+f"(c[2]), "+f"(c[3])
        : "r"(a[0]), "r"(a[1]), "r"(a[2]), "r"(a[3]), "r"(b[0]), "r"(b[1]));
}

// ---------------------------------------------------------------------------
// split: fp32 -> (fp16 hi, fp16 lo), vectorized x4
// ---------------------------------------------------------------------------
__global__ void split_kernel(const float* __restrict__ X,
                             __half* __restrict__ H,
                             __half* __restrict__ L, int n4)
{
    int i = blockIdx.x * blockDim.x + threadIdx.x;
    if (i >= n4) return;
    float4 v = ((const float4*)X)[i];
    float vv[4] = {v.x, v.y, v.z, v.w};
    __half h[4], l[4];
#pragma unroll
    for (int j = 0; j < 4; j++) {
        h[j] = __float2half(vv[j]);
        l[j] = __float2half(vv[j] - __half2float(h[j]));
    }
    __half2 h0 = {h[0], h[1]}, h1 = {h[2], h[3]};
    __half2 l0 = {l[0], l[1]}, l1 = {l[2], l[3]};
    ((__half2*)H)[2 * i]     = h0;
    ((__half2*)H)[2 * i + 1] = h1;
    ((__half2*)L)[2 * i]     = l0;
    ((__half2*)L)[2 * i + 1] = l1;
}

// ---------------------------------------------------------------------------
// transpose: W[K,N] fp32 -> Th [N,K] fp16 (hi only — 2-pass scheme)
// ---------------------------------------------------------------------------
__global__ void transpose_half_kernel(const float* __restrict__ W,
                                      __half* __restrict__ Th, int K, int N)
{
    __shared__ float t[32][33];
    int n0 = blockIdx.x * 32, k0 = blockIdx.y * 32;
    int tx = threadIdx.x, ty = threadIdx.y;  // 32 x 8
#pragma unroll
    for (int j = 0; j < 4; j++)
        t[ty + 8 * j][tx] = W[(size_t)(k0 + ty + 8 * j) * N + n0 + tx];
    __syncthreads();
#pragma unroll
    for (int j = 0; j < 4; j++)
        Th[(size_t)(n0 + ty + 8 * j) * K + k0 + tx] =
            __float2half(t[tx][ty + 8 * j]);
}

// ---------------------------------------------------------------------------
// Fused QKV projection + RoPE + fp16 split, fp16 2-pass mma.sync GEMM.
// Grid x: 0-15 -> Q n-tiles, 16-19 -> K, 20-23 -> V. CTA 128x128, BK=32.
// Warp covers cols [wn*16,+16) U [wn*16+64,+16) so rope pairs (c, c+64)
// land in one thread (frag nt and nt+2). RoPE applied on fp32 accumulators.
// ---------------------------------------------------------------------------
#define SAS 40

__global__ __launch_bounds__(256) void qkv_gemm(
    const __half* __restrict__ Ah, const __half* __restrict__ Al,
    const __half* __restrict__ Wqh, const __half* __restrict__ Wkh,
    const __half* __restrict__ Wvh,
    __half* __restrict__ Qh, __half* __restrict__ Ql,
    __half* __restrict__ Kh, __half* __restrict__ Vh,
    const int* __restrict__ posp)
{
    __shared__ __half sAh[128 * SAS], sAl[128 * SAS], sBh[128 * SAS];
    const int K = C_;

    const int tid = threadIdx.x;
    const int lane = tid & 31, wid = tid >> 5;
    const int wm = wid & 1, wn = wid >> 1;
    const int m0 = blockIdx.y * 128;
    const int nq = blockIdx.x;

    const __half* Bp;
    int mode;                      // 0=Q(rope,hi/lo) 1=K(rope,hi) 2=V(convert)
    if (nq < 16)      { Bp = Wqh + (size_t)nq * 128 * K;        mode = 0; }
    else if (nq < 20) { Bp = Wkh + (size_t)(nq - 16) * 128 * K; mode = 1; }
    else              { Bp = Wvh + (size_t)(nq - 20) * 128 * K; mode = 2; }

    const int ldrow = tid >> 1, ldhalf = tid & 1;
    const __half* gAh = Ah + (size_t)(m0 + ldrow) * K + ldhalf * 16;
    const __half* gAl = Al + (size_t)(m0 + ldrow) * K + ldhalf * 16;
    const __half* gBh = Bp + (size_t)ldrow * K + ldhalf * 16;
    char* stAh = (char*)sAh + (ldrow * SAS + ldhalf * 16) * 2;
    char* stAl = (char*)sAl + (ldrow * SAS + ldhalf * 16) * 2;
    char* stBh = (char*)sBh + (ldrow * SAS + ldhalf * 16) * 2;

    const int mid = lane >> 3, rin = lane & 7;
    const uint32_t aoff =
        ((wm * 64 + (mid & 1) * 8 + rin) * SAS + (mid >> 1) * 8) * 2;
    const uint32_t boff =
        ((wn * 16 + (mid >> 1) * 8 + rin) * SAS + (mid & 1) * 8) * 2;
    const uint32_t uAh = smem_u32(sAh) + aoff, uAl = smem_u32(sAl) + aoff;
    const uint32_t uBh = smem_u32(sBh) + boff;

    float acc[4][4][4];
#pragma unroll
    for (int mt = 0; mt < 4; mt++)
#pragma unroll
        for (int nt = 0; nt < 4; nt++)
#pragma unroll
            for (int j = 0; j < 4; j++) acc[mt][nt][j] = 0.0f;

    uint4 rah[2], ral[2], rbh[2];

#define GLOAD(k0)                                            \
    {                                                        \
        rah[0] = *(const uint4*)(gAh + (k0));                \
        rah[1] = *(const uint4*)(gAh + (k0) + 8);            \
        ral[0] = *(const uint4*)(gAl + (k0));                \
        ral[1] = *(const uint4*)(gAl + (k0) + 8);            \
        rbh[0] = *(const uint4*)(gBh + (k0));                \
        rbh[1] = *(const uint4*)(gBh + (k0) + 8);            \
    }
#define SSTORE()                                             \
    {                                                        \
        *(uint4*)(stAh) = rah[0]; *(uint4*)(stAh + 16) = rah[1]; \
        *(uint4*)(stAl) = ral[0]; *(uint4*)(stAl + 16) = ral[1]; \
        *(uint4*)(stBh) = rbh[0]; *(uint4*)(stBh + 16) = rbh[1]; \
    }

    GLOAD(0);
    SSTORE();
    __syncthreads();

    const int nch = K / 32;
    for (int ch = 0; ch < nch; ch++) {
        const bool more = (ch + 1 < nch);
        if (more) GLOAD((ch + 1) * 32);

#pragma unroll
        for (int ks = 0; ks < 2; ks++) {
            uint32_t fah[4][4], fal[4][4], fbh[2][4];
#pragma unroll
            for (int mt = 0; mt < 4; mt++) {
                ldsm4(fah[mt], uAh + mt * (16 * SAS * 2) + ks * 32);
                ldsm4(fal[mt], uAl + mt * (16 * SAS * 2) + ks * 32);
            }
            ldsm4(fbh[0], uBh + ks * 32);
            ldsm4(fbh[1], uBh + 64 * (SAS * 2) + ks * 32);
#pragma unroll
            for (int mt = 0; mt < 4; mt++)
#pragma unroll
                for (int nt = 0; nt < 4; nt++) {
                    const uint32_t* b_h = &fbh[nt >> 1][(nt & 1) * 2];
                    mma16816h(acc[mt][nt], fah[mt], b_h);
                    mma16816h(acc[mt][nt], fal[mt], b_h);
                }
        }
        __syncthreads();
        if (more) SSTORE();
        __syncthreads();
    }
#undef GLOAD
#undef SSTORE

    const int g = lane >> 2, tg = lane & 3;

    if (mode == 2) {
        // V: plain fp16 convert. col(nt) = wn*16 + (nt&1)*8 + (nt>=2)*64 + tg*2
        const int coff = (nq - 20) * 128;
#pragma unroll
        for (int mt = 0; mt < 4; mt++) {
            const int r0 = m0 + wm * 64 + mt * 16 + g;
#pragma unroll
            for (int nt = 0; nt < 4; nt++) {
                const int c = wn * 16 + (nt & 1) * 8 + ((nt & 2) ? 64 : 0) + tg * 2;
                __half2 h0 = __floats2half2_rn(acc[mt][nt][0], acc[mt][nt][1]);
                __half2 h1 = __floats2half2_rn(acc[mt][nt][2], acc[mt][nt][3]);
                *(uint32_t*)(Vh + (size_t)r0 * KVD + coff + c)       = *(uint32_t*)&h0;
                *(uint32_t*)(Vh + (size_t)(r0 + 8) * KVD + coff + c) = *(uint32_t*)&h1;
            }
        }
        return;
    }

    // Q/K: RoPE on accumulator pairs (nt, nt+2) = cols (c, c+64)
    const int posv = posp[0];
    const float LN1E4_128 = 9.210340371976184f / 128.0f;
#pragma unroll
    for (int mt = 0; mt < 4; mt++) {
        const int mr = m0 + wm * 64 + mt * 16 + g;
#pragma unroll
        for (int nt = 0; nt < 2; nt++) {
            const int c = wn * 16 + nt * 8 + tg * 2;          // even, < 64
            const float f1 = __expf(-(float)(2 * (c >> 1)) * LN1E4_128);
            const float f2 = f1 * 0.01f;
#pragma unroll
            for (int rj = 0; rj < 2; rj++) {
                const int row = mr + rj * 8;
                const float pos = (float)(posv + (row & (T_ - 1)));
                const float a1 = pos * f1, a2 = pos * f2;
                const float c1 = cosf(a1), s1 = sinf(a1);
                const float c2 = cosf(a2), s2 = sinf(a2);
                float o1[2], o2[2];
#pragma unroll
                for (int jj = 0; jj < 2; jj++) {
                    const float x1 = acc[mt][nt][rj * 2 + jj];
                    const float x2 = acc[mt][nt + 2][rj * 2 + jj];
                    o1[jj] = x1 * c1 - x2 * s1;
                    o2[jj] = x2 * c2 + x1 * s2;
                }
                __half2 hi1 = __floats2half2_rn(o1[0], o1[1]);
                __half2 hi2 = __floats2half2_rn(o2[0], o2[1]);
                if (mode == 0) {
                    float2 hf1 = __half22float2(hi1), hf2 = __half22float2(hi2);
                    __half2 lo1 = __floats2half2_rn(o1[0] - hf1.x, o1[1] - hf1.y);
                    __half2 lo2 = __floats2half2_rn(o2[0] - hf2.x, o2[1] - hf2.y);
                    size_t base = (size_t)row * C_ + nq * 128 + c;
                    *(uint32_t*)(Qh + base)      = *(uint32_t*)&hi1;
                    *(uint32_t*)(Ql + base)      = *(uint32_t*)&lo1;
                    *(uint32_t*)(Qh + base + 64) = *(uint32_t*)&hi2;
                    *(uint32_t*)(Ql + base + 64) = *(uint32_t*)&lo2;
                } else {
                    size_t base = (size_t)row * KVD + (nq - 16) * 128 + c;
                    *(uint32_t*)(Kh + base)      = *(uint32_t*)&hi1;
                    *(uint32_t*)(Kh + base + 64) = *(uint32_t*)&hi2;
                }
            }
        }
    }
}

// ---------------------------------------------------------------------------
// fp16 2-pass GEMM via mma.sync (Wo projection, fp32 out) — unchanged R8 core
// ---------------------------------------------------------------------------
__global__ __launch_bounds__(256) void gemm_mma(
    const __half* __restrict__ Ah, const __half* __restrict__ Al,
    const __half* __restrict__ Bh,
    float* __restrict__ C, int N, int K)
{
    __shared__ __half sAh[128 * SAS], sAl[128 * SAS], sBh[128 * SAS];

    const int tid = threadIdx.x;
    const int lane = tid & 31, wid = tid >> 5;
    const int wm = wid & 1, wn = wid >> 1;
    const int m0 = blockIdx.y * 128, n0 = blockIdx.x * 128;

    const int ldrow = tid >> 1, ldhalf = tid & 1;
    const __half* gAh = Ah + (size_t)(m0 + ldrow) * K + ldhalf * 16;
    const __half* gAl = Al + (size_t)(m0 + ldrow) * K + ldhalf * 16;
    const __half* gBh = Bh + (size_t)(n0 + ldrow) * K + ldhalf * 16;
    char* stAh = (char*)sAh + (ldrow * SAS + ldhalf * 16) * 2;
    char* stAl = (char*)sAl + (ldrow * SAS + ldhalf * 16) * 2;
    char* stBh = (char*)sBh + (ldrow * SAS + ldhalf * 16) * 2;

    const int mid = lane >> 3, rin = lane & 7;
    const uint32_t aoff =
        ((wm * 64 + (mid & 1) * 8 + rin) * SAS + (mid >> 1) * 8) * 2;
    const uint32_t boff =
        ((wn * 32 + (mid >> 1) * 8 + rin) * SAS + (mid & 1) * 8) * 2;
    const uint32_t uAh = smem_u32(sAh) + aoff, uAl = smem_u32(sAl) + aoff;
    const uint32_t uBh = smem_u32(sBh) + boff;

    float acc[4][4][4];
#pragma unroll
    for (int mt = 0; mt < 4; mt++)
#pragma unroll
        for (int nt = 0; nt < 4; nt++)
#pragma unroll
            for (int j = 0; j < 4; j++) acc[mt][nt][j] = 0.0f;

    uint4 rah[2], ral[2], rbh[2];

#define GLOAD(k0)                                            \
    {                                                        \
        rah[0] = *(const uint4*)(gAh + (k0));                \
        rah[1] = *(const uint4*)(gAh + (k0) + 8);            \
        ral[0] = *(const uint4*)(gAl + (k0));                \
        ral[1] = *(const uint4*)(gAl + (k0) + 8);            \
        rbh[0] = *(const uint4*)(gBh + (k0));                \
        rbh[1] = *(const uint4*)(gBh + (k0) + 8);            \
    }
#define SSTORE()                                             \
    {                                                        \
        *(uint4*)(stAh) = rah[0]; *(uint4*)(stAh + 16) = rah[1]; \
        *(uint4*)(stAl) = ral[0]; *(uint4*)(stAl + 16) = ral[1]; \
        *(uint4*)(stBh) = rbh[0]; *(uint4*)(stBh + 16) = rbh[1]; \
    }

    GLOAD(0);
    SSTORE();
    __syncthreads();

    const int nch = K / 32;
    for (int ch = 0; ch < nch; ch++) {
        const bool more = (ch + 1 < nch);
        if (more) GLOAD((ch + 1) * 32);

#pragma unroll
        for (int ks = 0; ks < 2; ks++) {
            uint32_t fah[4][4], fal[4][4], fbh[2][4];
#pragma unroll
            for (int mt = 0; mt < 4; mt++) {
                ldsm4(fah[mt], uAh + mt * (16 * SAS * 2) + ks * 32);
                ldsm4(fal[mt], uAl + mt * (16 * SAS * 2) + ks * 32);
            }
#pragma unroll
            for (int np = 0; np < 2; np++)
                ldsm4(fbh[np], uBh + np * (16 * SAS * 2) + ks * 32);
#pragma unroll
            for (int mt = 0; mt < 4; mt++)
#pragma unroll
                for (int nt = 0; nt < 4; nt++) {
                    const uint32_t* b_h = &fbh[nt >> 1][(nt & 1) * 2];
                    mma16816h(acc[mt][nt], fah[mt], b_h);
                    mma16816h(acc[mt][nt], fal[mt], b_h);
                }
        }
        __syncthreads();
        if (more) SSTORE();
        __syncthreads();
    }
#undef GLOAD
#undef SSTORE

    const int g = lane >> 2, tg = lane & 3;
#pragma unroll
    for (int mt = 0; mt < 4; mt++) {
        const int mrow = m0 + wm * 64 + mt * 16 + g;
#pragma unroll
        for (int nt = 0; nt < 4; nt++) {
            const int ncol = n0 + wn * 32 + nt * 8 + tg * 2;
            float2 v0 = {acc[mt][nt][0], acc[mt][nt][1]};
            float2 v1 = {acc[mt][nt][2], acc[mt][nt][3]};
            *(float2*)(C + (size_t)mrow * N + ncol)       = v0;
            *(float2*)(C + (size_t)(mrow + 8) * N + ncol) = v1;
        }
    }
}

// ---------------------------------------------------------------------------
// Flash attention on mma.sync, fp16 2-pass QK (Qh,Ql vs Kh), fp16 PV.
// ---------------------------------------------------------------------------
#define SKP 136
#define FL_SMEM (2 * 64 * SKP * 2)

extern __shared__ char dynsm[];

__global__ __launch_bounds__(256) void flash_mma(
    const __half* __restrict__ Qh, const __half* __restrict__ Ql,
    const __half* __restrict__ Khg, const __half* __restrict__ Vhg,
    __half* __restrict__ Yh, __half* __restrict__ Yl)
{
    __half* sKh = (__half*)dynsm;
    __half* sVh = sKh + 64 * SKP;

    const int tid = threadIdx.x, lane = tid & 31, w = tid >> 5;
    const int qb = blockIdx.x, h = blockIdx.y, b = blockIdx.z;
    const int kvh = h >> 2;
    const int g = lane >> 2, tg = lane & 3;
    const int mid = lane >> 3, rin = lane & 7;
    const int qrow0 = qb * 128 + w * 16;

    uint32_t qh[8][4], ql[8][4];
    {
        const __half* Qhb = Qh + ((size_t)b * T_ + qrow0) * C_ + h * HD;
        const __half* Qlb = Ql + ((size_t)b * T_ + qrow0) * C_ + h * HD;
#pragma unroll
        for (int kc = 0; kc < 8; kc++) {
#pragma unroll
            for (int fr = 0; fr < 4; fr++) {
                int r = g + (fr & 1) * 8;
                int c = kc * 16 + tg * 2 + (fr >> 1) * 8;
                qh[kc][fr] = *(const uint32_t*)(Qhb + (size_t)r * C_ + c);
                ql[kc][fr] = *(const uint32_t*)(Qlb + (size_t)r * C_ + c);
            }
        }
    }

    float o[16][4];
#pragma unroll
    for (int nt = 0; nt < 16; nt++)
#pragma unroll
        for (int j = 0; j < 4; j++) o[nt][j] = 0.0f;
    float m0 = -INFINITY, m1 = -INFINITY, l0 = 0.0f, l1 = 0.0f;

    const float cscale = 0.08838834764831845f;
    const int rg0 = qrow0 + g, rg1 = rg0 + 8;
    const int ktmax = 2 * qb + 2;

    const __half* Kh0 = Khg + (size_t)b * T_ * KVD + kvh * HD;
    const __half* Vh0 = Vhg + (size_t)b * T_ * KVD + kvh * HD;

    const uint32_t uKh = smem_u32(sKh), uVh = smem_u32(sVh);
    const uint32_t kfrag = (((mid >> 1) * 8 + rin) * SKP + (mid & 1) * 8) * 2;
    const uint32_t vfrag = (((mid & 1) * 8 + rin) * SKP + (mid >> 1) * 8) * 2;

    for (int kt = 0; kt < ktmax; kt++) {
        __syncthreads();
        {
            const __half* Kht = Kh0 + (size_t)kt * 64 * KVD;
            const __half* Vht = Vh0 + (size_t)kt * 64 * KVD;
#pragma unroll
            for (int it = 0; it < 4; it++) {
                int i = tid + it * 256;
                int r = i >> 4, c8 = (i & 15) << 3;
                *(uint4*)(sKh + r * SKP + c8) = *(const uint4*)(Kht + (size_t)r * KVD + c8);
                *(uint4*)(sVh + r * SKP + c8) = *(const uint4*)(Vht + (size_t)r * KVD + c8);
            }
        }
        __syncthreads();

        if (kt * 64 > qrow0 + 15) continue;
        const bool needmask = (kt * 64 + 63 > qrow0);

        float s[8][4];
#pragma unroll
        for (int nt = 0; nt < 8; nt++)
#pragma unroll
            for (int j = 0; j < 4; j++) s[nt][j] = 0.0f;

#pragma unroll
        for (int kc = 0; kc < 8; kc++) {
            uint32_t bt[4][4];
#pragma unroll
            for (int nt2 = 0; nt2 < 4; nt2++)
                ldsm4(bt[nt2], uKh + kfrag + (nt2 * 16 * SKP + kc * 16) * 2);
#pragma unroll
            for (int nt = 0; nt < 8; nt++) {
                const uint32_t* bb = &bt[nt >> 1][(nt & 1) * 2];
                mma16816h(s[nt], qh[kc], bb);
                mma16816h(s[nt], ql[kc], bb);
            }
        }

#pragma unroll
        for (int nt = 0; nt < 8; nt++) {
#pragma unroll
            for (int j = 0; j < 4; j++) s[nt][j] *= cscale;
            if (needmask) {
                int c0 = kt * 64 + nt * 8 + tg * 2;
                if (c0 > rg0)     s[nt][0] = -1e30f;
                if (c0 + 1 > rg0) s[nt][1] = -1e30f;
                if (c0 > rg1)     s[nt][2] = -1e30f;
                if (c0 + 1 > rg1) s[nt][3] = -1e30f;
            }
        }

        float mn0 = m0, mn1 = m1;
#pragma unroll
        for (int nt = 0; nt < 8; nt++) {
            mn0 = fmaxf(mn0, fmaxf(s[nt][0], s[nt][1]));
            mn1 = fmaxf(mn1, fmaxf(s[nt][2], s[nt][3]));
        }
        mn0 = fmaxf(mn0, __shfl_xor_sync(0xffffffffu, mn0, 1));
        mn0 = fmaxf(mn0, __shfl_xor_sync(0xffffffffu, mn0, 2));
        mn1 = fmaxf(mn1, __shfl_xor_sync(0xffffffffu, mn1, 1));
        mn1 = fmaxf(mn1, __shfl_xor_sync(0xffffffffu, mn1, 2));
        float fac0 = __expf(m0 - mn0), fac1 = __expf(m1 - mn1);
        m0 = mn0; m1 = mn1;

        uint32_t pa[4][4];
        float ps0 = 0.0f, ps1 = 0.0f;
#pragma unroll
        for (int kk = 0; kk < 4; kk++) {
            int nt = 2 * kk;
            float p00 = __expf(s[nt][0] - m0),     p01 = __expf(s[nt][1] - m0);
            float p02 = __expf(s[nt][2] - m1),     p03 = __expf(s[nt][3] - m1);
            float p10 = __expf(s[nt + 1][0] - m0), p11 = __expf(s[nt + 1][1] - m0);
            float p12 = __expf(s[nt + 1][2] - m1), p13 = __expf(s[nt + 1][3] - m1);
            ps0 += p00 + p01 + p10 + p11;
            ps1 += p02 + p03 + p12 + p13;
            __half2 a0 = __floats2half2_rn(p00, p01);
            __half2 a1 = __floats2half2_rn(p02, p03);
            __half2 a2 = __floats2half2_rn(p10, p11);
            __half2 a3 = __floats2half2_rn(p12, p13);
            pa[kk][0] = *(uint32_t*)&a0;
            pa[kk][1] = *(uint32_t*)&a1;
            pa[kk][2] = *(uint32_t*)&a2;
            pa[kk][3] = *(uint32_t*)&a3;
        }
        l0 = l0 * fac0 + ps0;
        l1 = l1 * fac1 + ps1;

#pragma unroll
        for (int nt = 0; nt < 16; nt++) {
            o[nt][0] *= fac0; o[nt][1] *= fac0;
            o[nt][2] *= fac1; o[nt][3] *= fac1;
        }

#pragma unroll
        for (int kk = 0; kk < 4; kk++) {
            uint32_t vb[8][4];
#pragma unroll
            for (int np = 0; np < 8; np++)
                ldsm4t(vb[np], uVh + vfrag + (kk * 16 * SKP + np * 16) * 2);
#pragma unroll
            for (int nt = 0; nt < 16; nt++)
                mma16816h(o[nt], pa[kk], &vb[nt >> 1][(nt & 1) * 2]);
        }
    }

    l0 += __shfl_xor_sync(0xffffffffu, l0, 1);
    l0 += __shfl_xor_sync(0xffffffffu, l0, 2);
    l1 += __shfl_xor_sync(0xffffffffu, l1, 1);
    l1 += __shfl_xor_sync(0xffffffffu, l1, 2);
    float inv0 = 1.0f / l0, inv1 = 1.0f / l1;

    size_t row0 = (size_t)b * T_ + rg0;
    size_t row1 = (size_t)b * T_ + rg1;
#pragma unroll
    for (int nt = 0; nt < 16; nt++) {
        int col = h * HD + nt * 8 + tg * 2;
        float2 v0 = {o[nt][0] * inv0, o[nt][1] * inv0};
        float2 v1 = {o[nt][2] * inv1, o[nt][3] * inv1};
        __half2 h0 = __floats2half2_rn(v0.x, v0.y);
        __half2 h1 = __floats2half2_rn(v1.x, v1.y);
        float2 f0 = __half22float2(h0), f1 = __half22float2(h1);
        __half2 e0 = __floats2half2_rn(v0.x - f0.x, v0.y - f0.y);
        __half2 e1 = __floats2half2_rn(v1.x - f1.x, v1.y - f1.y);
        *(uint32_t*)(Yh + row0 * C_ + col) = *(uint32_t*)&h0;
        *(uint32_t*)(Yh + row1 * C_ + col) = *(uint32_t*)&h1;
        *(uint32_t*)(Yl + row0 * C_ + col) = *(uint32_t*)&e0;
        *(uint32_t*)(Yl + row1 * C_ + col) = *(uint32_t*)&e1;
    }
}

// ---------------------------------------------------------------------------
extern "C" void kernel_launch(void* const* d_in, const int* in_sizes, int n_in,
                              void* d_out, int out_size)
{
    const float* x  = (const float*)d_in[0];
    const float* Wq = (const float*)d_in[1];
    const float* Wk = (const float*)d_in[2];
    const float* Wv = (const float*)d_in[3];
    const float* Wo = (const float*)d_in[4];
    const int*  pos = (const int*)d_in[5];
    float* out = (float*)d_out;

    __half *qh, *ql, *kh, *vh;
    cudaGetSymbolAddress((void**)&qh, s_qh); cudaGetSymbolAddress((void**)&ql, s_ql);
    cudaGetSymbolAddress((void**)&kh, s_kh); cudaGetSymbolAddress((void**)&vh, s_vh);
    __half *xh, *xl, *yh, *yl, *wqh, *wkh, *wvh, *woh;
    cudaGetSymbolAddress((void**)&xh, s_xh);   cudaGetSymbolAddress((void**)&xl, s_xl);
    cudaGetSymbolAddress((void**)&yh, s_yh);   cudaGetSymbolAddress((void**)&yl, s_yl);
    cudaGetSymbolAddress((void**)&wqh, s_wqh);
    cudaGetSymbolAddress((void**)&wkh, s_wkh);
    cudaGetSymbolAddress((void**)&wvh, s_wvh);
    cudaGetSymbolAddress((void**)&woh, s_woh);

    cudaFuncSetAttribute(flash_mma, cudaFuncAttributeMaxDynamicSharedMemorySize,
                         FL_SMEM);

    // split x (fp16 hi/lo)
    {
        int n4 = M_ * C_ / 4;
        split_kernel<<<(n4 + 255) / 256, 256>>>(x, xh, xl, n4);
    }
    // transpose weights (fp16 hi only)
    transpose_half_kernel<<<dim3(C_ / 32,  C_ / 32), dim3(32, 8)>>>(Wq, wqh, C_, C_);
    transpose_half_kernel<<<dim3(KVD / 32, C_ / 32), dim3(32, 8)>>>(Wk, wkh, C_, KVD);
    transpose_half_kernel<<<dim3(KVD / 32, C_ / 32), dim3(32, 8)>>>(Wv, wvh, C_, KVD);
    transpose_half_kernel<<<dim3(C_ / 32,  C_ / 32), dim3(32, 8)>>>(Wo, woh, C_, C_);

    // fused QKV projection + RoPE + split (one launch, 24x64 grid)
    qkv_gemm<<<dim3(24, M_ / 128), 256>>>(xh, xl, wqh, wkh, wvh,
                                          qh, ql, kh, vh, pos);

    // attention (fp16 2-pass QK, fp16 PV), writes fp16 hi/lo y
    flash_mma<<<dim3(T_ / 128, NH, B_), 256, FL_SMEM>>>(qh, ql, kh, vh, yh, yl);

    // output projection
    gemm_mma<<<dim3(C_ / 128, M_ / 128), 256>>>(yh, yl, woh, out, C_, C_);
}

// round 10
// speedup vs baseline: 1.6498x; 1.1199x over previous
#include <cuda_runtime.h>
#include <cuda_fp16.h>
#include <math.h>
#include <stdint.h>

#define B_   4
#define T_   2048
#define C_   2048
#define NH   16
#define NKV  4
#define HD   128
#define KVD  (NKV*HD)   // 512
#define M_   (B_*T_)    // 8192

// ---------------- scratch (__device__ globals; no allocs allowed) ----------
__device__ __half s_qh[(size_t)M_ * C_],  s_ql[(size_t)M_ * C_];
__device__ __half s_kh[(size_t)M_ * KVD];
__device__ __half s_vh[(size_t)M_ * KVD];

__device__ __half s_xh[(size_t)M_ * C_],  s_xl[(size_t)M_ * C_];
__device__ __half s_yh[(size_t)M_ * C_];
__device__ __half s_wqh[(size_t)C_ * C_];
__device__ __half s_wkh[(size_t)KVD * C_];
__device__ __half s_wvh[(size_t)KVD * C_];
__device__ __half s_woh[(size_t)C_ * C_];

// ---------------- helpers ---------------------------------------------------
__device__ __forceinline__ uint32_t smem_u32(const void* p) {
    uint32_t a;
    asm("{ .reg .u64 t; cvta.to.shared.u64 t, %1; cvt.u32.u64 %0, t; }"
        : "=r"(a) : "l"(p));
    return a;
}
__device__ __forceinline__ void ldsm4(uint32_t* r, uint32_t addr) {
    asm volatile("ldmatrix.sync.aligned.m8n8.x4.shared.b16 {%0,%1,%2,%3}, [%4];"
                 : "=r"(r[0]), "=r"(r[1]), "=r"(r[2]), "=r"(r[3]) : "r"(addr));
}
__device__ __forceinline__ void ldsm4t(uint32_t* r, uint32_t addr) {
    asm volatile("ldmatrix.sync.aligned.m8n8.x4.trans.shared.b16 {%0,%1,%2,%3}, [%4];"
                 : "=r"(r[0]), "=r"(r[1]), "=r"(r[2]), "=r"(r[3]) : "r"(addr));
}
__device__ __forceinline__ void mma16816h(float* c, const uint32_t* a,
                                          const uint32_t* b) {
    asm volatile(
        "mma.sync.aligned.m16n8k16.row.col.f32.f16.f16.f32 "
        "{%0,%1,%2,%3}, {%4,%5,%6,%7}, {%8,%9}, {%0,%1,%2,%3};"
        : "+f"(c[0]), "+f"(c[1]), "+f"(c[2]), "+f"(c[3])
        : "r"(a[0]), "r"(a[1]), "r"(a[2]), "r"(a[3]), "r"(b[0]), "r"(b[1]));
}

// ---------------------------------------------------------------------------
// split: fp32 -> (fp16 hi, fp16 lo), vectorized x4
// ---------------------------------------------------------------------------
__global__ void split_kernel(const float* __restrict__ X,
                             __half* __restrict__ H,
                             __half* __restrict__ L, int n4)
{
    int i = blockIdx.x * blockDim.x + threadIdx.x;
    if (i >= n4) return;
    float4 v = ((const float4*)X)[i];
    float vv[4] = {v.x, v.y, v.z, v.w};
    __half h[4], l[4];
#pragma unroll
    for (int j = 0; j < 4; j++) {
        h[j] = __float2half(vv[j]);
        l[j] = __float2half(vv[j] - __half2float(h[j]));
    }
    __half2 h0 = {h[0], h[1]}, h1 = {h[2], h[3]};
    __half2 l0 = {l[0], l[1]}, l1 = {l[2], l[3]};
    ((__half2*)H)[2 * i]     = h0;
    ((__half2*)H)[2 * i + 1] = h1;
    ((__half2*)L)[2 * i]     = l0;
    ((__half2*)L)[2 * i + 1] = l1;
}

// ---------------------------------------------------------------------------
// transpose: W[K,N] fp32 -> Th [N,K] fp16 (hi only — 2-pass scheme)
// ---------------------------------------------------------------------------
__global__ void transpose_half_kernel(const float* __restrict__ W,
                                      __half* __restrict__ Th, int K, int N)
{
    __shared__ float t[32][33];
    int n0 = blockIdx.x * 32, k0 = blockIdx.y * 32;
    int tx = threadIdx.x, ty = threadIdx.y;  // 32 x 8
#pragma unroll
    for (int j = 0; j < 4; j++)
        t[ty + 8 * j][tx] = W[(size_t)(k0 + ty + 8 * j) * N + n0 + tx];
    __syncthreads();
#pragma unroll
    for (int j = 0; j < 4; j++)
        Th[(size_t)(n0 + ty + 8 * j) * K + k0 + tx] =
            __float2half(t[tx][ty + 8 * j]);
}

// ---------------------------------------------------------------------------
// Fused QKV projection + RoPE + fp16 split, fp16 2-pass mma.sync GEMM.
// Grid x: 0-15 -> Q n-tiles, 16-19 -> K, 20-23 -> V. CTA 128x128, BK=32.
// Warp covers cols [wn*16,+16) U [wn*16+64,+16) so rope pairs (c, c+64)
// land in one thread (frag nt and nt+2). RoPE applied on fp32 accumulators.
// ---------------------------------------------------------------------------
#define SAS 40

__global__ __launch_bounds__(256) void qkv_gemm(
    const __half* __restrict__ Ah, const __half* __restrict__ Al,
    const __half* __restrict__ Wqh, const __half* __restrict__ Wkh,
    const __half* __restrict__ Wvh,
    __half* __restrict__ Qh, __half* __restrict__ Ql,
    __half* __restrict__ Kh, __half* __restrict__ Vh,
    const int* __restrict__ posp)
{
    __shared__ __half sAh[128 * SAS], sAl[128 * SAS], sBh[128 * SAS];
    const int K = C_;

    const int tid = threadIdx.x;
    const int lane = tid & 31, wid = tid >> 5;
    const int wm = wid & 1, wn = wid >> 1;
    const int m0 = blockIdx.y * 128;
    const int nq = blockIdx.x;

    const __half* Bp;
    int mode;                      // 0=Q(rope,hi/lo) 1=K(rope,hi) 2=V(convert)
    if (nq < 16)      { Bp = Wqh + (size_t)nq * 128 * K;        mode = 0; }
    else if (nq < 20) { Bp = Wkh + (size_t)(nq - 16) * 128 * K; mode = 1; }
    else              { Bp = Wvh + (size_t)(nq - 20) * 128 * K; mode = 2; }

    const int ldrow = tid >> 1, ldhalf = tid & 1;
    const __half* gAh = Ah + (size_t)(m0 + ldrow) * K + ldhalf * 16;
    const __half* gAl = Al + (size_t)(m0 + ldrow) * K + ldhalf * 16;
    const __half* gBh = Bp + (size_t)ldrow * K + ldhalf * 16;
    char* stAh = (char*)sAh + (ldrow * SAS + ldhalf * 16) * 2;
    char* stAl = (char*)sAl + (ldrow * SAS + ldhalf * 16) * 2;
    char* stBh = (char*)sBh + (ldrow * SAS + ldhalf * 16) * 2;

    const int mid = lane >> 3, rin = lane & 7;
    const uint32_t aoff =
        ((wm * 64 + (mid & 1) * 8 + rin) * SAS + (mid >> 1) * 8) * 2;
    const uint32_t boff =
        ((wn * 16 + (mid >> 1) * 8 + rin) * SAS + (mid & 1) * 8) * 2;
    const uint32_t uAh = smem_u32(sAh) + aoff, uAl = smem_u32(sAl) + aoff;
    const uint32_t uBh = smem_u32(sBh) + boff;

    float acc[4][4][4];
#pragma unroll
    for (int mt = 0; mt < 4; mt++)
#pragma unroll
        for (int nt = 0; nt < 4; nt++)
#pragma unroll
            for (int j = 0; j < 4; j++) acc[mt][nt][j] = 0.0f;

    uint4 rah[2], ral[2], rbh[2];

#define GLOAD(k0)                                            \
    {                                                        \
        rah[0] = *(const uint4*)(gAh + (k0));                \
        rah[1] = *(const uint4*)(gAh + (k0) + 8);            \
        ral[0] = *(const uint4*)(gAl + (k0));                \
        ral[1] = *(const uint4*)(gAl + (k0) + 8);            \
        rbh[0] = *(const uint4*)(gBh + (k0));                \
        rbh[1] = *(const uint4*)(gBh + (k0) + 8);            \
    }
#define SSTORE()                                             \
    {                                                        \
        *(uint4*)(stAh) = rah[0]; *(uint4*)(stAh + 16) = rah[1]; \
        *(uint4*)(stAl) = ral[0]; *(uint4*)(stAl + 16) = ral[1]; \
        *(uint4*)(stBh) = rbh[0]; *(uint4*)(stBh + 16) = rbh[1]; \
    }

    GLOAD(0);
    SSTORE();
    __syncthreads();

    const int nch = K / 32;
    for (int ch = 0; ch < nch; ch++) {
        const bool more = (ch + 1 < nch);
        if (more) GLOAD((ch + 1) * 32);

#pragma unroll
        for (int ks = 0; ks < 2; ks++) {
            uint32_t fah[4][4], fal[4][4], fbh[2][4];
#pragma unroll
            for (int mt = 0; mt < 4; mt++) {
                ldsm4(fah[mt], uAh + mt * (16 * SAS * 2) + ks * 32);
                ldsm4(fal[mt], uAl + mt * (16 * SAS * 2) + ks * 32);
            }
            ldsm4(fbh[0], uBh + ks * 32);
            ldsm4(fbh[1], uBh + 64 * (SAS * 2) + ks * 32);
#pragma unroll
            for (int mt = 0; mt < 4; mt++)
#pragma unroll
                for (int nt = 0; nt < 4; nt++) {
                    const uint32_t* b_h = &fbh[nt >> 1][(nt & 1) * 2];
                    mma16816h(acc[mt][nt], fah[mt], b_h);
                    mma16816h(acc[mt][nt], fal[mt], b_h);
                }
        }
        __syncthreads();
        if (more) SSTORE();
        __syncthreads();
    }
#undef GLOAD
#undef SSTORE

    const int g = lane >> 2, tg = lane & 3;

    if (mode == 2) {
        const int coff = (nq - 20) * 128;
#pragma unroll
        for (int mt = 0; mt < 4; mt++) {
            const int r0 = m0 + wm * 64 + mt * 16 + g;
#pragma unroll
            for (int nt = 0; nt < 4; nt++) {
                const int c = wn * 16 + (nt & 1) * 8 + ((nt & 2) ? 64 : 0) + tg * 2;
                __half2 h0 = __floats2half2_rn(acc[mt][nt][0], acc[mt][nt][1]);
                __half2 h1 = __floats2half2_rn(acc[mt][nt][2], acc[mt][nt][3]);
                *(uint32_t*)(Vh + (size_t)r0 * KVD + coff + c)       = *(uint32_t*)&h0;
                *(uint32_t*)(Vh + (size_t)(r0 + 8) * KVD + coff + c) = *(uint32_t*)&h1;
            }
        }
        return;
    }

    // Q/K: RoPE on accumulator pairs (nt, nt+2) = cols (c, c+64)
    const int posv = posp[0];
    const float LN1E4_128 = 9.210340371976184f / 128.0f;
#pragma unroll
    for (int mt = 0; mt < 4; mt++) {
        const int mr = m0 + wm * 64 + mt * 16 + g;
#pragma unroll
        for (int nt = 0; nt < 2; nt++) {
            const int c = wn * 16 + nt * 8 + tg * 2;          // even, < 64
            const float f1 = __expf(-(float)(2 * (c >> 1)) * LN1E4_128);
            const float f2 = f1 * 0.01f;
#pragma unroll
            for (int rj = 0; rj < 2; rj++) {
                const int row = mr + rj * 8;
                const float pos = (float)(posv + (row & (T_ - 1)));
                const float a1 = pos * f1, a2 = pos * f2;
                const float c1 = cosf(a1), s1 = sinf(a1);
                const float c2 = cosf(a2), s2 = sinf(a2);
                float o1[2], o2[2];
#pragma unroll
                for (int jj = 0; jj < 2; jj++) {
                    const float x1 = acc[mt][nt][rj * 2 + jj];
                    const float x2 = acc[mt][nt + 2][rj * 2 + jj];
                    o1[jj] = x1 * c1 - x2 * s1;
                    o2[jj] = x2 * c2 + x1 * s2;
                }
                __half2 hi1 = __floats2half2_rn(o1[0], o1[1]);
                __half2 hi2 = __floats2half2_rn(o2[0], o2[1]);
                if (mode == 0) {
                    float2 hf1 = __half22float2(hi1), hf2 = __half22float2(hi2);
                    __half2 lo1 = __floats2half2_rn(o1[0] - hf1.x, o1[1] - hf1.y);
                    __half2 lo2 = __floats2half2_rn(o2[0] - hf2.x, o2[1] - hf2.y);
                    size_t base = (size_t)row * C_ + nq * 128 + c;
                    *(uint32_t*)(Qh + base)      = *(uint32_t*)&hi1;
                    *(uint32_t*)(Ql + base)      = *(uint32_t*)&lo1;
                    *(uint32_t*)(Qh + base + 64) = *(uint32_t*)&hi2;
                    *(uint32_t*)(Ql + base + 64) = *(uint32_t*)&lo2;
                } else {
                    size_t base = (size_t)row * KVD + (nq - 16) * 128 + c;
                    *(uint32_t*)(Kh + base)      = *(uint32_t*)&hi1;
                    *(uint32_t*)(Kh + base + 64) = *(uint32_t*)&hi2;
                }
            }
        }
    }
}

// ---------------------------------------------------------------------------
// fp16 SINGLE-pass GEMM via mma.sync (Wo projection, fp32 out).
// A = yh fp16 [M,K]; B = Wo^T fp16 [N,K]. Uncorrected A+B rounding ~2^-12 rms.
// ---------------------------------------------------------------------------
__global__ __launch_bounds__(256) void gemm_mma1(
    const __half* __restrict__ Ah, const __half* __restrict__ Bh,
    float* __restrict__ C, int N, int K)
{
    __shared__ __half sAh[128 * SAS], sBh[128 * SAS];

    const int tid = threadIdx.x;
    const int lane = tid & 31, wid = tid >> 5;
    const int wm = wid & 1, wn = wid >> 1;
    const int m0 = blockIdx.y * 128, n0 = blockIdx.x * 128;

    const int ldrow = tid >> 1, ldhalf = tid & 1;
    const __half* gAh = Ah + (size_t)(m0 + ldrow) * K + ldhalf * 16;
    const __half* gBh = Bh + (size_t)(n0 + ldrow) * K + ldhalf * 16;
    char* stAh = (char*)sAh + (ldrow * SAS + ldhalf * 16) * 2;
    char* stBh = (char*)sBh + (ldrow * SAS + ldhalf * 16) * 2;

    const int mid = lane >> 3, rin = lane & 7;
    const uint32_t aoff =
        ((wm * 64 + (mid & 1) * 8 + rin) * SAS + (mid >> 1) * 8) * 2;
    const uint32_t boff =
        ((wn * 32 + (mid >> 1) * 8 + rin) * SAS + (mid & 1) * 8) * 2;
    const uint32_t uAh = smem_u32(sAh) + aoff;
    const uint32_t uBh = smem_u32(sBh) + boff;

    float acc[4][4][4];
#pragma unroll
    for (int mt = 0; mt < 4; mt++)
#pragma unroll
        for (int nt = 0; nt < 4; nt++)
#pragma unroll
            for (int j = 0; j < 4; j++) acc[mt][nt][j] = 0.0f;

    uint4 rah[2], rbh[2];

#define GLOAD(k0)                                            \
    {                                                        \
        rah[0] = *(const uint4*)(gAh + (k0));                \
        rah[1] = *(const uint4*)(gAh + (k0) + 8);            \
        rbh[0] = *(const uint4*)(gBh + (k0));                \
        rbh[1] = *(const uint4*)(gBh + (k0) + 8);            \
    }
#define SSTORE()                                             \
    {                                                        \
        *(uint4*)(stAh) = rah[0]; *(uint4*)(stAh + 16) = rah[1]; \
        *(uint4*)(stBh) = rbh[0]; *(uint4*)(stBh + 16) = rbh[1]; \
    }

    GLOAD(0);
    SSTORE();
    __syncthreads();

    const int nch = K / 32;
    for (int ch = 0; ch < nch; ch++) {
        const bool more = (ch + 1 < nch);
        if (more) GLOAD((ch + 1) * 32);

#pragma unroll
        for (int ks = 0; ks < 2; ks++) {
            uint32_t fah[4][4], fbh[2][4];
#pragma unroll
            for (int mt = 0; mt < 4; mt++)
                ldsm4(fah[mt], uAh + mt * (16 * SAS * 2) + ks * 32);
#pragma unroll
            for (int np = 0; np < 2; np++)
                ldsm4(fbh[np], uBh + np * (16 * SAS * 2) + ks * 32);
#pragma unroll
            for (int mt = 0; mt < 4; mt++)
#pragma unroll
                for (int nt = 0; nt < 4; nt++)
                    mma16816h(acc[mt][nt], fah[mt], &fbh[nt >> 1][(nt & 1) * 2]);
        }
        __syncthreads();
        if (more) SSTORE();
        __syncthreads();
    }
#undef GLOAD
#undef SSTORE

    const int g = lane >> 2, tg = lane & 3;
#pragma unroll
    for (int mt = 0; mt < 4; mt++) {
        const int mrow = m0 + wm * 64 + mt * 16 + g;
#pragma unroll
        for (int nt = 0; nt < 4; nt++) {
            const int ncol = n0 + wn * 32 + nt * 8 + tg * 2;
            float2 v0 = {acc[mt][nt][0], acc[mt][nt][1]};
            float2 v1 = {acc[mt][nt][2], acc[mt][nt][3]};
            *(float2*)(C + (size_t)mrow * N + ncol)       = v0;
            *(float2*)(C + (size_t)(mrow + 8) * N + ncol) = v1;
        }
    }
}

// ---------------------------------------------------------------------------
// Flash attention on mma.sync, fp16 2-pass QK (Qh,Ql vs Kh), fp16 PV.
// Output: fp16 hi only (feeds single-pass Wo GEMM).
// ---------------------------------------------------------------------------
#define SKP 136
#define FL_SMEM (2 * 64 * SKP * 2)

extern __shared__ char dynsm[];

__global__ __launch_bounds__(256) void flash_mma(
    const __half* __restrict__ Qh, const __half* __restrict__ Ql,
    const __half* __restrict__ Khg, const __half* __restrict__ Vhg,
    __half* __restrict__ Yh)
{
    __half* sKh = (__half*)dynsm;
    __half* sVh = sKh + 64 * SKP;

    const int tid = threadIdx.x, lane = tid & 31, w = tid >> 5;
    const int qb = blockIdx.x, h = blockIdx.y, b = blockIdx.z;
    const int kvh = h >> 2;
    const int g = lane >> 2, tg = lane & 3;
    const int mid = lane >> 3, rin = lane & 7;
    const int qrow0 = qb * 128 + w * 16;

    uint32_t qh[8][4], ql[8][4];
    {
        const __half* Qhb = Qh + ((size_t)b * T_ + qrow0) * C_ + h * HD;
        const __half* Qlb = Ql + ((size_t)b * T_ + qrow0) * C_ + h * HD;
#pragma unroll
        for (int kc = 0; kc < 8; kc++) {
#pragma unroll
            for (int fr = 0; fr < 4; fr++) {
                int r = g + (fr & 1) * 8;
                int c = kc * 16 + tg * 2 + (fr >> 1) * 8;
                qh[kc][fr] = *(const uint32_t*)(Qhb + (size_t)r * C_ + c);
                ql[kc][fr] = *(const uint32_t*)(Qlb + (size_t)r * C_ + c);
            }
        }
    }

    float o[16][4];
#pragma unroll
    for (int nt = 0; nt < 16; nt++)
#pragma unroll
        for (int j = 0; j < 4; j++) o[nt][j] = 0.0f;
    float m0 = -INFINITY, m1 = -INFINITY, l0 = 0.0f, l1 = 0.0f;

    const float cscale = 0.08838834764831845f;
    const int rg0 = qrow0 + g, rg1 = rg0 + 8;
    const int ktmax = 2 * qb + 2;

    const __half* Kh0 = Khg + (size_t)b * T_ * KVD + kvh * HD;
    const __half* Vh0 = Vhg + (size_t)b * T_ * KVD + kvh * HD;

    const uint32_t uKh = smem_u32(sKh), uVh = smem_u32(sVh);
    const uint32_t kfrag = (((mid >> 1) * 8 + rin) * SKP + (mid & 1) * 8) * 2;
    const uint32_t vfrag = (((mid & 1) * 8 + rin) * SKP + (mid >> 1) * 8) * 2;

    for (int kt = 0; kt < ktmax; kt++) {
        __syncthreads();
        {
            const __half* Kht = Kh0 + (size_t)kt * 64 * KVD;
            const __half* Vht = Vh0 + (size_t)kt * 64 * KVD;
#pragma unroll
            for (int it = 0; it < 4; it++) {
                int i = tid + it * 256;
                int r = i >> 4, c8 = (i & 15) << 3;
                *(uint4*)(sKh + r * SKP + c8) = *(const uint4*)(Kht + (size_t)r * KVD + c8);
                *(uint4*)(sVh + r * SKP + c8) = *(const uint4*)(Vht + (size_t)r * KVD + c8);
            }
        }
        __syncthreads();

        if (kt * 64 > qrow0 + 15) continue;
        const bool needmask = (kt * 64 + 63 > qrow0);

        float s[8][4];
#pragma unroll
        for (int nt = 0; nt < 8; nt++)
#pragma unroll
            for (int j = 0; j < 4; j++) s[nt][j] = 0.0f;

#pragma unroll
        for (int kc = 0; kc < 8; kc++) {
            uint32_t bt[4][4];
#pragma unroll
            for (int nt2 = 0; nt2 < 4; nt2++)
                ldsm4(bt[nt2], uKh + kfrag + (nt2 * 16 * SKP + kc * 16) * 2);
#pragma unroll
            for (int nt = 0; nt < 8; nt++) {
                const uint32_t* bb = &bt[nt >> 1][(nt & 1) * 2];
                mma16816h(s[nt], qh[kc], bb);
                mma16816h(s[nt], ql[kc], bb);
            }
        }

#pragma unroll
        for (int nt = 0; nt < 8; nt++) {
#pragma unroll
            for (int j = 0; j < 4; j++) s[nt][j] *= cscale;
            if (needmask) {
                int c0 = kt * 64 + nt * 8 + tg * 2;
                if (c0 > rg0)     s[nt][0] = -1e30f;
                if (c0 + 1 > rg0) s[nt][1] = -1e30f;
                if (c0 > rg1)     s[nt][2] = -1e30f;
                if (c0 + 1 > rg1) s[nt][3] = -1e30f;
            }
        }

        float mn0 = m0, mn1 = m1;
#pragma unroll
        for (int nt = 0; nt < 8; nt++) {
            mn0 = fmaxf(mn0, fmaxf(s[nt][0], s[nt][1]));
            mn1 = fmaxf(mn1, fmaxf(s[nt][2], s[nt][3]));
        }
        mn0 = fmaxf(mn0, __shfl_xor_sync(0xffffffffu, mn0, 1));
        mn0 = fmaxf(mn0, __shfl_xor_sync(0xffffffffu, mn0, 2));
        mn1 = fmaxf(mn1, __shfl_xor_sync(0xffffffffu, mn1, 1));
        mn1 = fmaxf(mn1, __shfl_xor_sync(0xffffffffu, mn1, 2));
        float fac0 = __expf(m0 - mn0), fac1 = __expf(m1 - mn1);
        m0 = mn0; m1 = mn1;

        uint32_t pa[4][4];
        float ps0 = 0.0f, ps1 = 0.0f;
#pragma unroll
        for (int kk = 0; kk < 4; kk++) {
            int nt = 2 * kk;
            float p00 = __expf(s[nt][0] - m0),     p01 = __expf(s[nt][1] - m0);
            float p02 = __expf(s[nt][2] - m1),     p03 = __expf(s[nt][3] - m1);
            float p10 = __expf(s[nt + 1][0] - m0), p11 = __expf(s[nt + 1][1] - m0);
            float p12 = __expf(s[nt + 1][2] - m1), p13 = __expf(s[nt + 1][3] - m1);
            ps0 += p00 + p01 + p10 + p11;
            ps1 += p02 + p03 + p12 + p13;
            __half2 a0 = __floats2half2_rn(p00, p01);
            __half2 a1 = __floats2half2_rn(p02, p03);
            __half2 a2 = __floats2half2_rn(p10, p11);
            __half2 a3 = __floats2half2_rn(p12, p13);
            pa[kk][0] = *(uint32_t*)&a0;
            pa[kk][1] = *(uint32_t*)&a1;
            pa[kk][2] = *(uint32_t*)&a2;
            pa[kk][3] = *(uint32_t*)&a3;
        }
        l0 = l0 * fac0 + ps0;
        l1 = l1 * fac1 + ps1;

#pragma unroll
        for (int nt = 0; nt < 16; nt++) {
            o[nt][0] *= fac0; o[nt][1] *= fac0;
            o[nt][2] *= fac1; o[nt][3] *= fac1;
        }

#pragma unroll
        for (int kk = 0; kk < 4; kk++) {
            uint32_t vb[8][4];
#pragma unroll
            for (int np = 0; np < 8; np++)
                ldsm4t(vb[np], uVh + vfrag + (kk * 16 * SKP + np * 16) * 2);
#pragma unroll
            for (int nt = 0; nt < 16; nt++)
                mma16816h(o[nt], pa[kk], &vb[nt >> 1][(nt & 1) * 2]);
        }
    }

    l0 += __shfl_xor_sync(0xffffffffu, l0, 1);
    l0 += __shfl_xor_sync(0xffffffffu, l0, 2);
    l1 += __shfl_xor_sync(0xffffffffu, l1, 1);
    l1 += __shfl_xor_sync(0xffffffffu, l1, 2);
    float inv0 = 1.0f / l0, inv1 = 1.0f / l1;

    size_t row0 = (size_t)b * T_ + rg0;
    size_t row1 = (size_t)b * T_ + rg1;
#pragma unroll
    for (int nt = 0; nt < 16; nt++) {
        int col = h * HD + nt * 8 + tg * 2;
        __half2 h0 = __floats2half2_rn(o[nt][0] * inv0, o[nt][1] * inv0);
        __half2 h1 = __floats2half2_rn(o[nt][2] * inv1, o[nt][3] * inv1);
        *(uint32_t*)(Yh + row0 * C_ + col) = *(uint32_t*)&h0;
        *(uint32_t*)(Yh + row1 * C_ + col) = *(uint32_t*)&h1;
    }
}

// ---------------------------------------------------------------------------
extern "C" void kernel_launch(void* const* d_in, const int* in_sizes, int n_in,
                              void* d_out, int out_size)
{
    const float* x  = (const float*)d_in[0];
    const float* Wq = (const float*)d_in[1];
    const float* Wk = (const float*)d_in[2];
    const float* Wv = (const float*)d_in[3];
    const float* Wo = (const float*)d_in[4];
    const int*  pos = (const int*)d_in[5];
    float* out = (float*)d_out;

    __half *qh, *ql, *kh, *vh;
    cudaGetSymbolAddress((void**)&qh, s_qh); cudaGetSymbolAddress((void**)&ql, s_ql);
    cudaGetSymbolAddress((void**)&kh, s_kh); cudaGetSymbolAddress((void**)&vh, s_vh);
    __half *xh, *xl, *yh, *wqh, *wkh, *wvh, *woh;
    cudaGetSymbolAddress((void**)&xh, s_xh);   cudaGetSymbolAddress((void**)&xl, s_xl);
    cudaGetSymbolAddress((void**)&yh, s_yh);
    cudaGetSymbolAddress((void**)&wqh, s_wqh);
    cudaGetSymbolAddress((void**)&wkh, s_wkh);
    cudaGetSymbolAddress((void**)&wvh, s_wvh);
    cudaGetSymbolAddress((void**)&woh, s_woh);

    cudaFuncSetAttribute(flash_mma, cudaFuncAttributeMaxDynamicSharedMemorySize,
                         FL_SMEM);

    // split x (fp16 hi/lo)
    {
        int n4 = M_ * C_ / 4;
        split_kernel<<<(n4 + 255) / 256, 256>>>(x, xh, xl, n4);
    }
    // transpose weights (fp16 hi only)
    transpose_half_kernel<<<dim3(C_ / 32,  C_ / 32), dim3(32, 8)>>>(Wq, wqh, C_, C_);
    transpose_half_kernel<<<dim3(KVD / 32, C_ / 32), dim3(32, 8)>>>(Wk, wkh, C_, KVD);
    transpose_half_kernel<<<dim3(KVD / 32, C_ / 32), dim3(32, 8)>>>(Wv, wvh, C_, KVD);
    transpose_half_kernel<<<dim3(C_ / 32,  C_ / 32), dim3(32, 8)>>>(Wo, woh, C_, C_);

    // fused QKV projection + RoPE + split (one launch, 24x64 grid)
    qkv_gemm<<<dim3(24, M_ / 128), 256>>>(xh, xl, wqh, wkh, wvh,
                                          qh, ql, kh, vh, pos);

    // attention (fp16 2-pass QK, fp16 PV), writes fp16 y (hi only)
    flash_mma<<<dim3(T_ / 128, NH, B_), 256, FL_SMEM>>>(qh, ql, kh, vh, yh);

    // output projection (single-pass fp16)
    gemm_mma1<<<dim3(C_ / 128, M_ / 128), 256>>>(yh, woh, out, C_, C_);
}

// round 11
// speedup vs baseline: 1.6677x; 1.0108x over previous
#include <cuda_runtime.h>
#include <cuda_fp16.h>
#include <math.h>
#include <stdint.h>

#define B_   4
#define T_   2048
#define C_   2048
#define NH   16
#define NKV  4
#define HD   128
#define KVD  (NKV*HD)   // 512
#define M_   (B_*T_)    // 8192

// ---------------- scratch (__device__ globals; no allocs allowed) ----------
__device__ __half s_qh[(size_t)M_ * C_],  s_ql[(size_t)M_ * C_];
__device__ __half s_kh[(size_t)M_ * KVD];
__device__ __half s_vh[(size_t)M_ * KVD];

__device__ __half s_xh[(size_t)M_ * C_],  s_xl[(size_t)M_ * C_];
__device__ __half s_yh[(size_t)M_ * C_];
__device__ __half s_wqh[(size_t)C_ * C_];
__device__ __half s_wkh[(size_t)KVD * C_];
__device__ __half s_wvh[(size_t)KVD * C_];
__device__ __half s_woh[(size_t)C_ * C_];

// ---------------- helpers ---------------------------------------------------
__device__ __forceinline__ uint32_t smem_u32(const void* p) {
    uint32_t a;
    asm("{ .reg .u64 t; cvta.to.shared.u64 t, %1; cvt.u32.u64 %0, t; }"
        : "=r"(a) : "l"(p));
    return a;
}
__device__ __forceinline__ void ldsm4(uint32_t* r, uint32_t addr) {
    asm volatile("ldmatrix.sync.aligned.m8n8.x4.shared.b16 {%0,%1,%2,%3}, [%4];"
                 : "=r"(r[0]), "=r"(r[1]), "=r"(r[2]), "=r"(r[3]) : "r"(addr));
}
__device__ __forceinline__ void ldsm4t(uint32_t* r, uint32_t addr) {
    asm volatile("ldmatrix.sync.aligned.m8n8.x4.trans.shared.b16 {%0,%1,%2,%3}, [%4];"
                 : "=r"(r[0]), "=r"(r[1]), "=r"(r[2]), "=r"(r[3]) : "r"(addr));
}
__device__ __forceinline__ void mma16816h(float* c, const uint32_t* a,
                                          const uint32_t* b) {
    asm volatile(
        "mma.sync.aligned.m16n8k16.row.col.f32.f16.f16.f32 "
        "{%0,%1,%2,%3}, {%4,%5,%6,%7}, {%8,%9}, {%0,%1,%2,%3};"
        : "+f"(c[0]), "+f"(c[1]), "+f"(c[2]), "+f"(c[3])
        : "r"(a[0]), "r"(a[1]), "r"(a[2]), "r"(a[3]), "r"(b[0]), "r"(b[1]));
}

// ---------------------------------------------------------------------------
// split: fp32 -> (fp16 hi, fp16 lo), vectorized x4
// ---------------------------------------------------------------------------
__global__ void split_kernel(const float* __restrict__ X,
                             __half* __restrict__ H,
                             __half* __restrict__ L, int n4)
{
    int i = blockIdx.x * blockDim.x + threadIdx.x;
    if (i >= n4) return;
    float4 v = ((const float4*)X)[i];
    float vv[4] = {v.x, v.y, v.z, v.w};
    __half h[4], l[4];
#pragma unroll
    for (int j = 0; j < 4; j++) {
        h[j] = __float2half(vv[j]);
        l[j] = __float2half(vv[j] - __half2float(h[j]));
    }
    __half2 h0 = {h[0], h[1]}, h1 = {h[2], h[3]};
    __half2 l0 = {l[0], l[1]}, l1 = {l[2], l[3]};
    ((__half2*)H)[2 * i]     = h0;
    ((__half2*)H)[2 * i + 1] = h1;
    ((__half2*)L)[2 * i]     = l0;
    ((__half2*)L)[2 * i + 1] = l1;
}

// ---------------------------------------------------------------------------
// merged transpose: all four weights in one launch (grid.z selects tensor)
// W[K,N] fp32 -> Th [N,K] fp16 hi
// ---------------------------------------------------------------------------
__global__ void transpose_all_kernel(
    const float* __restrict__ Wq, const float* __restrict__ Wk,
    const float* __restrict__ Wv, const float* __restrict__ Wo,
    __half* __restrict__ Tq, __half* __restrict__ Tk,
    __half* __restrict__ Tv, __half* __restrict__ To)
{
    const int z = blockIdx.z;
    const float* W;
    __half* Th;
    int N;
    if (z == 0)      { W = Wq; Th = Tq; N = C_; }
    else if (z == 1) { W = Wk; Th = Tk; N = KVD; }
    else if (z == 2) { W = Wv; Th = Tv; N = KVD; }
    else             { W = Wo; Th = To; N = C_; }
    const int K = C_;
    const int n0 = blockIdx.x * 32, k0 = blockIdx.y * 32;
    if (n0 >= N) return;

    __shared__ float t[32][33];
    int tx = threadIdx.x, ty = threadIdx.y;  // 32 x 8
#pragma unroll
    for (int j = 0; j < 4; j++)
        t[ty + 8 * j][tx] = W[(size_t)(k0 + ty + 8 * j) * N + n0 + tx];
    __syncthreads();
#pragma unroll
    for (int j = 0; j < 4; j++)
        Th[(size_t)(n0 + ty + 8 * j) * K + k0 + tx] =
            __float2half(t[tx][ty + 8 * j]);
}

// ---------------------------------------------------------------------------
// Fused QKV projection + RoPE + fp16 split; double-buffered smem, ONE barrier
// per K-chunk. Grid x: 0-15 Q, 16-19 K, 20-23 V. CTA 128x128, BK=32.
// ---------------------------------------------------------------------------
#define SAS   40
#define GBUF  (128 * SAS * 2)       // 10240 B per tile buffer
#define GSTG3 (3 * GBUF)            // stage for qkv (Ah,Al,Bh)
#define QKV_SMEM (2 * GSTG3)        // 61440
#define GSTG2 (2 * GBUF)            // stage for Wo gemm (Ah,Bh)
#define G1_SMEM (2 * GSTG2)         // 40960

extern __shared__ char dynsm[];

__global__ __launch_bounds__(256) void qkv_gemm(
    const __half* __restrict__ Ah, const __half* __restrict__ Al,
    const __half* __restrict__ Wqh, const __half* __restrict__ Wkh,
    const __half* __restrict__ Wvh,
    __half* __restrict__ Qh, __half* __restrict__ Ql,
    __half* __restrict__ Kh, __half* __restrict__ Vh,
    const int* __restrict__ posp)
{
    const int K = C_;
    const int tid = threadIdx.x;
    const int lane = tid & 31, wid = tid >> 5;
    const int wm = wid & 1, wn = wid >> 1;
    const int m0 = blockIdx.y * 128;
    const int nq = blockIdx.x;

    const __half* Bp;
    int mode;                      // 0=Q(rope,hi/lo) 1=K(rope,hi) 2=V(convert)
    if (nq < 16)      { Bp = Wqh + (size_t)nq * 128 * K;        mode = 0; }
    else if (nq < 20) { Bp = Wkh + (size_t)(nq - 16) * 128 * K; mode = 1; }
    else              { Bp = Wvh + (size_t)(nq - 20) * 128 * K; mode = 2; }

    const int ldrow = tid >> 1, ldhalf = tid & 1;
    const __half* gAh = Ah + (size_t)(m0 + ldrow) * K + ldhalf * 16;
    const __half* gAl = Al + (size_t)(m0 + ldrow) * K + ldhalf * 16;
    const __half* gBh = Bp + (size_t)ldrow * K + ldhalf * 16;
    char* dsm = dynsm + (ldrow * SAS + ldhalf * 16) * 2;

    const int mid = lane >> 3, rin = lane & 7;
    const uint32_t usm = smem_u32(dynsm);
    const uint32_t aoff =
        ((wm * 64 + (mid & 1) * 8 + rin) * SAS + (mid >> 1) * 8) * 2;
    const uint32_t boff =
        ((wn * 16 + (mid >> 1) * 8 + rin) * SAS + (mid & 1) * 8) * 2;
    const uint32_t uAh = usm + aoff, uAl = usm + GBUF + aoff;
    const uint32_t uBh = usm + 2 * GBUF + boff;

    float acc[4][4][4];
#pragma unroll
    for (int mt = 0; mt < 4; mt++)
#pragma unroll
        for (int nt = 0; nt < 4; nt++)
#pragma unroll
            for (int j = 0; j < 4; j++) acc[mt][nt][j] = 0.0f;

    uint4 rah[2], ral[2], rbh[2];

#define GLOAD(k0)                                            \
    {                                                        \
        rah[0] = *(const uint4*)(gAh + (k0));                \
        rah[1] = *(const uint4*)(gAh + (k0) + 8);            \
        ral[0] = *(const uint4*)(gAl + (k0));                \
        ral[1] = *(const uint4*)(gAl + (k0) + 8);            \
        rbh[0] = *(const uint4*)(gBh + (k0));                \
        rbh[1] = *(const uint4*)(gBh + (k0) + 8);            \
    }
#define SSTORE(stg)                                               \
    {                                                             \
        char* d = dsm + (stg) * GSTG3;                            \
        *(uint4*)(d)                 = rah[0];                    \
        *(uint4*)(d + 16)            = rah[1];                    \
        *(uint4*)(d + GBUF)          = ral[0];                    \
        *(uint4*)(d + GBUF + 16)     = ral[1];                    \
        *(uint4*)(d + 2 * GBUF)      = rbh[0];                    \
        *(uint4*)(d + 2 * GBUF + 16) = rbh[1];                    \
    }

    GLOAD(0);
    SSTORE(0);
    __syncthreads();

    const int nch = K / 32;
    for (int ch = 0; ch < nch; ch++) {
        const bool more = (ch + 1 < nch);
        if (more) GLOAD((ch + 1) * 32);
        const uint32_t so = (ch & 1) * GSTG3;

#pragma unroll
        for (int ks = 0; ks < 2; ks++) {
            uint32_t fah[4][4], fal[4][4], fbh[2][4];
#pragma unroll
            for (int mt = 0; mt < 4; mt++) {
                ldsm4(fah[mt], uAh + so + mt * (16 * SAS * 2) + ks * 32);
                ldsm4(fal[mt], uAl + so + mt * (16 * SAS * 2) + ks * 32);
            }
            ldsm4(fbh[0], uBh + so + ks * 32);
            ldsm4(fbh[1], uBh + so + 64 * (SAS * 2) + ks * 32);
#pragma unroll
            for (int mt = 0; mt < 4; mt++)
#pragma unroll
                for (int nt = 0; nt < 4; nt++) {
                    const uint32_t* b_h = &fbh[nt >> 1][(nt & 1) * 2];
                    mma16816h(acc[mt][nt], fah[mt], b_h);
                    mma16816h(acc[mt][nt], fal[mt], b_h);
                }
        }
        if (more) {
            SSTORE((ch + 1) & 1);
            __syncthreads();
        }
    }
#undef GLOAD
#undef SSTORE

    const int g = lane >> 2, tg = lane & 3;

    if (mode == 2) {
        const int coff = (nq - 20) * 128;
#pragma unroll
        for (int mt = 0; mt < 4; mt++) {
            const int r0 = m0 + wm * 64 + mt * 16 + g;
#pragma unroll
            for (int nt = 0; nt < 4; nt++) {
                const int c = wn * 16 + (nt & 1) * 8 + ((nt & 2) ? 64 : 0) + tg * 2;
                __half2 h0 = __floats2half2_rn(acc[mt][nt][0], acc[mt][nt][1]);
                __half2 h1 = __floats2half2_rn(acc[mt][nt][2], acc[mt][nt][3]);
                *(uint32_t*)(Vh + (size_t)r0 * KVD + coff + c)       = *(uint32_t*)&h0;
                *(uint32_t*)(Vh + (size_t)(r0 + 8) * KVD + coff + c) = *(uint32_t*)&h1;
            }
        }
        return;
    }

    // Q/K: RoPE on accumulator pairs (nt, nt+2) = cols (c, c+64)
    const int posv = posp[0];
    const float LN1E4_128 = 9.210340371976184f / 128.0f;
#pragma unroll
    for (int mt = 0; mt < 4; mt++) {
        const int mr = m0 + wm * 64 + mt * 16 + g;
#pragma unroll
        for (int nt = 0; nt < 2; nt++) {
            const int c = wn * 16 + nt * 8 + tg * 2;          // even, < 64
            const float f1 = __expf(-(float)(2 * (c >> 1)) * LN1E4_128);
            const float f2 = f1 * 0.01f;
#pragma unroll
            for (int rj = 0; rj < 2; rj++) {
                const int row = mr + rj * 8;
                const float pos = (float)(posv + (row & (T_ - 1)));
                const float a1 = pos * f1, a2 = pos * f2;
                const float c1 = cosf(a1), s1 = sinf(a1);
                const float c2 = cosf(a2), s2 = sinf(a2);
                float o1[2], o2[2];
#pragma unroll
                for (int jj = 0; jj < 2; jj++) {
                    const float x1 = acc[mt][nt][rj * 2 + jj];
                    const float x2 = acc[mt][nt + 2][rj * 2 + jj];
                    o1[jj] = x1 * c1 - x2 * s1;
                    o2[jj] = x2 * c2 + x1 * s2;
                }
                __half2 hi1 = __floats2half2_rn(o1[0], o1[1]);
                __half2 hi2 = __floats2half2_rn(o2[0], o2[1]);
                if (mode == 0) {
                    float2 hf1 = __half22float2(hi1), hf2 = __half22float2(hi2);
                    __half2 lo1 = __floats2half2_rn(o1[0] - hf1.x, o1[1] - hf1.y);
                    __half2 lo2 = __floats2half2_rn(o2[0] - hf2.x, o2[1] - hf2.y);
                    size_t base = (size_t)row * C_ + nq * 128 + c;
                    *(uint32_t*)(Qh + base)      = *(uint32_t*)&hi1;
                    *(uint32_t*)(Ql + base)      = *(uint32_t*)&lo1;
                    *(uint32_t*)(Qh + base + 64) = *(uint32_t*)&hi2;
                    *(uint32_t*)(Ql + base + 64) = *(uint32_t*)&lo2;
                } else {
                    size_t base = (size_t)row * KVD + (nq - 16) * 128 + c;
                    *(uint32_t*)(Kh + base)      = *(uint32_t*)&hi1;
                    *(uint32_t*)(Kh + base + 64) = *(uint32_t*)&hi2;
                }
            }
        }
    }
}

// ---------------------------------------------------------------------------
// fp16 single-pass Wo GEMM; double-buffered smem, ONE barrier per chunk.
// ---------------------------------------------------------------------------
__global__ __launch_bounds__(256) void gemm_mma1(
    const __half* __restrict__ Ah, const __half* __restrict__ Bh,
    float* __restrict__ C, int N, int K)
{
    const int tid = threadIdx.x;
    const int lane = tid & 31, wid = tid >> 5;
    const int wm = wid & 1, wn = wid >> 1;
    const int m0 = blockIdx.y * 128, n0 = blockIdx.x * 128;

    const int ldrow = tid >> 1, ldhalf = tid & 1;
    const __half* gAh = Ah + (size_t)(m0 + ldrow) * K + ldhalf * 16;
    const __half* gBh = Bh + (size_t)(n0 + ldrow) * K + ldhalf * 16;
    char* dsm = dynsm + (ldrow * SAS + ldhalf * 16) * 2;

    const int mid = lane >> 3, rin = lane & 7;
    const uint32_t usm = smem_u32(dynsm);
    const uint32_t aoff =
        ((wm * 64 + (mid & 1) * 8 + rin) * SAS + (mid >> 1) * 8) * 2;
    const uint32_t boff =
        ((wn * 32 + (mid >> 1) * 8 + rin) * SAS + (mid & 1) * 8) * 2;
    const uint32_t uAh = usm + aoff;
    const uint32_t uBh = usm + GBUF + boff;

    float acc[4][4][4];
#pragma unroll
    for (int mt = 0; mt < 4; mt++)
#pragma unroll
        for (int nt = 0; nt < 4; nt++)
#pragma unroll
            for (int j = 0; j < 4; j++) acc[mt][nt][j] = 0.0f;

    uint4 rah[2], rbh[2];

#define GLOAD(k0)                                            \
    {                                                        \
        rah[0] = *(const uint4*)(gAh + (k0));                \
        rah[1] = *(const uint4*)(gAh + (k0) + 8);            \
        rbh[0] = *(const uint4*)(gBh + (k0));                \
        rbh[1] = *(const uint4*)(gBh + (k0) + 8);            \
    }
#define SSTORE(stg)                                          \
    {                                                        \
        char* d = dsm + (stg) * GSTG2;                       \
        *(uint4*)(d)             = rah[0];                   \
        *(uint4*)(d + 16)        = rah[1];                   \
        *(uint4*)(d + GBUF)      = rbh[0];                   \
        *(uint4*)(d + GBUF + 16) = rbh[1];                   \
    }

    GLOAD(0);
    SSTORE(0);
    __syncthreads();

    const int nch = K / 32;
    for (int ch = 0; ch < nch; ch++) {
        const bool more = (ch + 1 < nch);
        if (more) GLOAD((ch + 1) * 32);
        const uint32_t so = (ch & 1) * GSTG2;

#pragma unroll
        for (int ks = 0; ks < 2; ks++) {
            uint32_t fah[4][4], fbh[2][4];
#pragma unroll
            for (int mt = 0; mt < 4; mt++)
                ldsm4(fah[mt], uAh + so + mt * (16 * SAS * 2) + ks * 32);
#pragma unroll
            for (int np = 0; np < 2; np++)
                ldsm4(fbh[np], uBh + so + np * (16 * SAS * 2) + ks * 32);
#pragma unroll
            for (int mt = 0; mt < 4; mt++)
#pragma unroll
                for (int nt = 0; nt < 4; nt++)
                    mma16816h(acc[mt][nt], fah[mt], &fbh[nt >> 1][(nt & 1) * 2]);
        }
        if (more) {
            SSTORE((ch + 1) & 1);
            __syncthreads();
        }
    }
#undef GLOAD
#undef SSTORE

    const int g = lane >> 2, tg = lane & 3;
#pragma unroll
    for (int mt = 0; mt < 4; mt++) {
        const int mrow = m0 + wm * 64 + mt * 16 + g;
#pragma unroll
        for (int nt = 0; nt < 4; nt++) {
            const int ncol = n0 + wn * 32 + nt * 8 + tg * 2;
            float2 v0 = {acc[mt][nt][0], acc[mt][nt][1]};
            float2 v1 = {acc[mt][nt][2], acc[mt][nt][3]};
            *(float2*)(C + (size_t)mrow * N + ncol)       = v0;
            *(float2*)(C + (size_t)(mrow + 8) * N + ncol) = v1;
        }
    }
}

// ---------------------------------------------------------------------------
// Flash attention on mma.sync (unchanged from R10 — proven)
// ---------------------------------------------------------------------------
#define SKP 136
#define FL_SMEM (2 * 64 * SKP * 2)

__global__ __launch_bounds__(256) void flash_mma(
    const __half* __restrict__ Qh, const __half* __restrict__ Ql,
    const __half* __restrict__ Khg, const __half* __restrict__ Vhg,
    __half* __restrict__ Yh)
{
    __half* sKh = (__half*)dynsm;
    __half* sVh = sKh + 64 * SKP;

    const int tid = threadIdx.x, lane = tid & 31, w = tid >> 5;
    const int qb = blockIdx.x, h = blockIdx.y, b = blockIdx.z;
    const int kvh = h >> 2;
    const int g = lane >> 2, tg = lane & 3;
    const int mid = lane >> 3, rin = lane & 7;
    const int qrow0 = qb * 128 + w * 16;

    uint32_t qh[8][4], ql[8][4];
    {
        const __half* Qhb = Qh + ((size_t)b * T_ + qrow0) * C_ + h * HD;
        const __half* Qlb = Ql + ((size_t)b * T_ + qrow0) * C_ + h * HD;
#pragma unroll
        for (int kc = 0; kc < 8; kc++) {
#pragma unroll
            for (int fr = 0; fr < 4; fr++) {
                int r = g + (fr & 1) * 8;
                int c = kc * 16 + tg * 2 + (fr >> 1) * 8;
                qh[kc][fr] = *(const uint32_t*)(Qhb + (size_t)r * C_ + c);
                ql[kc][fr] = *(const uint32_t*)(Qlb + (size_t)r * C_ + c);
            }
        }
    }

    float o[16][4];
#pragma unroll
    for (int nt = 0; nt < 16; nt++)
#pragma unroll
        for (int j = 0; j < 4; j++) o[nt][j] = 0.0f;
    float m0 = -INFINITY, m1 = -INFINITY, l0 = 0.0f, l1 = 0.0f;

    const float cscale = 0.08838834764831845f;
    const int rg0 = qrow0 + g, rg1 = rg0 + 8;
    const int ktmax = 2 * qb + 2;

    const __half* Kh0 = Khg + (size_t)b * T_ * KVD + kvh * HD;
    const __half* Vh0 = Vhg + (size_t)b * T_ * KVD + kvh * HD;

    const uint32_t uKh = smem_u32(sKh), uVh = smem_u32(sVh);
    const uint32_t kfrag = (((mid >> 1) * 8 + rin) * SKP + (mid & 1) * 8) * 2;
    const uint32_t vfrag = (((mid & 1) * 8 + rin) * SKP + (mid >> 1) * 8) * 2;

    for (int kt = 0; kt < ktmax; kt++) {
        __syncthreads();
        {
            const __half* Kht = Kh0 + (size_t)kt * 64 * KVD;
            const __half* Vht = Vh0 + (size_t)kt * 64 * KVD;
#pragma unroll
            for (int it = 0; it < 4; it++) {
                int i = tid + it * 256;
                int r = i >> 4, c8 = (i & 15) << 3;
                *(uint4*)(sKh + r * SKP + c8) = *(const uint4*)(Kht + (size_t)r * KVD + c8);
                *(uint4*)(sVh + r * SKP + c8) = *(const uint4*)(Vht + (size_t)r * KVD + c8);
            }
        }
        __syncthreads();

        if (kt * 64 > qrow0 + 15) continue;
        const bool needmask = (kt * 64 + 63 > qrow0);

        float s[8][4];
#pragma unroll
        for (int nt = 0; nt < 8; nt++)
#pragma unroll
            for (int j = 0; j < 4; j++) s[nt][j] = 0.0f;

#pragma unroll
        for (int kc = 0; kc < 8; kc++) {
            uint32_t bt[4][4];
#pragma unroll
            for (int nt2 = 0; nt2 < 4; nt2++)
                ldsm4(bt[nt2], uKh + kfrag + (nt2 * 16 * SKP + kc * 16) * 2);
#pragma unroll
            for (int nt = 0; nt < 8; nt++) {
                const uint32_t* bb = &bt[nt >> 1][(nt & 1) * 2];
                mma16816h(s[nt], qh[kc], bb);
                mma16816h(s[nt], ql[kc], bb);
            }
        }

#pragma unroll
        for (int nt = 0; nt < 8; nt++) {
#pragma unroll
            for (int j = 0; j < 4; j++) s[nt][j] *= cscale;
            if (needmask) {
                int c0 = kt * 64 + nt * 8 + tg * 2;
                if (c0 > rg0)     s[nt][0] = -1e30f;
                if (c0 + 1 > rg0) s[nt][1] = -1e30f;
                if (c0 > rg1)     s[nt][2] = -1e30f;
                if (c0 + 1 > rg1) s[nt][3] = -1e30f;
            }
        }

        float mn0 = m0, mn1 = m1;
#pragma unroll
        for (int nt = 0; nt < 8; nt++) {
            mn0 = fmaxf(mn0, fmaxf(s[nt][0], s[nt][1]));
            mn1 = fmaxf(mn1, fmaxf(s[nt][2], s[nt][3]));
        }
        mn0 = fmaxf(mn0, __shfl_xor_sync(0xffffffffu, mn0, 1));
        mn0 = fmaxf(mn0, __shfl_xor_sync(0xffffffffu, mn0, 2));
        mn1 = fmaxf(mn1, __shfl_xor_sync(0xffffffffu, mn1, 1));
        mn1 = fmaxf(mn1, __shfl_xor_sync(0xffffffffu, mn1, 2));
        float fac0 = __expf(m0 - mn0), fac1 = __expf(m1 - mn1);
        m0 = mn0; m1 = mn1;

        uint32_t pa[4][4];
        float ps0 = 0.0f, ps1 = 0.0f;
#pragma unroll
        for (int kk = 0; kk < 4; kk++) {
            int nt = 2 * kk;
            float p00 = __expf(s[nt][0] - m0),     p01 = __expf(s[nt][1] - m0);
            float p02 = __expf(s[nt][2] - m1),     p03 = __expf(s[nt][3] - m1);
            float p10 = __expf(s[nt + 1][0] - m0), p11 = __expf(s[nt + 1][1] - m0);
            float p12 = __expf(s[nt + 1][2] - m1), p13 = __expf(s[nt + 1][3] - m1);
            ps0 += p00 + p01 + p10 + p11;
            ps1 += p02 + p03 + p12 + p13;
            __half2 a0 = __floats2half2_rn(p00, p01);
            __half2 a1 = __floats2half2_rn(p02, p03);
            __half2 a2 = __floats2half2_rn(p10, p11);
            __half2 a3 = __floats2half2_rn(p12, p13);
            pa[kk][0] = *(uint32_t*)&a0;
            pa[kk][1] = *(uint32_t*)&a1;
            pa[kk][2] = *(uint32_t*)&a2;
            pa[kk][3] = *(uint32_t*)&a3;
        }
        l0 = l0 * fac0 + ps0;
        l1 = l1 * fac1 + ps1;

#pragma unroll
        for (int nt = 0; nt < 16; nt++) {
            o[nt][0] *= fac0; o[nt][1] *= fac0;
            o[nt][2] *= fac1; o[nt][3] *= fac1;
        }

#pragma unroll
        for (int kk = 0; kk < 4; kk++) {
            uint32_t vb[8][4];
#pragma unroll
            for (int np = 0; np < 8; np++)
                ldsm4t(vb[np], uVh + vfrag + (kk * 16 * SKP + np * 16) * 2);
#pragma unroll
            for (int nt = 0; nt < 16; nt++)
                mma16816h(o[nt], pa[kk], &vb[nt >> 1][(nt & 1) * 2]);
        }
    }

    l0 += __shfl_xor_sync(0xffffffffu, l0, 1);
    l0 += __shfl_xor_sync(0xffffffffu, l0, 2);
    l1 += __shfl_xor_sync(0xffffffffu, l1, 1);
    l1 += __shfl_xor_sync(0xffffffffu, l1, 2);
    float inv0 = 1.0f / l0, inv1 = 1.0f / l1;

    size_t row0 = (size_t)b * T_ + rg0;
    size_t row1 = (size_t)b * T_ + rg1;
#pragma unroll
    for (int nt = 0; nt < 16; nt++) {
        int col = h * HD + nt * 8 + tg * 2;
        __half2 h0 = __floats2half2_rn(o[nt][0] * inv0, o[nt][1] * inv0);
        __half2 h1 = __floats2half2_rn(o[nt][2] * inv1, o[nt][3] * inv1);
        *(uint32_t*)(Yh + row0 * C_ + col) = *(uint32_t*)&h0;
        *(uint32_t*)(Yh + row1 * C_ + col) = *(uint32_t*)&h1;
    }
}

// ---------------------------------------------------------------------------
extern "C" void kernel_launch(void* const* d_in, const int* in_sizes, int n_in,
                              void* d_out, int out_size)
{
    const float* x  = (const float*)d_in[0];
    const float* Wq = (const float*)d_in[1];
    const float* Wk = (const float*)d_in[2];
    const float* Wv = (const float*)d_in[3];
    const float* Wo = (const float*)d_in[4];
    const int*  pos = (const int*)d_in[5];
    float* out = (float*)d_out;

    __half *qh, *ql, *kh, *vh;
    cudaGetSymbolAddress((void**)&qh, s_qh); cudaGetSymbolAddress((void**)&ql, s_ql);
    cudaGetSymbolAddress((void**)&kh, s_kh); cudaGetSymbolAddress((void**)&vh, s_vh);
    __half *xh, *xl, *yh, *wqh, *wkh, *wvh, *woh;
    cudaGetSymbolAddress((void**)&xh, s_xh);   cudaGetSymbolAddress((void**)&xl, s_xl);
    cudaGetSymbolAddress((void**)&yh, s_yh);
    cudaGetSymbolAddress((void**)&wqh, s_wqh);
    cudaGetSymbolAddress((void**)&wkh, s_wkh);
    cudaGetSymbolAddress((void**)&wvh, s_wvh);
    cudaGetSymbolAddress((void**)&woh, s_woh);

    cudaFuncSetAttribute(qkv_gemm, cudaFuncAttributeMaxDynamicSharedMemorySize,
                         QKV_SMEM);
    cudaFuncSetAttribute(gemm_mma1, cudaFuncAttributeMaxDynamicSharedMemorySize,
                         G1_SMEM);
    cudaFuncSetAttribute(flash_mma, cudaFuncAttributeMaxDynamicSharedMemorySize,
                         FL_SMEM);

    // split x (fp16 hi/lo)
    {
        int n4 = M_ * C_ / 4;
        split_kernel<<<(n4 + 255) / 256, 256>>>(x, xh, xl, n4);
    }
    // all four weight transposes in one launch
    transpose_all_kernel<<<dim3(C_ / 32, C_ / 32, 4), dim3(32, 8)>>>(
        Wq, Wk, Wv, Wo, wqh, wkh, wvh, woh);

    // fused QKV projection + RoPE + split (double-buffered)
    qkv_gemm<<<dim3(24, M_ / 128), 256, QKV_SMEM>>>(xh, xl, wqh, wkh, wvh,
                                                    qh, ql, kh, vh, pos);

    // attention (fp16 2-pass QK, fp16 PV)
    flash_mma<<<dim3(T_ / 128, NH, B_), 256, FL_SMEM>>>(qh, ql, kh, vh, yh);

    // output projection (single-pass fp16, double-buffered)
    gemm_mma1<<<dim3(C_ / 128, M_ / 128), 256, G1_SMEM>>>(yh, woh, out, C_, C_);
}

// round 12
// speedup vs baseline: 1.6974x; 1.0178x over previous
#include <cuda_runtime.h>
#include <cuda_fp16.h>
#include <math.h>
#include <stdint.h>

#define B_   4
#define T_   2048
#define C_   2048
#define NH   16
#define NKV  4
#define HD   128
#define KVD  (NKV*HD)   // 512
#define M_   (B_*T_)    // 8192

// ---------------- scratch (__device__ globals; no allocs allowed) ----------
__device__ __half s_qh[(size_t)M_ * C_],  s_ql[(size_t)M_ * C_];
__device__ __half s_kh[(size_t)M_ * KVD];
__device__ __half s_vh[(size_t)M_ * KVD];

__device__ __half s_xh[(size_t)M_ * C_],  s_xl[(size_t)M_ * C_];
__device__ __half s_yh[(size_t)M_ * C_];
__device__ __half s_wqh[(size_t)C_ * C_];
__device__ __half s_wkh[(size_t)KVD * C_];
__device__ __half s_wvh[(size_t)KVD * C_];
__device__ __half s_woh[(size_t)C_ * C_];

// ---------------- helpers ---------------------------------------------------
__device__ __forceinline__ uint32_t smem_u32(const void* p) {
    uint32_t a;
    asm("{ .reg .u64 t; cvta.to.shared.u64 t, %1; cvt.u32.u64 %0, t; }"
        : "=r"(a) : "l"(p));
    return a;
}
__device__ __forceinline__ void ldsm4(uint32_t* r, uint32_t addr) {
    asm volatile("ldmatrix.sync.aligned.m8n8.x4.shared.b16 {%0,%1,%2,%3}, [%4];"
                 : "=r"(r[0]), "=r"(r[1]), "=r"(r[2]), "=r"(r[3]) : "r"(addr));
}
__device__ __forceinline__ void ldsm4t(uint32_t* r, uint32_t addr) {
    asm volatile("ldmatrix.sync.aligned.m8n8.x4.trans.shared.b16 {%0,%1,%2,%3}, [%4];"
                 : "=r"(r[0]), "=r"(r[1]), "=r"(r[2]), "=r"(r[3]) : "r"(addr));
}
__device__ __forceinline__ void mma16816h(float* c, const uint32_t* a,
                                          const uint32_t* b) {
    asm volatile(
        "mma.sync.aligned.m16n8k16.row.col.f32.f16.f16.f32 "
        "{%0,%1,%2,%3}, {%4,%5,%6,%7}, {%8,%9}, {%0,%1,%2,%3};"
        : "+f"(c[0]), "+f"(c[1]), "+f"(c[2]), "+f"(c[3])
        : "r"(a[0]), "r"(a[1]), "r"(a[2]), "r"(a[3]), "r"(b[0]), "r"(b[1]));
}
__device__ __forceinline__ void cpa16(uint32_t dst, const void* src) {
    asm volatile("cp.async.cg.shared.global [%0], [%1], 16;"
                 :: "r"(dst), "l"(src));
}
__device__ __forceinline__ void cp_commit() {
    asm volatile("cp.async.commit_group;");
}
__device__ __forceinline__ void cp_wait0() {
    asm volatile("cp.async.wait_group 0;" ::: "memory");
}
__device__ __forceinline__ void cp_wait1() {
    asm volatile("cp.async.wait_group 1;" ::: "memory");
}

// ---------------------------------------------------------------------------
// split: fp32 -> (fp16 hi, fp16 lo), vectorized x4
// ---------------------------------------------------------------------------
__global__ void split_kernel(const float* __restrict__ X,
                             __half* __restrict__ H,
                             __half* __restrict__ L, int n4)
{
    int i = blockIdx.x * blockDim.x + threadIdx.x;
    if (i >= n4) return;
    float4 v = ((const float4*)X)[i];
    float vv[4] = {v.x, v.y, v.z, v.w};
    __half h[4], l[4];
#pragma unroll
    for (int j = 0; j < 4; j++) {
        h[j] = __float2half(vv[j]);
        l[j] = __float2half(vv[j] - __half2float(h[j]));
    }
    __half2 h0 = {h[0], h[1]}, h1 = {h[2], h[3]};
    __half2 l0 = {l[0], l[1]}, l1 = {l[2], l[3]};
    ((__half2*)H)[2 * i]     = h0;
    ((__half2*)H)[2 * i + 1] = h1;
    ((__half2*)L)[2 * i]     = l0;
    ((__half2*)L)[2 * i + 1] = l1;
}

// ---------------------------------------------------------------------------
// merged transpose: all four weights in one launch (grid.z selects tensor)
// ---------------------------------------------------------------------------
__global__ void transpose_all_kernel(
    const float* __restrict__ Wq, const float* __restrict__ Wk,
    const float* __restrict__ Wv, const float* __restrict__ Wo,
    __half* __restrict__ Tq, __half* __restrict__ Tk,
    __half* __restrict__ Tv, __half* __restrict__ To)
{
    const int z = blockIdx.z;
    const float* W;
    __half* Th;
    int N;
    if (z == 0)      { W = Wq; Th = Tq; N = C_; }
    else if (z == 1) { W = Wk; Th = Tk; N = KVD; }
    else if (z == 2) { W = Wv; Th = Tv; N = KVD; }
    else             { W = Wo; Th = To; N = C_; }
    const int K = C_;
    const int n0 = blockIdx.x * 32, k0 = blockIdx.y * 32;
    if (n0 >= N) return;

    __shared__ float t[32][33];
    int tx = threadIdx.x, ty = threadIdx.y;  // 32 x 8
#pragma unroll
    for (int j = 0; j < 4; j++)
        t[ty + 8 * j][tx] = W[(size_t)(k0 + ty + 8 * j) * N + n0 + tx];
    __syncthreads();
#pragma unroll
    for (int j = 0; j < 4; j++)
        Th[(size_t)(n0 + ty + 8 * j) * K + k0 + tx] =
            __float2half(t[tx][ty + 8 * j]);
}

// ---------------------------------------------------------------------------
// Fused QKV projection + RoPE + fp16 split; double-buffered smem (R11 proven)
// ---------------------------------------------------------------------------
#define SAS   40
#define GBUF  (128 * SAS * 2)
#define GSTG3 (3 * GBUF)
#define QKV_SMEM (2 * GSTG3)
#define GSTG2 (2 * GBUF)
#define G1_SMEM (2 * GSTG2)

extern __shared__ char dynsm[];

__global__ __launch_bounds__(256) void qkv_gemm(
    const __half* __restrict__ Ah, const __half* __restrict__ Al,
    const __half* __restrict__ Wqh, const __half* __restrict__ Wkh,
    const __half* __restrict__ Wvh,
    __half* __restrict__ Qh, __half* __restrict__ Ql,
    __half* __restrict__ Kh, __half* __restrict__ Vh,
    const int* __restrict__ posp)
{
    const int K = C_;
    const int tid = threadIdx.x;
    const int lane = tid & 31, wid = tid >> 5;
    const int wm = wid & 1, wn = wid >> 1;
    const int m0 = blockIdx.y * 128;
    const int nq = blockIdx.x;

    const __half* Bp;
    int mode;
    if (nq < 16)      { Bp = Wqh + (size_t)nq * 128 * K;        mode = 0; }
    else if (nq < 20) { Bp = Wkh + (size_t)(nq - 16) * 128 * K; mode = 1; }
    else              { Bp = Wvh + (size_t)(nq - 20) * 128 * K; mode = 2; }

    const int ldrow = tid >> 1, ldhalf = tid & 1;
    const __half* gAh = Ah + (size_t)(m0 + ldrow) * K + ldhalf * 16;
    const __half* gAl = Al + (size_t)(m0 + ldrow) * K + ldhalf * 16;
    const __half* gBh = Bp + (size_t)ldrow * K + ldhalf * 16;
    char* dsm = dynsm + (ldrow * SAS + ldhalf * 16) * 2;

    const int mid = lane >> 3, rin = lane & 7;
    const uint32_t usm = smem_u32(dynsm);
    const uint32_t aoff =
        ((wm * 64 + (mid & 1) * 8 + rin) * SAS + (mid >> 1) * 8) * 2;
    const uint32_t boff =
        ((wn * 16 + (mid >> 1) * 8 + rin) * SAS + (mid & 1) * 8) * 2;
    const uint32_t uAh = usm + aoff, uAl = usm + GBUF + aoff;
    const uint32_t uBh = usm + 2 * GBUF + boff;

    float acc[4][4][4];
#pragma unroll
    for (int mt = 0; mt < 4; mt++)
#pragma unroll
        for (int nt = 0; nt < 4; nt++)
#pragma unroll
            for (int j = 0; j < 4; j++) acc[mt][nt][j] = 0.0f;

    uint4 rah[2], ral[2], rbh[2];

#define GLOAD(k0)                                            \
    {                                                        \
        rah[0] = *(const uint4*)(gAh + (k0));                \
        rah[1] = *(const uint4*)(gAh + (k0) + 8);            \
        ral[0] = *(const uint4*)(gAl + (k0));                \
        ral[1] = *(const uint4*)(gAl + (k0) + 8);            \
        rbh[0] = *(const uint4*)(gBh + (k0));                \
        rbh[1] = *(const uint4*)(gBh + (k0) + 8);            \
    }
#define SSTORE(stg)                                               \
    {                                                             \
        char* d = dsm + (stg) * GSTG3;                            \
        *(uint4*)(d)                 = rah[0];                    \
        *(uint4*)(d + 16)            = rah[1];                    \
        *(uint4*)(d + GBUF)          = ral[0];                    \
        *(uint4*)(d + GBUF + 16)     = ral[1];                    \
        *(uint4*)(d + 2 * GBUF)      = rbh[0];                    \
        *(uint4*)(d + 2 * GBUF + 16) = rbh[1];                    \
    }

    GLOAD(0);
    SSTORE(0);
    __syncthreads();

    const int nch = K / 32;
    for (int ch = 0; ch < nch; ch++) {
        const bool more = (ch + 1 < nch);
        if (more) GLOAD((ch + 1) * 32);
        const uint32_t so = (ch & 1) * GSTG3;

#pragma unroll
        for (int ks = 0; ks < 2; ks++) {
            uint32_t fah[4][4], fal[4][4], fbh[2][4];
#pragma unroll
            for (int mt = 0; mt < 4; mt++) {
                ldsm4(fah[mt], uAh + so + mt * (16 * SAS * 2) + ks * 32);
                ldsm4(fal[mt], uAl + so + mt * (16 * SAS * 2) + ks * 32);
            }
            ldsm4(fbh[0], uBh + so + ks * 32);
            ldsm4(fbh[1], uBh + so + 64 * (SAS * 2) + ks * 32);
#pragma unroll
            for (int mt = 0; mt < 4; mt++)
#pragma unroll
                for (int nt = 0; nt < 4; nt++) {
                    const uint32_t* b_h = &fbh[nt >> 1][(nt & 1) * 2];
                    mma16816h(acc[mt][nt], fah[mt], b_h);
                    mma16816h(acc[mt][nt], fal[mt], b_h);
                }
        }
        if (more) {
            SSTORE((ch + 1) & 1);
            __syncthreads();
        }
    }
#undef GLOAD
#undef SSTORE

    const int g = lane >> 2, tg = lane & 3;

    if (mode == 2) {
        const int coff = (nq - 20) * 128;
#pragma unroll
        for (int mt = 0; mt < 4; mt++) {
            const int r0 = m0 + wm * 64 + mt * 16 + g;
#pragma unroll
            for (int nt = 0; nt < 4; nt++) {
                const int c = wn * 16 + (nt & 1) * 8 + ((nt & 2) ? 64 : 0) + tg * 2;
                __half2 h0 = __floats2half2_rn(acc[mt][nt][0], acc[mt][nt][1]);
                __half2 h1 = __floats2half2_rn(acc[mt][nt][2], acc[mt][nt][3]);
                *(uint32_t*)(Vh + (size_t)r0 * KVD + coff + c)       = *(uint32_t*)&h0;
                *(uint32_t*)(Vh + (size_t)(r0 + 8) * KVD + coff + c) = *(uint32_t*)&h1;
            }
        }
        return;
    }

    const int posv = posp[0];
    const float LN1E4_128 = 9.210340371976184f / 128.0f;
#pragma unroll
    for (int mt = 0; mt < 4; mt++) {
        const int mr = m0 + wm * 64 + mt * 16 + g;
#pragma unroll
        for (int nt = 0; nt < 2; nt++) {
            const int c = wn * 16 + nt * 8 + tg * 2;
            const float f1 = __expf(-(float)(2 * (c >> 1)) * LN1E4_128);
            const float f2 = f1 * 0.01f;
#pragma unroll
            for (int rj = 0; rj < 2; rj++) {
                const int row = mr + rj * 8;
                const float pos = (float)(posv + (row & (T_ - 1)));
                const float a1 = pos * f1, a2 = pos * f2;
                const float c1 = cosf(a1), s1 = sinf(a1);
                const float c2 = cosf(a2), s2 = sinf(a2);
                float o1[2], o2[2];
#pragma unroll
                for (int jj = 0; jj < 2; jj++) {
                    const float x1 = acc[mt][nt][rj * 2 + jj];
                    const float x2 = acc[mt][nt + 2][rj * 2 + jj];
                    o1[jj] = x1 * c1 - x2 * s1;
                    o2[jj] = x2 * c2 + x1 * s2;
                }
                __half2 hi1 = __floats2half2_rn(o1[0], o1[1]);
                __half2 hi2 = __floats2half2_rn(o2[0], o2[1]);
                if (mode == 0) {
                    float2 hf1 = __half22float2(hi1), hf2 = __half22float2(hi2);
                    __half2 lo1 = __floats2half2_rn(o1[0] - hf1.x, o1[1] - hf1.y);
                    __half2 lo2 = __floats2half2_rn(o2[0] - hf2.x, o2[1] - hf2.y);
                    size_t base = (size_t)row * C_ + nq * 128 + c;
                    *(uint32_t*)(Qh + base)      = *(uint32_t*)&hi1;
                    *(uint32_t*)(Ql + base)      = *(uint32_t*)&lo1;
                    *(uint32_t*)(Qh + base + 64) = *(uint32_t*)&hi2;
                    *(uint32_t*)(Ql + base + 64) = *(uint32_t*)&lo2;
                } else {
                    size_t base = (size_t)row * KVD + (nq - 16) * 128 + c;
                    *(uint32_t*)(Kh + base)      = *(uint32_t*)&hi1;
                    *(uint32_t*)(Kh + base + 64) = *(uint32_t*)&hi2;
                }
            }
        }
    }
}

// ---------------------------------------------------------------------------
// fp16 single-pass Wo GEMM; double-buffered smem (R11 proven)
// ---------------------------------------------------------------------------
__global__ __launch_bounds__(256) void gemm_mma1(
    const __half* __restrict__ Ah, const __half* __restrict__ Bh,
    float* __restrict__ C, int N, int K)
{
    const int tid = threadIdx.x;
    const int lane = tid & 31, wid = tid >> 5;
    const int wm = wid & 1, wn = wid >> 1;
    const int m0 = blockIdx.y * 128, n0 = blockIdx.x * 128;

    const int ldrow = tid >> 1, ldhalf = tid & 1;
    const __half* gAh = Ah + (size_t)(m0 + ldrow) * K + ldhalf * 16;
    const __half* gBh = Bh + (size_t)(n0 + ldrow) * K + ldhalf * 16;
    char* dsm = dynsm + (ldrow * SAS + ldhalf * 16) * 2;

    const int mid = lane >> 3, rin = lane & 7;
    const uint32_t usm = smem_u32(dynsm);
    const uint32_t aoff =
        ((wm * 64 + (mid & 1) * 8 + rin) * SAS + (mid >> 1) * 8) * 2;
    const uint32_t boff =
        ((wn * 32 + (mid >> 1) * 8 + rin) * SAS + (mid & 1) * 8) * 2;
    const uint32_t uAh = usm + aoff;
    const uint32_t uBh = usm + GBUF + boff;

    float acc[4][4][4];
#pragma unroll
    for (int mt = 0; mt < 4; mt++)
#pragma unroll
        for (int nt = 0; nt < 4; nt++)
#pragma unroll
            for (int j = 0; j < 4; j++) acc[mt][nt][j] = 0.0f;

    uint4 rah[2], rbh[2];

#define GLOAD(k0)                                            \
    {                                                        \
        rah[0] = *(const uint4*)(gAh + (k0));                \
        rah[1] = *(const uint4*)(gAh + (k0) + 8);            \
        rbh[0] = *(const uint4*)(gBh + (k0));                \
        rbh[1] = *(const uint4*)(gBh + (k0) + 8);            \
    }
#define SSTORE(stg)                                          \
    {                                                        \
        char* d = dsm + (stg) * GSTG2;                       \
        *(uint4*)(d)             = rah[0];                   \
        *(uint4*)(d + 16)        = rah[1];                   \
        *(uint4*)(d + GBUF)      = rbh[0];                   \
        *(uint4*)(d + GBUF + 16) = rbh[1];                   \
    }

    GLOAD(0);
    SSTORE(0);
    __syncthreads();

    const int nch = K / 32;
    for (int ch = 0; ch < nch; ch++) {
        const bool more = (ch + 1 < nch);
        if (more) GLOAD((ch + 1) * 32);
        const uint32_t so = (ch & 1) * GSTG2;

#pragma unroll
        for (int ks = 0; ks < 2; ks++) {
            uint32_t fah[4][4], fbh[2][4];
#pragma unroll
            for (int mt = 0; mt < 4; mt++)
                ldsm4(fah[mt], uAh + so + mt * (16 * SAS * 2) + ks * 32);
#pragma unroll
            for (int np = 0; np < 2; np++)
                ldsm4(fbh[np], uBh + so + np * (16 * SAS * 2) + ks * 32);
#pragma unroll
            for (int mt = 0; mt < 4; mt++)
#pragma unroll
                for (int nt = 0; nt < 4; nt++)
                    mma16816h(acc[mt][nt], fah[mt], &fbh[nt >> 1][(nt & 1) * 2]);
        }
        if (more) {
            SSTORE((ch + 1) & 1);
            __syncthreads();
        }
    }
#undef GLOAD
#undef SSTORE

    const int g = lane >> 2, tg = lane & 3;
#pragma unroll
    for (int mt = 0; mt < 4; mt++) {
        const int mrow = m0 + wm * 64 + mt * 16 + g;
#pragma unroll
        for (int nt = 0; nt < 4; nt++) {
            const int ncol = n0 + wn * 32 + nt * 8 + tg * 2;
            float2 v0 = {acc[mt][nt][0], acc[mt][nt][1]};
            float2 v1 = {acc[mt][nt][2], acc[mt][nt][3]};
            *(float2*)(C + (size_t)mrow * N + ncol)       = v0;
            *(float2*)(C + (size_t)(mrow + 8) * N + ncol) = v1;
        }
    }
}

// ---------------------------------------------------------------------------
// Flash attention on mma.sync, cp.async double-buffered K/V tiles.
// 1 CTA/SM (reg-limited) — cp.async overlaps tile kt+1 DMA with tile kt compute.
// ---------------------------------------------------------------------------
#define SKP 136
#define FSTG (2 * 64 * SKP * 2)      // one stage: Kh + Vh (34816 B)
#define FL_SMEM (2 * FSTG)

__global__ __launch_bounds__(256) void flash_mma(
    const __half* __restrict__ Qh, const __half* __restrict__ Ql,
    const __half* __restrict__ Khg, const __half* __restrict__ Vhg,
    __half* __restrict__ Yh)
{
    const int tid = threadIdx.x, lane = tid & 31, w = tid >> 5;
    const int qb = blockIdx.x, h = blockIdx.y, b = blockIdx.z;
    const int kvh = h >> 2;
    const int g = lane >> 2, tg = lane & 3;
    const int mid = lane >> 3, rin = lane & 7;
    const int qrow0 = qb * 128 + w * 16;

    uint32_t qh[8][4], ql[8][4];
    {
        const __half* Qhb = Qh + ((size_t)b * T_ + qrow0) * C_ + h * HD;
        const __half* Qlb = Ql + ((size_t)b * T_ + qrow0) * C_ + h * HD;
#pragma unroll
        for (int kc = 0; kc < 8; kc++) {
#pragma unroll
            for (int fr = 0; fr < 4; fr++) {
                int r = g + (fr & 1) * 8;
                int c = kc * 16 + tg * 2 + (fr >> 1) * 8;
                qh[kc][fr] = *(const uint32_t*)(Qhb + (size_t)r * C_ + c);
                ql[kc][fr] = *(const uint32_t*)(Qlb + (size_t)r * C_ + c);
            }
        }
    }

    float o[16][4];
#pragma unroll
    for (int nt = 0; nt < 16; nt++)
#pragma unroll
        for (int j = 0; j < 4; j++) o[nt][j] = 0.0f;
    float m0 = -INFINITY, m1 = -INFINITY, l0 = 0.0f, l1 = 0.0f;

    const float cscale = 0.08838834764831845f;
    const int rg0 = qrow0 + g, rg1 = rg0 + 8;
    const int ktmax = 2 * qb + 2;

    const __half* Kh0 = Khg + (size_t)b * T_ * KVD + kvh * HD;
    const __half* Vh0 = Vhg + (size_t)b * T_ * KVD + kvh * HD;

    const uint32_t usm = smem_u32(dynsm);
    const uint32_t uK = usm, uV = usm + 64 * SKP * 2;
    const uint32_t kfrag = (((mid >> 1) * 8 + rin) * SKP + (mid & 1) * 8) * 2;
    const uint32_t vfrag = (((mid & 1) * 8 + rin) * SKP + (mid >> 1) * 8) * 2;

    // per-thread cp.async lane: 4 chunks of 16B for K and V each
    const int lr = tid >> 4, lc8 = (tid & 15) << 3;   // row 0..15, col 0,8,..,120

#define FLOAD(stg, kt)                                                        \
    {                                                                         \
        const __half* Kt = Kh0 + (size_t)(kt) * 64 * KVD;                     \
        const __half* Vt = Vh0 + (size_t)(kt) * 64 * KVD;                     \
        uint32_t base = usm + (stg) * FSTG;                                   \
        _Pragma("unroll")                                                     \
        for (int it = 0; it < 4; it++) {                                      \
            int r = lr + it * 16;                                             \
            uint32_t so = base + (r * SKP + lc8) * 2;                         \
            cpa16(so,                 Kt + (size_t)r * KVD + lc8);            \
            cpa16(so + 64 * SKP * 2,  Vt + (size_t)r * KVD + lc8);            \
        }                                                                     \
        cp_commit();                                                          \
    }

    FLOAD(0, 0);

    for (int kt = 0; kt < ktmax; kt++) {
        const bool more = (kt + 1 < ktmax);
        if (more) FLOAD((kt + 1) & 1, kt + 1);
        if (more) cp_wait1(); else cp_wait0();
        __syncthreads();

        const uint32_t so = (kt & 1) * FSTG;
        const uint32_t uKh = uK + so, uVh = uV + so;

        if (kt * 64 <= qrow0 + 15) {
            const bool needmask = (kt * 64 + 63 > qrow0);

            float s[8][4];
#pragma unroll
            for (int nt = 0; nt < 8; nt++)
#pragma unroll
                for (int j = 0; j < 4; j++) s[nt][j] = 0.0f;

#pragma unroll
            for (int kc = 0; kc < 8; kc++) {
                uint32_t bt[4][4];
#pragma unroll
                for (int nt2 = 0; nt2 < 4; nt2++)
                    ldsm4(bt[nt2], uKh + kfrag + (nt2 * 16 * SKP + kc * 16) * 2);
#pragma unroll
                for (int nt = 0; nt < 8; nt++) {
                    const uint32_t* bb = &bt[nt >> 1][(nt & 1) * 2];
                    mma16816h(s[nt], qh[kc], bb);
                    mma16816h(s[nt], ql[kc], bb);
                }
            }

#pragma unroll
            for (int nt = 0; nt < 8; nt++) {
#pragma unroll
                for (int j = 0; j < 4; j++) s[nt][j] *= cscale;
                if (needmask) {
                    int c0 = kt * 64 + nt * 8 + tg * 2;
                    if (c0 > rg0)     s[nt][0] = -1e30f;
                    if (c0 + 1 > rg0) s[nt][1] = -1e30f;
                    if (c0 > rg1)     s[nt][2] = -1e30f;
                    if (c0 + 1 > rg1) s[nt][3] = -1e30f;
                }
            }

            float mn0 = m0, mn1 = m1;
#pragma unroll
            for (int nt = 0; nt < 8; nt++) {
                mn0 = fmaxf(mn0, fmaxf(s[nt][0], s[nt][1]));
                mn1 = fmaxf(mn1, fmaxf(s[nt][2], s[nt][3]));
            }
            mn0 = fmaxf(mn0, __shfl_xor_sync(0xffffffffu, mn0, 1));
            mn0 = fmaxf(mn0, __shfl_xor_sync(0xffffffffu, mn0, 2));
            mn1 = fmaxf(mn1, __shfl_xor_sync(0xffffffffu, mn1, 1));
            mn1 = fmaxf(mn1, __shfl_xor_sync(0xffffffffu, mn1, 2));
            float fac0 = __expf(m0 - mn0), fac1 = __expf(m1 - mn1);
            m0 = mn0; m1 = mn1;

            uint32_t pa[4][4];
            float ps0 = 0.0f, ps1 = 0.0f;
#pragma unroll
            for (int kk = 0; kk < 4; kk++) {
                int nt = 2 * kk;
                float p00 = __expf(s[nt][0] - m0),     p01 = __expf(s[nt][1] - m0);
                float p02 = __expf(s[nt][2] - m1),     p03 = __expf(s[nt][3] - m1);
                float p10 = __expf(s[nt + 1][0] - m0), p11 = __expf(s[nt + 1][1] - m0);
                float p12 = __expf(s[nt + 1][2] - m1), p13 = __expf(s[nt + 1][3] - m1);
                ps0 += p00 + p01 + p10 + p11;
                ps1 += p02 + p03 + p12 + p13;
                __half2 a0 = __floats2half2_rn(p00, p01);
                __half2 a1 = __floats2half2_rn(p02, p03);
                __half2 a2 = __floats2half2_rn(p10, p11);
                __half2 a3 = __floats2half2_rn(p12, p13);
                pa[kk][0] = *(uint32_t*)&a0;
                pa[kk][1] = *(uint32_t*)&a1;
                pa[kk][2] = *(uint32_t*)&a2;
                pa[kk][3] = *(uint32_t*)&a3;
            }
            l0 = l0 * fac0 + ps0;
            l1 = l1 * fac1 + ps1;

#pragma unroll
            for (int nt = 0; nt < 16; nt++) {
                o[nt][0] *= fac0; o[nt][1] *= fac0;
                o[nt][2] *= fac1; o[nt][3] *= fac1;
            }

#pragma unroll
            for (int kk = 0; kk < 4; kk++) {
                uint32_t vb[8][4];
#pragma unroll
                for (int np = 0; np < 8; np++)
                    ldsm4t(vb[np], uVh + vfrag + (kk * 16 * SKP + np * 16) * 2);
#pragma unroll
                for (int nt = 0; nt < 16; nt++)
                    mma16816h(o[nt], pa[kk], &vb[nt >> 1][(nt & 1) * 2]);
            }
        }
        __syncthreads();
    }
#undef FLOAD

    l0 += __shfl_xor_sync(0xffffffffu, l0, 1);
    l0 += __shfl_xor_sync(0xffffffffu, l0, 2);
    l1 += __shfl_xor_sync(0xffffffffu, l1, 1);
    l1 += __shfl_xor_sync(0xffffffffu, l1, 2);
    float inv0 = 1.0f / l0, inv1 = 1.0f / l1;

    size_t row0 = (size_t)b * T_ + rg0;
    size_t row1 = (size_t)b * T_ + rg1;
#pragma unroll
    for (int nt = 0; nt < 16; nt++) {
        int col = h * HD + nt * 8 + tg * 2;
        __half2 h0 = __floats2half2_rn(o[nt][0] * inv0, o[nt][1] * inv0);
        __half2 h1 = __floats2half2_rn(o[nt][2] * inv1, o[nt][3] * inv1);
        *(uint32_t*)(Yh + row0 * C_ + col) = *(uint32_t*)&h0;
        *(uint32_t*)(Yh + row1 * C_ + col) = *(uint32_t*)&h1;
    }
}

// ---------------------------------------------------------------------------
extern "C" void kernel_launch(void* const* d_in, const int* in_sizes, int n_in,
                              void* d_out, int out_size)
{
    const float* x  = (const float*)d_in[0];
    const float* Wq = (const float*)d_in[1];
    const float* Wk = (const float*)d_in[2];
    const float* Wv = (const float*)d_in[3];
    const float* Wo = (const float*)d_in[4];
    const int*  pos = (const int*)d_in[5];
    float* out = (float*)d_out;

    __half *qh, *ql, *kh, *vh;
    cudaGetSymbolAddress((void**)&qh, s_qh); cudaGetSymbolAddress((void**)&ql, s_ql);
    cudaGetSymbolAddress((void**)&kh, s_kh); cudaGetSymbolAddress((void**)&vh, s_vh);
    __half *xh, *xl, *yh, *wqh, *wkh, *wvh, *woh;
    cudaGetSymbolAddress((void**)&xh, s_xh);   cudaGetSymbolAddress((void**)&xl, s_xl);
    cudaGetSymbolAddress((void**)&yh, s_yh);
    cudaGetSymbolAddress((void**)&wqh, s_wqh);
    cudaGetSymbolAddress((void**)&wkh, s_wkh);
    cudaGetSymbolAddress((void**)&wvh, s_wvh);
    cudaGetSymbolAddress((void**)&woh, s_woh);

    cudaFuncSetAttribute(qkv_gemm, cudaFuncAttributeMaxDynamicSharedMemorySize,
                         QKV_SMEM);
    cudaFuncSetAttribute(gemm_mma1, cudaFuncAttributeMaxDynamicSharedMemorySize,
                         G1_SMEM);
    cudaFuncSetAttribute(flash_mma, cudaFuncAttributeMaxDynamicSharedMemorySize,
                         FL_SMEM);

    {
        int n4 = M_ * C_ / 4;
        split_kernel<<<(n4 + 255) / 256, 256>>>(x, xh, xl, n4);
    }
    transpose_all_kernel<<<dim3(C_ / 32, C_ / 32, 4), dim3(32, 8)>>>(
        Wq, Wk, Wv, Wo, wqh, wkh, wvh, woh);

    qkv_gemm<<<dim3(24, M_ / 128), 256, QKV_SMEM>>>(xh, xl, wqh, wkh, wvh,
                                                    qh, ql, kh, vh, pos);

    flash_mma<<<dim3(T_ / 128, NH, B_), 256, FL_SMEM>>>(qh, ql, kh, vh, yh);

    gemm_mma1<<<dim3(C_ / 128, M_ / 128), 256, G1_SMEM>>>(yh, woh, out, C_, C_);
}

// round 13
// speedup vs baseline: 1.7177x; 1.0120x over previous
#include <cuda_runtime.h>
#include <cuda_fp16.h>
#include <math.h>
#include <stdint.h>

#define B_   4
#define T_   2048
#define C_   2048
#define NH   16
#define NKV  4
#define HD   128
#define KVD  (NKV*HD)   // 512
#define M_   (B_*T_)    // 8192

// ---------------- scratch (__device__ globals; no allocs allowed) ----------
__device__ __half s_qh[(size_t)M_ * C_],  s_ql[(size_t)M_ * C_];
__device__ __half s_kh[(size_t)M_ * KVD];
__device__ __half s_vh[(size_t)M_ * KVD];

__device__ __half s_xh[(size_t)M_ * C_],  s_xl[(size_t)M_ * C_];
__device__ __half s_yh[(size_t)M_ * C_];
__device__ __half s_wqh[(size_t)C_ * C_];
__device__ __half s_wkh[(size_t)KVD * C_];
__device__ __half s_wvh[(size_t)KVD * C_];
__device__ __half s_woh[(size_t)C_ * C_];

// ---------------- helpers ---------------------------------------------------
__device__ __forceinline__ uint32_t smem_u32(const void* p) {
    uint32_t a;
    asm("{ .reg .u64 t; cvta.to.shared.u64 t, %1; cvt.u32.u64 %0, t; }"
        : "=r"(a) : "l"(p));
    return a;
}
__device__ __forceinline__ void ldsm4(uint32_t* r, uint32_t addr) {
    asm volatile("ldmatrix.sync.aligned.m8n8.x4.shared.b16 {%0,%1,%2,%3}, [%4];"
                 : "=r"(r[0]), "=r"(r[1]), "=r"(r[2]), "=r"(r[3]) : "r"(addr));
}
__device__ __forceinline__ void ldsm4t(uint32_t* r, uint32_t addr) {
    asm volatile("ldmatrix.sync.aligned.m8n8.x4.trans.shared.b16 {%0,%1,%2,%3}, [%4];"
                 : "=r"(r[0]), "=r"(r[1]), "=r"(r[2]), "=r"(r[3]) : "r"(addr));
}
__device__ __forceinline__ void mma16816h(float* c, const uint32_t* a,
                                          const uint32_t* b) {
    asm volatile(
        "mma.sync.aligned.m16n8k16.row.col.f32.f16.f16.f32 "
        "{%0,%1,%2,%3}, {%4,%5,%6,%7}, {%8,%9}, {%0,%1,%2,%3};"
        : "+f"(c[0]), "+f"(c[1]), "+f"(c[2]), "+f"(c[3])
        : "r"(a[0]), "r"(a[1]), "r"(a[2]), "r"(a[3]), "r"(b[0]), "r"(b[1]));
}
__device__ __forceinline__ void cpa16(uint32_t dst, const void* src) {
    asm volatile("cp.async.cg.shared.global [%0], [%1], 16;"
                 :: "r"(dst), "l"(src));
}
__device__ __forceinline__ void cp_commit() {
    asm volatile("cp.async.commit_group;");
}
__device__ __forceinline__ void cp_wait0() {
    asm volatile("cp.async.wait_group 0;" ::: "memory");
}
__device__ __forceinline__ void cp_wait1() {
    asm volatile("cp.async.wait_group 1;" ::: "memory");
}

// ---------------------------------------------------------------------------
// split: fp32 -> (fp16 hi, fp16 lo), vectorized x4
// ---------------------------------------------------------------------------
__global__ void split_kernel(const float* __restrict__ X,
                             __half* __restrict__ H,
                             __half* __restrict__ L, int n4)
{
    int i = blockIdx.x * blockDim.x + threadIdx.x;
    if (i >= n4) return;
    float4 v = ((const float4*)X)[i];
    float vv[4] = {v.x, v.y, v.z, v.w};
    __half h[4], l[4];
#pragma unroll
    for (int j = 0; j < 4; j++) {
        h[j] = __float2half(vv[j]);
        l[j] = __float2half(vv[j] - __half2float(h[j]));
    }
    __half2 h0 = {h[0], h[1]}, h1 = {h[2], h[3]};
    __half2 l0 = {l[0], l[1]}, l1 = {l[2], l[3]};
    ((__half2*)H)[2 * i]     = h0;
    ((__half2*)H)[2 * i + 1] = h1;
    ((__half2*)L)[2 * i]     = l0;
    ((__half2*)L)[2 * i + 1] = l1;
}

// ---------------------------------------------------------------------------
// merged transpose: all four weights in one launch (grid.z selects tensor)
// ---------------------------------------------------------------------------
__global__ void transpose_all_kernel(
    const float* __restrict__ Wq, const float* __restrict__ Wk,
    const float* __restrict__ Wv, const float* __restrict__ Wo,
    __half* __restrict__ Tq, __half* __restrict__ Tk,
    __half* __restrict__ Tv, __half* __restrict__ To)
{
    const int z = blockIdx.z;
    const float* W;
    __half* Th;
    int N;
    if (z == 0)      { W = Wq; Th = Tq; N = C_; }
    else if (z == 1) { W = Wk; Th = Tk; N = KVD; }
    else if (z == 2) { W = Wv; Th = Tv; N = KVD; }
    else             { W = Wo; Th = To; N = C_; }
    const int K = C_;
    const int n0 = blockIdx.x * 32, k0 = blockIdx.y * 32;
    if (n0 >= N) return;

    __shared__ float t[32][33];
    int tx = threadIdx.x, ty = threadIdx.y;  // 32 x 8
#pragma unroll
    for (int j = 0; j < 4; j++)
        t[ty + 8 * j][tx] = W[(size_t)(k0 + ty + 8 * j) * N + n0 + tx];
    __syncthreads();
#pragma unroll
    for (int j = 0; j < 4; j++)
        Th[(size_t)(n0 + ty + 8 * j) * K + k0 + tx] =
            __float2half(t[tx][ty + 8 * j]);
}

// ---------------------------------------------------------------------------
// Fused QKV projection + RoPE + fp16 split; double-buffered smem (R11 proven)
// ---------------------------------------------------------------------------
#define SAS   40
#define GBUF  (128 * SAS * 2)
#define GSTG3 (3 * GBUF)
#define QKV_SMEM (2 * GSTG3)
#define GSTG2 (2 * GBUF)
#define G1_SMEM (2 * GSTG2)

extern __shared__ char dynsm[];

__global__ __launch_bounds__(256) void qkv_gemm(
    const __half* __restrict__ Ah, const __half* __restrict__ Al,
    const __half* __restrict__ Wqh, const __half* __restrict__ Wkh,
    const __half* __restrict__ Wvh,
    __half* __restrict__ Qh, __half* __restrict__ Ql,
    __half* __restrict__ Kh, __half* __restrict__ Vh,
    const int* __restrict__ posp)
{
    const int K = C_;
    const int tid = threadIdx.x;
    const int lane = tid & 31, wid = tid >> 5;
    const int wm = wid & 1, wn = wid >> 1;
    const int m0 = blockIdx.y * 128;
    const int nq = blockIdx.x;

    const __half* Bp;
    int mode;
    if (nq < 16)      { Bp = Wqh + (size_t)nq * 128 * K;        mode = 0; }
    else if (nq < 20) { Bp = Wkh + (size_t)(nq - 16) * 128 * K; mode = 1; }
    else              { Bp = Wvh + (size_t)(nq - 20) * 128 * K; mode = 2; }

    const int ldrow = tid >> 1, ldhalf = tid & 1;
    const __half* gAh = Ah + (size_t)(m0 + ldrow) * K + ldhalf * 16;
    const __half* gAl = Al + (size_t)(m0 + ldrow) * K + ldhalf * 16;
    const __half* gBh = Bp + (size_t)ldrow * K + ldhalf * 16;
    char* dsm = dynsm + (ldrow * SAS + ldhalf * 16) * 2;

    const int mid = lane >> 3, rin = lane & 7;
    const uint32_t usm = smem_u32(dynsm);
    const uint32_t aoff =
        ((wm * 64 + (mid & 1) * 8 + rin) * SAS + (mid >> 1) * 8) * 2;
    const uint32_t boff =
        ((wn * 16 + (mid >> 1) * 8 + rin) * SAS + (mid & 1) * 8) * 2;
    const uint32_t uAh = usm + aoff, uAl = usm + GBUF + aoff;
    const uint32_t uBh = usm + 2 * GBUF + boff;

    float acc[4][4][4];
#pragma unroll
    for (int mt = 0; mt < 4; mt++)
#pragma unroll
        for (int nt = 0; nt < 4; nt++)
#pragma unroll
            for (int j = 0; j < 4; j++) acc[mt][nt][j] = 0.0f;

    uint4 rah[2], ral[2], rbh[2];

#define GLOAD(k0)                                            \
    {                                                        \
        rah[0] = *(const uint4*)(gAh + (k0));                \
        rah[1] = *(const uint4*)(gAh + (k0) + 8);            \
        ral[0] = *(const uint4*)(gAl + (k0));                \
        ral[1] = *(const uint4*)(gAl + (k0) + 8);            \
        rbh[0] = *(const uint4*)(gBh + (k0));                \
        rbh[1] = *(const uint4*)(gBh + (k0) + 8);            \
    }
#define SSTORE(stg)                                               \
    {                                                             \
        char* d = dsm + (stg) * GSTG3;                            \
        *(uint4*)(d)                 = rah[0];                    \
        *(uint4*)(d + 16)            = rah[1];                    \
        *(uint4*)(d + GBUF)          = ral[0];                    \
        *(uint4*)(d + GBUF + 16)     = ral[1];                    \
        *(uint4*)(d + 2 * GBUF)      = rbh[0];                    \
        *(uint4*)(d + 2 * GBUF + 16) = rbh[1];                    \
    }

    GLOAD(0);
    SSTORE(0);
    __syncthreads();

    const int nch = K / 32;
    for (int ch = 0; ch < nch; ch++) {
        const bool more = (ch + 1 < nch);
        if (more) GLOAD((ch + 1) * 32);
        const uint32_t so = (ch & 1) * GSTG3;

#pragma unroll
        for (int ks = 0; ks < 2; ks++) {
            uint32_t fah[4][4], fal[4][4], fbh[2][4];
#pragma unroll
            for (int mt = 0; mt < 4; mt++) {
                ldsm4(fah[mt], uAh + so + mt * (16 * SAS * 2) + ks * 32);
                ldsm4(fal[mt], uAl + so + mt * (16 * SAS * 2) + ks * 32);
            }
            ldsm4(fbh[0], uBh + so + ks * 32);
            ldsm4(fbh[1], uBh + so + 64 * (SAS * 2) + ks * 32);
#pragma unroll
            for (int mt = 0; mt < 4; mt++)
#pragma unroll
                for (int nt = 0; nt < 4; nt++) {
                    const uint32_t* b_h = &fbh[nt >> 1][(nt & 1) * 2];
                    mma16816h(acc[mt][nt], fah[mt], b_h);
                    mma16816h(acc[mt][nt], fal[mt], b_h);
                }
        }
        if (more) {
            SSTORE((ch + 1) & 1);
            __syncthreads();
        }
    }
#undef GLOAD
#undef SSTORE

    const int g = lane >> 2, tg = lane & 3;

    if (mode == 2) {
        const int coff = (nq - 20) * 128;
#pragma unroll
        for (int mt = 0; mt < 4; mt++) {
            const int r0 = m0 + wm * 64 + mt * 16 + g;
#pragma unroll
            for (int nt = 0; nt < 4; nt++) {
                const int c = wn * 16 + (nt & 1) * 8 + ((nt & 2) ? 64 : 0) + tg * 2;
                __half2 h0 = __floats2half2_rn(acc[mt][nt][0], acc[mt][nt][1]);
                __half2 h1 = __floats2half2_rn(acc[mt][nt][2], acc[mt][nt][3]);
                *(uint32_t*)(Vh + (size_t)r0 * KVD + coff + c)       = *(uint32_t*)&h0;
                *(uint32_t*)(Vh + (size_t)(r0 + 8) * KVD + coff + c) = *(uint32_t*)&h1;
            }
        }
        return;
    }

    const int posv = posp[0];
    const float LN1E4_128 = 9.210340371976184f / 128.0f;
#pragma unroll
    for (int mt = 0; mt < 4; mt++) {
        const int mr = m0 + wm * 64 + mt * 16 + g;
#pragma unroll
        for (int nt = 0; nt < 2; nt++) {
            const int c = wn * 16 + nt * 8 + tg * 2;
            const float f1 = __expf(-(float)(2 * (c >> 1)) * LN1E4_128);
            const float f2 = f1 * 0.01f;
#pragma unroll
            for (int rj = 0; rj < 2; rj++) {
                const int row = mr + rj * 8;
                const float pos = (float)(posv + (row & (T_ - 1)));
                const float a1 = pos * f1, a2 = pos * f2;
                const float c1 = cosf(a1), s1 = sinf(a1);
                const float c2 = cosf(a2), s2 = sinf(a2);
                float o1[2], o2[2];
#pragma unroll
                for (int jj = 0; jj < 2; jj++) {
                    const float x1 = acc[mt][nt][rj * 2 + jj];
                    const float x2 = acc[mt][nt + 2][rj * 2 + jj];
                    o1[jj] = x1 * c1 - x2 * s1;
                    o2[jj] = x2 * c2 + x1 * s2;
                }
                __half2 hi1 = __floats2half2_rn(o1[0], o1[1]);
                __half2 hi2 = __floats2half2_rn(o2[0], o2[1]);
                if (mode == 0) {
                    float2 hf1 = __half22float2(hi1), hf2 = __half22float2(hi2);
                    __half2 lo1 = __floats2half2_rn(o1[0] - hf1.x, o1[1] - hf1.y);
                    __half2 lo2 = __floats2half2_rn(o2[0] - hf2.x, o2[1] - hf2.y);
                    size_t base = (size_t)row * C_ + nq * 128 + c;
                    *(uint32_t*)(Qh + base)      = *(uint32_t*)&hi1;
                    *(uint32_t*)(Ql + base)      = *(uint32_t*)&lo1;
                    *(uint32_t*)(Qh + base + 64) = *(uint32_t*)&hi2;
                    *(uint32_t*)(Ql + base + 64) = *(uint32_t*)&lo2;
                } else {
                    size_t base = (size_t)row * KVD + (nq - 16) * 128 + c;
                    *(uint32_t*)(Kh + base)      = *(uint32_t*)&hi1;
                    *(uint32_t*)(Kh + base + 64) = *(uint32_t*)&hi2;
                }
            }
        }
    }
}

// ---------------------------------------------------------------------------
// fp16 single-pass Wo GEMM; double-buffered smem (R11 proven)
// ---------------------------------------------------------------------------
__global__ __launch_bounds__(256) void gemm_mma1(
    const __half* __restrict__ Ah, const __half* __restrict__ Bh,
    float* __restrict__ C, int N, int K)
{
    const int tid = threadIdx.x;
    const int lane = tid & 31, wid = tid >> 5;
    const int wm = wid & 1, wn = wid >> 1;
    const int m0 = blockIdx.y * 128, n0 = blockIdx.x * 128;

    const int ldrow = tid >> 1, ldhalf = tid & 1;
    const __half* gAh = Ah + (size_t)(m0 + ldrow) * K + ldhalf * 16;
    const __half* gBh = Bh + (size_t)(n0 + ldrow) * K + ldhalf * 16;
    char* dsm = dynsm + (ldrow * SAS + ldhalf * 16) * 2;

    const int mid = lane >> 3, rin = lane & 7;
    const uint32_t usm = smem_u32(dynsm);
    const uint32_t aoff =
        ((wm * 64 + (mid & 1) * 8 + rin) * SAS + (mid >> 1) * 8) * 2;
    const uint32_t boff =
        ((wn * 32 + (mid >> 1) * 8 + rin) * SAS + (mid & 1) * 8) * 2;
    const uint32_t uAh = usm + aoff;
    const uint32_t uBh = usm + GBUF + boff;

    float acc[4][4][4];
#pragma unroll
    for (int mt = 0; mt < 4; mt++)
#pragma unroll
        for (int nt = 0; nt < 4; nt++)
#pragma unroll
            for (int j = 0; j < 4; j++) acc[mt][nt][j] = 0.0f;

    uint4 rah[2], rbh[2];

#define GLOAD(k0)                                            \
    {                                                        \
        rah[0] = *(const uint4*)(gAh + (k0));                \
        rah[1] = *(const uint4*)(gAh + (k0) + 8);            \
        rbh[0] = *(const uint4*)(gBh + (k0));                \
        rbh[1] = *(const uint4*)(gBh + (k0) + 8);            \
    }
#define SSTORE(stg)                                          \
    {                                                        \
        char* d = dsm + (stg) * GSTG2;                       \
        *(uint4*)(d)             = rah[0];                   \
        *(uint4*)(d + 16)        = rah[1];                   \
        *(uint4*)(d + GBUF)      = rbh[0];                   \
        *(uint4*)(d + GBUF + 16) = rbh[1];                   \
    }

    GLOAD(0);
    SSTORE(0);
    __syncthreads();

    const int nch = K / 32;
    for (int ch = 0; ch < nch; ch++) {
        const bool more = (ch + 1 < nch);
        if (more) GLOAD((ch + 1) * 32);
        const uint32_t so = (ch & 1) * GSTG2;

#pragma unroll
        for (int ks = 0; ks < 2; ks++) {
            uint32_t fah[4][4], fbh[2][4];
#pragma unroll
            for (int mt = 0; mt < 4; mt++)
                ldsm4(fah[mt], uAh + so + mt * (16 * SAS * 2) + ks * 32);
#pragma unroll
            for (int np = 0; np < 2; np++)
                ldsm4(fbh[np], uBh + so + np * (16 * SAS * 2) + ks * 32);
#pragma unroll
            for (int mt = 0; mt < 4; mt++)
#pragma unroll
                for (int nt = 0; nt < 4; nt++)
                    mma16816h(acc[mt][nt], fah[mt], &fbh[nt >> 1][(nt & 1) * 2]);
        }
        if (more) {
            SSTORE((ch + 1) & 1);
            __syncthreads();
        }
    }
#undef GLOAD
#undef SSTORE

    const int g = lane >> 2, tg = lane & 3;
#pragma unroll
    for (int mt = 0; mt < 4; mt++) {
        const int mrow = m0 + wm * 64 + mt * 16 + g;
#pragma unroll
        for (int nt = 0; nt < 4; nt++) {
            const int ncol = n0 + wn * 32 + nt * 8 + tg * 2;
            float2 v0 = {acc[mt][nt][0], acc[mt][nt][1]};
            float2 v1 = {acc[mt][nt][2], acc[mt][nt][3]};
            *(float2*)(C + (size_t)mrow * N + ncol)       = v0;
            *(float2*)(C + (size_t)(mrow + 8) * N + ncol) = v1;
        }
    }
}

// ---------------------------------------------------------------------------
// Flash attention: 128-thread CTA (4 warps x 16 rows = 64 q-rows) so two CTAs
// co-reside per SM (230 regs/thread). cp.async double-buffered K/V tiles.
// ---------------------------------------------------------------------------
#define SKP 136
#define FSTG (2 * 64 * SKP * 2)      // one stage: Kh + Vh (34816 B)
#define FL_SMEM (2 * FSTG)

__global__ __launch_bounds__(128) void flash_mma(
    const __half* __restrict__ Qh, const __half* __restrict__ Ql,
    const __half* __restrict__ Khg, const __half* __restrict__ Vhg,
    __half* __restrict__ Yh)
{
    const int tid = threadIdx.x, lane = tid & 31, w = tid >> 5;
    const int qb = blockIdx.x, h = blockIdx.y, b = blockIdx.z;
    const int kvh = h >> 2;
    const int g = lane >> 2, tg = lane & 3;
    const int mid = lane >> 3, rin = lane & 7;
    const int qrow0 = qb * 64 + w * 16;

    uint32_t qh[8][4], ql[8][4];
    {
        const __half* Qhb = Qh + ((size_t)b * T_ + qrow0) * C_ + h * HD;
        const __half* Qlb = Ql + ((size_t)b * T_ + qrow0) * C_ + h * HD;
#pragma unroll
        for (int kc = 0; kc < 8; kc++) {
#pragma unroll
            for (int fr = 0; fr < 4; fr++) {
                int r = g + (fr & 1) * 8;
                int c = kc * 16 + tg * 2 + (fr >> 1) * 8;
                qh[kc][fr] = *(const uint32_t*)(Qhb + (size_t)r * C_ + c);
                ql[kc][fr] = *(const uint32_t*)(Qlb + (size_t)r * C_ + c);
            }
        }
    }

    float o[16][4];
#pragma unroll
    for (int nt = 0; nt < 16; nt++)
#pragma unroll
        for (int j = 0; j < 4; j++) o[nt][j] = 0.0f;
    float m0 = -INFINITY, m1 = -INFINITY, l0 = 0.0f, l1 = 0.0f;

    const float cscale = 0.08838834764831845f;
    const int rg0 = qrow0 + g, rg1 = rg0 + 8;
    const int ktmax = qb + 1;

    const __half* Kh0 = Khg + (size_t)b * T_ * KVD + kvh * HD;
    const __half* Vh0 = Vhg + (size_t)b * T_ * KVD + kvh * HD;

    const uint32_t usm = smem_u32(dynsm);
    const uint32_t uK = usm, uV = usm + 64 * SKP * 2;
    const uint32_t kfrag = (((mid >> 1) * 8 + rin) * SKP + (mid & 1) * 8) * 2;
    const uint32_t vfrag = (((mid & 1) * 8 + rin) * SKP + (mid >> 1) * 8) * 2;

    // 128-thread loader: 8 row-steps x 16B chunks for each of K, V
    const int lr = tid >> 4, lc8 = (tid & 15) << 3;   // row 0..7, col 0..120

#define FLOAD(stg, kt)                                                        \
    {                                                                         \
        const __half* Kt = Kh0 + (size_t)(kt) * 64 * KVD;                     \
        const __half* Vt = Vh0 + (size_t)(kt) * 64 * KVD;                     \
        uint32_t base = usm + (stg) * FSTG;                                   \
        _Pragma("unroll")                                                     \
        for (int it = 0; it < 8; it++) {                                      \
            int r = lr + it * 8;                                              \
            uint32_t so = base + (r * SKP + lc8) * 2;                         \
            cpa16(so,                 Kt + (size_t)r * KVD + lc8);            \
            cpa16(so + 64 * SKP * 2,  Vt + (size_t)r * KVD + lc8);            \
        }                                                                     \
        cp_commit();                                                          \
    }

    FLOAD(0, 0);

    for (int kt = 0; kt < ktmax; kt++) {
        const bool more = (kt + 1 < ktmax);
        if (more) FLOAD((kt + 1) & 1, kt + 1);
        if (more) cp_wait1(); else cp_wait0();
        __syncthreads();

        const uint32_t so = (kt & 1) * FSTG;
        const uint32_t uKh = uK + so, uVh = uV + so;

        {
            const bool needmask = (kt * 64 + 63 > qrow0);

            float s[8][4];
#pragma unroll
            for (int nt = 0; nt < 8; nt++)
#pragma unroll
                for (int j = 0; j < 4; j++) s[nt][j] = 0.0f;

#pragma unroll
            for (int kc = 0; kc < 8; kc++) {
                uint32_t bt[4][4];
#pragma unroll
                for (int nt2 = 0; nt2 < 4; nt2++)
                    ldsm4(bt[nt2], uKh + kfrag + (nt2 * 16 * SKP + kc * 16) * 2);
#pragma unroll
                for (int nt = 0; nt < 8; nt++) {
                    const uint32_t* bb = &bt[nt >> 1][(nt & 1) * 2];
                    mma16816h(s[nt], qh[kc], bb);
                    mma16816h(s[nt], ql[kc], bb);
                }
            }

#pragma unroll
            for (int nt = 0; nt < 8; nt++) {
#pragma unroll
                for (int j = 0; j < 4; j++) s[nt][j] *= cscale;
                if (needmask) {
                    int c0 = kt * 64 + nt * 8 + tg * 2;
                    if (c0 > rg0)     s[nt][0] = -1e30f;
                    if (c0 + 1 > rg0) s[nt][1] = -1e30f;
                    if (c0 > rg1)     s[nt][2] = -1e30f;
                    if (c0 + 1 > rg1) s[nt][3] = -1e30f;
                }
            }

            float mn0 = m0, mn1 = m1;
#pragma unroll
            for (int nt = 0; nt < 8; nt++) {
                mn0 = fmaxf(mn0, fmaxf(s[nt][0], s[nt][1]));
                mn1 = fmaxf(mn1, fmaxf(s[nt][2], s[nt][3]));
            }
            mn0 = fmaxf(mn0, __shfl_xor_sync(0xffffffffu, mn0, 1));
            mn0 = fmaxf(mn0, __shfl_xor_sync(0xffffffffu, mn0, 2));
            mn1 = fmaxf(mn1, __shfl_xor_sync(0xffffffffu, mn1, 1));
            mn1 = fmaxf(mn1, __shfl_xor_sync(0xffffffffu, mn1, 2));
            float fac0 = __expf(m0 - mn0), fac1 = __expf(m1 - mn1);
            m0 = mn0; m1 = mn1;

            uint32_t pa[4][4];
            float ps0 = 0.0f, ps1 = 0.0f;
#pragma unroll
            for (int kk = 0; kk < 4; kk++) {
                int nt = 2 * kk;
                float p00 = __expf(s[nt][0] - m0),     p01 = __expf(s[nt][1] - m0);
                float p02 = __expf(s[nt][2] - m1),     p03 = __expf(s[nt][3] - m1);
                float p10 = __expf(s[nt + 1][0] - m0), p11 = __expf(s[nt + 1][1] - m0);
                float p12 = __expf(s[nt + 1][2] - m1), p13 = __expf(s[nt + 1][3] - m1);
                ps0 += p00 + p01 + p10 + p11;
                ps1 += p02 + p03 + p12 + p13;
                __half2 a0 = __floats2half2_rn(p00, p01);
                __half2 a1 = __floats2half2_rn(p02, p03);
                __half2 a2 = __floats2half2_rn(p10, p11);
                __half2 a3 = __floats2half2_rn(p12, p13);
                pa[kk][0] = *(uint32_t*)&a0;
                pa[kk][1] = *(uint32_t*)&a1;
                pa[kk][2] = *(uint32_t*)&a2;
                pa[kk][3] = *(uint32_t*)&a3;
            }
            l0 = l0 * fac0 + ps0;
            l1 = l1 * fac1 + ps1;

#pragma unroll
            for (int nt = 0; nt < 16; nt++) {
                o[nt][0] *= fac0; o[nt][1] *= fac0;
                o[nt][2] *= fac1; o[nt][3] *= fac1;
            }

#pragma unroll
            for (int kk = 0; kk < 4; kk++) {
                uint32_t vb[8][4];
#pragma unroll
                for (int np = 0; np < 8; np++)
                    ldsm4t(vb[np], uVh + vfrag + (kk * 16 * SKP + np * 16) * 2);
#pragma unroll
                for (int nt = 0; nt < 16; nt++)
                    mma16816h(o[nt], pa[kk], &vb[nt >> 1][(nt & 1) * 2]);
            }
        }
        __syncthreads();
    }
#undef FLOAD

    l0 += __shfl_xor_sync(0xffffffffu, l0, 1);
    l0 += __shfl_xor_sync(0xffffffffu, l0, 2);
    l1 += __shfl_xor_sync(0xffffffffu, l1, 1);
    l1 += __shfl_xor_sync(0xffffffffu, l1, 2);
    float inv0 = 1.0f / l0, inv1 = 1.0f / l1;

    size_t row0 = (size_t)b * T_ + rg0;
    size_t row1 = (size_t)b * T_ + rg1;
#pragma unroll
    for (int nt = 0; nt < 16; nt++) {
        int col = h * HD + nt * 8 + tg * 2;
        __half2 h0 = __floats2half2_rn(o[nt][0] * inv0, o[nt][1] * inv0);
        __half2 h1 = __floats2half2_rn(o[nt][2] * inv1, o[nt][3] * inv1);
        *(uint32_t*)(Yh + row0 * C_ + col) = *(uint32_t*)&h0;
        *(uint32_t*)(Yh + row1 * C_ + col) = *(uint32_t*)&h1;
    }
}

// ---------------------------------------------------------------------------
extern "C" void kernel_launch(void* const* d_in, const int* in_sizes, int n_in,
                              void* d_out, int out_size)
{
    const float* x  = (const float*)d_in[0];
    const float* Wq = (const float*)d_in[1];
    const float* Wk = (const float*)d_in[2];
    const float* Wv = (const float*)d_in[3];
    const float* Wo = (const float*)d_in[4];
    const int*  pos = (const int*)d_in[5];
    float* out = (float*)d_out;

    __half *qh, *ql, *kh, *vh;
    cudaGetSymbolAddress((void**)&qh, s_qh); cudaGetSymbolAddress((void**)&ql, s_ql);
    cudaGetSymbolAddress((void**)&kh, s_kh); cudaGetSymbolAddress((void**)&vh, s_vh);
    __half *xh, *xl, *yh, *wqh, *wkh, *wvh, *woh;
    cudaGetSymbolAddress((void**)&xh, s_xh);   cudaGetSymbolAddress((void**)&xl, s_xl);
    cudaGetSymbolAddress((void**)&yh, s_yh);
    cudaGetSymbolAddress((void**)&wqh, s_wqh);
    cudaGetSymbolAddress((void**)&wkh, s_wkh);
    cudaGetSymbolAddress((void**)&wvh, s_wvh);
    cudaGetSymbolAddress((void**)&woh, s_woh);

    cudaFuncSetAttribute(qkv_gemm, cudaFuncAttributeMaxDynamicSharedMemorySize,
                         QKV_SMEM);
    cudaFuncSetAttribute(gemm_mma1, cudaFuncAttributeMaxDynamicSharedMemorySize,
                         G1_SMEM);
    cudaFuncSetAttribute(flash_mma, cudaFuncAttributeMaxDynamicSharedMemorySize,
                         FL_SMEM);

    {
        int n4 = M_ * C_ / 4;
        split_kernel<<<(n4 + 255) / 256, 256>>>(x, xh, xl, n4);
    }
    transpose_all_kernel<<<dim3(C_ / 32, C_ / 32, 4), dim3(32, 8)>>>(
        Wq, Wk, Wv, Wo, wqh, wkh, wvh, woh);

    qkv_gemm<<<dim3(24, M_ / 128), 256, QKV_SMEM>>>(xh, xl, wqh, wkh, wvh,
                                                    qh, ql, kh, vh, pos);

    flash_mma<<<dim3(T_ / 64, NH, B_), 128, FL_SMEM>>>(qh, ql, kh, vh, yh);

    gemm_mma1<<<dim3(C_ / 128, M_ / 128), 256, G1_SMEM>>>(yh, woh, out, C_, C_);
}

// round 14
// speedup vs baseline: 2.0752x; 1.2081x over previous
#include <cuda_runtime.h>
#include <cuda_fp16.h>
#include <math.h>
#include <stdint.h>

#define B_   4
#define T_   2048
#define C_   2048
#define NH   16
#define NKV  4
#define HD   128
#define KVD  (NKV*HD)   // 512
#define M_   (B_*T_)    // 8192

// ---------------- scratch (__device__ globals; no allocs allowed) ----------
__device__ __half s_qh[(size_t)M_ * C_];
__device__ __half s_kh[(size_t)M_ * KVD];
__device__ __half s_vh[(size_t)M_ * KVD];

__device__ __half s_xh[(size_t)M_ * C_];
__device__ __half s_yh[(size_t)M_ * C_];
__device__ __half s_wqh[(size_t)C_ * C_];
__device__ __half s_wkh[(size_t)KVD * C_];
__device__ __half s_wvh[(size_t)KVD * C_];
__device__ __half s_woh[(size_t)C_ * C_];

// ---------------- helpers ---------------------------------------------------
__device__ __forceinline__ uint32_t smem_u32(const void* p) {
    uint32_t a;
    asm("{ .reg .u64 t; cvta.to.shared.u64 t, %1; cvt.u32.u64 %0, t; }"
        : "=r"(a) : "l"(p));
    return a;
}
__device__ __forceinline__ void ldsm4(uint32_t* r, uint32_t addr) {
    asm volatile("ldmatrix.sync.aligned.m8n8.x4.shared.b16 {%0,%1,%2,%3}, [%4];"
                 : "=r"(r[0]), "=r"(r[1]), "=r"(r[2]), "=r"(r[3]) : "r"(addr));
}
__device__ __forceinline__ void ldsm4t(uint32_t* r, uint32_t addr) {
    asm volatile("ldmatrix.sync.aligned.m8n8.x4.trans.shared.b16 {%0,%1,%2,%3}, [%4];"
                 : "=r"(r[0]), "=r"(r[1]), "=r"(r[2]), "=r"(r[3]) : "r"(addr));
}
__device__ __forceinline__ void mma16816h(float* c, const uint32_t* a,
                                          const uint32_t* b) {
    asm volatile(
        "mma.sync.aligned.m16n8k16.row.col.f32.f16.f16.f32 "
        "{%0,%1,%2,%3}, {%4,%5,%6,%7}, {%8,%9}, {%0,%1,%2,%3};"
        : "+f"(c[0]), "+f"(c[1]), "+f"(c[2]), "+f"(c[3])
        : "r"(a[0]), "r"(a[1]), "r"(a[2]), "r"(a[3]), "r"(b[0]), "r"(b[1]));
}
__device__ __forceinline__ void cpa16(uint32_t dst, const void* src) {
    asm volatile("cp.async.cg.shared.global [%0], [%1], 16;"
                 :: "r"(dst), "l"(src));
}
__device__ __forceinline__ void cp_commit() {
    asm volatile("cp.async.commit_group;");
}
__device__ __forceinline__ void cp_wait0() {
    asm volatile("cp.async.wait_group 0;" ::: "memory");
}
__device__ __forceinline__ void cp_wait1() {
    asm volatile("cp.async.wait_group 1;" ::: "memory");
}

// ---------------------------------------------------------------------------
// convert: fp32 -> fp16, vectorized x4
// ---------------------------------------------------------------------------
__global__ void convert_kernel(const float* __restrict__ X,
                               __half* __restrict__ H, int n4)
{
    int i = blockIdx.x * blockDim.x + threadIdx.x;
    if (i >= n4) return;
    float4 v = ((const float4*)X)[i];
    __half2 h0 = __floats2half2_rn(v.x, v.y);
    __half2 h1 = __floats2half2_rn(v.z, v.w);
    ((__half2*)H)[2 * i]     = h0;
    ((__half2*)H)[2 * i + 1] = h1;
}

// ---------------------------------------------------------------------------
// merged transpose: all four weights in one launch (grid.z selects tensor)
// ---------------------------------------------------------------------------
__global__ void transpose_all_kernel(
    const float* __restrict__ Wq, const float* __restrict__ Wk,
    const float* __restrict__ Wv, const float* __restrict__ Wo,
    __half* __restrict__ Tq, __half* __restrict__ Tk,
    __half* __restrict__ Tv, __half* __restrict__ To)
{
    const int z = blockIdx.z;
    const float* W;
    __half* Th;
    int N;
    if (z == 0)      { W = Wq; Th = Tq; N = C_; }
    else if (z == 1) { W = Wk; Th = Tk; N = KVD; }
    else if (z == 2) { W = Wv; Th = Tv; N = KVD; }
    else             { W = Wo; Th = To; N = C_; }
    const int K = C_;
    const int n0 = blockIdx.x * 32, k0 = blockIdx.y * 32;
    if (n0 >= N) return;

    __shared__ float t[32][33];
    int tx = threadIdx.x, ty = threadIdx.y;  // 32 x 8
#pragma unroll
    for (int j = 0; j < 4; j++)
        t[ty + 8 * j][tx] = W[(size_t)(k0 + ty + 8 * j) * N + n0 + tx];
    __syncthreads();
#pragma unroll
    for (int j = 0; j < 4; j++)
        Th[(size_t)(n0 + ty + 8 * j) * K + k0 + tx] =
            __float2half(t[tx][ty + 8 * j]);
}

// ---------------------------------------------------------------------------
// Fused QKV projection + RoPE, single-pass fp16; double-buffered smem.
// Grid x: 0-15 Q, 16-19 K, 20-23 V. CTA 128x128, BK=32.
// ---------------------------------------------------------------------------
#define SAS   40
#define GBUF  (128 * SAS * 2)
#define GSTG2 (2 * GBUF)
#define GEMM_SMEM (2 * GSTG2)

extern __shared__ char dynsm[];

__global__ __launch_bounds__(256) void qkv_gemm(
    const __half* __restrict__ Ah,
    const __half* __restrict__ Wqh, const __half* __restrict__ Wkh,
    const __half* __restrict__ Wvh,
    __half* __restrict__ Qh, __half* __restrict__ Kh, __half* __restrict__ Vh,
    const int* __restrict__ posp)
{
    const int K = C_;
    const int tid = threadIdx.x;
    const int lane = tid & 31, wid = tid >> 5;
    const int wm = wid & 1, wn = wid >> 1;
    const int m0 = blockIdx.y * 128;
    const int nq = blockIdx.x;

    const __half* Bp;
    int mode;                      // 0=Q(rope) 1=K(rope) 2=V
    if (nq < 16)      { Bp = Wqh + (size_t)nq * 128 * K;        mode = 0; }
    else if (nq < 20) { Bp = Wkh + (size_t)(nq - 16) * 128 * K; mode = 1; }
    else              { Bp = Wvh + (size_t)(nq - 20) * 128 * K; mode = 2; }

    const int ldrow = tid >> 1, ldhalf = tid & 1;
    const __half* gAh = Ah + (size_t)(m0 + ldrow) * K + ldhalf * 16;
    const __half* gBh = Bp + (size_t)ldrow * K + ldhalf * 16;
    char* dsm = dynsm + (ldrow * SAS + ldhalf * 16) * 2;

    const int mid = lane >> 3, rin = lane & 7;
    const uint32_t usm = smem_u32(dynsm);
    const uint32_t aoff =
        ((wm * 64 + (mid & 1) * 8 + rin) * SAS + (mid >> 1) * 8) * 2;
    const uint32_t boff =
        ((wn * 16 + (mid >> 1) * 8 + rin) * SAS + (mid & 1) * 8) * 2;
    const uint32_t uAh = usm + aoff;
    const uint32_t uBh = usm + GBUF + boff;

    float acc[4][4][4];
#pragma unroll
    for (int mt = 0; mt < 4; mt++)
#pragma unroll
        for (int nt = 0; nt < 4; nt++)
#pragma unroll
            for (int j = 0; j < 4; j++) acc[mt][nt][j] = 0.0f;

    uint4 rah[2], rbh[2];

#define GLOAD(k0)                                            \
    {                                                        \
        rah[0] = *(const uint4*)(gAh + (k0));                \
        rah[1] = *(const uint4*)(gAh + (k0) + 8);            \
        rbh[0] = *(const uint4*)(gBh + (k0));                \
        rbh[1] = *(const uint4*)(gBh + (k0) + 8);            \
    }
#define SSTORE(stg)                                          \
    {                                                        \
        char* d = dsm + (stg) * GSTG2;                       \
        *(uint4*)(d)             = rah[0];                   \
        *(uint4*)(d + 16)        = rah[1];                   \
        *(uint4*)(d + GBUF)      = rbh[0];                   \
        *(uint4*)(d + GBUF + 16) = rbh[1];                   \
    }

    GLOAD(0);
    SSTORE(0);
    __syncthreads();

    const int nch = K / 32;
    for (int ch = 0; ch < nch; ch++) {
        const bool more = (ch + 1 < nch);
        if (more) GLOAD((ch + 1) * 32);
        const uint32_t so = (ch & 1) * GSTG2;

#pragma unroll
        for (int ks = 0; ks < 2; ks++) {
            uint32_t fah[4][4], fbh[2][4];
#pragma unroll
            for (int mt = 0; mt < 4; mt++)
                ldsm4(fah[mt], uAh + so + mt * (16 * SAS * 2) + ks * 32);
            ldsm4(fbh[0], uBh + so + ks * 32);
            ldsm4(fbh[1], uBh + so + 64 * (SAS * 2) + ks * 32);
#pragma unroll
            for (int mt = 0; mt < 4; mt++)
#pragma unroll
                for (int nt = 0; nt < 4; nt++)
                    mma16816h(acc[mt][nt], fah[mt], &fbh[nt >> 1][(nt & 1) * 2]);
        }
        if (more) {
            SSTORE((ch + 1) & 1);
            __syncthreads();
        }
    }
#undef GLOAD
#undef SSTORE

    const int g = lane >> 2, tg = lane & 3;

    if (mode == 2) {
        const int coff = (nq - 20) * 128;
#pragma unroll
        for (int mt = 0; mt < 4; mt++) {
            const int r0 = m0 + wm * 64 + mt * 16 + g;
#pragma unroll
            for (int nt = 0; nt < 4; nt++) {
                const int c = wn * 16 + (nt & 1) * 8 + ((nt & 2) ? 64 : 0) + tg * 2;
                __half2 h0 = __floats2half2_rn(acc[mt][nt][0], acc[mt][nt][1]);
                __half2 h1 = __floats2half2_rn(acc[mt][nt][2], acc[mt][nt][3]);
                *(uint32_t*)(Vh + (size_t)r0 * KVD + coff + c)       = *(uint32_t*)&h0;
                *(uint32_t*)(Vh + (size_t)(r0 + 8) * KVD + coff + c) = *(uint32_t*)&h1;
            }
        }
        return;
    }

    // Q/K: RoPE on accumulator pairs (nt, nt+2) = cols (c, c+64)
    const int posv = posp[0];
    const float LN1E4_128 = 9.210340371976184f / 128.0f;
#pragma unroll
    for (int mt = 0; mt < 4; mt++) {
        const int mr = m0 + wm * 64 + mt * 16 + g;
#pragma unroll
        for (int nt = 0; nt < 2; nt++) {
            const int c = wn * 16 + nt * 8 + tg * 2;
            const float f1 = __expf(-(float)(2 * (c >> 1)) * LN1E4_128);
            const float f2 = f1 * 0.01f;
#pragma unroll
            for (int rj = 0; rj < 2; rj++) {
                const int row = mr + rj * 8;
                const float pos = (float)(posv + (row & (T_ - 1)));
                const float a1 = pos * f1, a2 = pos * f2;
                const float c1 = cosf(a1), s1 = sinf(a1);
                const float c2 = cosf(a2), s2 = sinf(a2);
                float o1[2], o2[2];
#pragma unroll
                for (int jj = 0; jj < 2; jj++) {
                    const float x1 = acc[mt][nt][rj * 2 + jj];
                    const float x2 = acc[mt][nt + 2][rj * 2 + jj];
                    o1[jj] = x1 * c1 - x2 * s1;
                    o2[jj] = x2 * c2 + x1 * s2;
                }
                __half2 hi1 = __floats2half2_rn(o1[0], o1[1]);
                __half2 hi2 = __floats2half2_rn(o2[0], o2[1]);
                if (mode == 0) {
                    size_t base = (size_t)row * C_ + nq * 128 + c;
                    *(uint32_t*)(Qh + base)      = *(uint32_t*)&hi1;
                    *(uint32_t*)(Qh + base + 64) = *(uint32_t*)&hi2;
                } else {
                    size_t base = (size_t)row * KVD + (nq - 16) * 128 + c;
                    *(uint32_t*)(Kh + base)      = *(uint32_t*)&hi1;
                    *(uint32_t*)(Kh + base + 64) = *(uint32_t*)&hi2;
                }
            }
        }
    }
}

// ---------------------------------------------------------------------------
// fp16 single-pass Wo GEMM; double-buffered smem (R11 proven)
// ---------------------------------------------------------------------------
__global__ __launch_bounds__(256) void gemm_mma1(
    const __half* __restrict__ Ah, const __half* __restrict__ Bh,
    float* __restrict__ C, int N, int K)
{
    const int tid = threadIdx.x;
    const int lane = tid & 31, wid = tid >> 5;
    const int wm = wid & 1, wn = wid >> 1;
    const int m0 = blockIdx.y * 128, n0 = blockIdx.x * 128;

    const int ldrow = tid >> 1, ldhalf = tid & 1;
    const __half* gAh = Ah + (size_t)(m0 + ldrow) * K + ldhalf * 16;
    const __half* gBh = Bh + (size_t)(n0 + ldrow) * K + ldhalf * 16;
    char* dsm = dynsm + (ldrow * SAS + ldhalf * 16) * 2;

    const int mid = lane >> 3, rin = lane & 7;
    const uint32_t usm = smem_u32(dynsm);
    const uint32_t aoff =
        ((wm * 64 + (mid & 1) * 8 + rin) * SAS + (mid >> 1) * 8) * 2;
    const uint32_t boff =
        ((wn * 32 + (mid >> 1) * 8 + rin) * SAS + (mid & 1) * 8) * 2;
    const uint32_t uAh = usm + aoff;
    const uint32_t uBh = usm + GBUF + boff;

    float acc[4][4][4];
#pragma unroll
    for (int mt = 0; mt < 4; mt++)
#pragma unroll
        for (int nt = 0; nt < 4; nt++)
#pragma unroll
            for (int j = 0; j < 4; j++) acc[mt][nt][j] = 0.0f;

    uint4 rah[2], rbh[2];

#define GLOAD(k0)                                            \
    {                                                        \
        rah[0] = *(const uint4*)(gAh + (k0));                \
        rah[1] = *(const uint4*)(gAh + (k0) + 8);            \
        rbh[0] = *(const uint4*)(gBh + (k0));                \
        rbh[1] = *(const uint4*)(gBh + (k0) + 8);            \
    }
#define SSTORE(stg)                                          \
    {                                                        \
        char* d = dsm + (stg) * GSTG2;                       \
        *(uint4*)(d)             = rah[0];                   \
        *(uint4*)(d + 16)        = rah[1];                   \
        *(uint4*)(d + GBUF)      = rbh[0];                   \
        *(uint4*)(d + GBUF + 16) = rbh[1];                   \
    }

    GLOAD(0);
    SSTORE(0);
    __syncthreads();

    const int nch = K / 32;
    for (int ch = 0; ch < nch; ch++) {
        const bool more = (ch + 1 < nch);
        if (more) GLOAD((ch + 1) * 32);
        const uint32_t so = (ch & 1) * GSTG2;

#pragma unroll
        for (int ks = 0; ks < 2; ks++) {
            uint32_t fah[4][4], fbh[2][4];
#pragma unroll
            for (int mt = 0; mt < 4; mt++)
                ldsm4(fah[mt], uAh + so + mt * (16 * SAS * 2) + ks * 32);
#pragma unroll
            for (int np = 0; np < 2; np++)
                ldsm4(fbh[np], uBh + so + np * (16 * SAS * 2) + ks * 32);
#pragma unroll
            for (int mt = 0; mt < 4; mt++)
#pragma unroll
                for (int nt = 0; nt < 4; nt++)
                    mma16816h(acc[mt][nt], fah[mt], &fbh[nt >> 1][(nt & 1) * 2]);
        }
        if (more) {
            SSTORE((ch + 1) & 1);
            __syncthreads();
        }
    }
#undef GLOAD
#undef SSTORE

    const int g = lane >> 2, tg = lane & 3;
#pragma unroll
    for (int mt = 0; mt < 4; mt++) {
        const int mrow = m0 + wm * 64 + mt * 16 + g;
#pragma unroll
        for (int nt = 0; nt < 4; nt++) {
            const int ncol = n0 + wn * 32 + nt * 8 + tg * 2;
            float2 v0 = {acc[mt][nt][0], acc[mt][nt][1]};
            float2 v1 = {acc[mt][nt][2], acc[mt][nt][3]};
            *(float2*)(C + (size_t)mrow * N + ncol)       = v0;
            *(float2*)(C + (size_t)(mrow + 8) * N + ncol) = v1;
        }
    }
}

// ---------------------------------------------------------------------------
// Flash attention: 128-thread CTA (4 warps x 16 rows = 64 q-rows), 2 CTAs/SM,
// cp.async double-buffered K/V, single-pass fp16 QK and PV.
// ---------------------------------------------------------------------------
#define SKP 136
#define FSTG (2 * 64 * SKP * 2)      // one stage: Kh + Vh (34816 B)
#define FL_SMEM (2 * FSTG)

__global__ __launch_bounds__(128) void flash_mma(
    const __half* __restrict__ Qh,
    const __half* __restrict__ Khg, const __half* __restrict__ Vhg,
    __half* __restrict__ Yh)
{
    const int tid = threadIdx.x, lane = tid & 31, w = tid >> 5;
    const int qb = blockIdx.x, h = blockIdx.y, b = blockIdx.z;
    const int kvh = h >> 2;
    const int g = lane >> 2, tg = lane & 3;
    const int mid = lane >> 3, rin = lane & 7;
    const int qrow0 = qb * 64 + w * 16;

    uint32_t qh[8][4];
    {
        const __half* Qhb = Qh + ((size_t)b * T_ + qrow0) * C_ + h * HD;
#pragma unroll
        for (int kc = 0; kc < 8; kc++) {
#pragma unroll
            for (int fr = 0; fr < 4; fr++) {
                int r = g + (fr & 1) * 8;
                int c = kc * 16 + tg * 2 + (fr >> 1) * 8;
                qh[kc][fr] = *(const uint32_t*)(Qhb + (size_t)r * C_ + c);
            }
        }
    }

    float o[16][4];
#pragma unroll
    for (int nt = 0; nt < 16; nt++)
#pragma unroll
        for (int j = 0; j < 4; j++) o[nt][j] = 0.0f;
    float m0 = -INFINITY, m1 = -INFINITY, l0 = 0.0f, l1 = 0.0f;

    const float cscale = 0.08838834764831845f;
    const int rg0 = qrow0 + g, rg1 = rg0 + 8;
    const int ktmax = qb + 1;

    const __half* Kh0 = Khg + (size_t)b * T_ * KVD + kvh * HD;
    const __half* Vh0 = Vhg + (size_t)b * T_ * KVD + kvh * HD;

    const uint32_t usm = smem_u32(dynsm);
    const uint32_t uK = usm, uV = usm + 64 * SKP * 2;
    const uint32_t kfrag = (((mid >> 1) * 8 + rin) * SKP + (mid & 1) * 8) * 2;
    const uint32_t vfrag = (((mid & 1) * 8 + rin) * SKP + (mid >> 1) * 8) * 2;

    const int lr = tid >> 4, lc8 = (tid & 15) << 3;

#define FLOAD(stg, kt)                                                        \
    {                                                                         \
        const __half* Kt = Kh0 + (size_t)(kt) * 64 * KVD;                     \
        const __half* Vt = Vh0 + (size_t)(kt) * 64 * KVD;                     \
        uint32_t base = usm + (stg) * FSTG;                                   \
        _Pragma("unroll")                                                     \
        for (int it = 0; it < 8; it++) {                                      \
            int r = lr + it * 8;                                              \
            uint32_t so = base + (r * SKP + lc8) * 2;                         \
            cpa16(so,                 Kt + (size_t)r * KVD + lc8);            \
            cpa16(so + 64 * SKP * 2,  Vt + (size_t)r * KVD + lc8);            \
        }                                                                     \
        cp_commit();                                                          \
    }

    FLOAD(0, 0);

    for (int kt = 0; kt < ktmax; kt++) {
        const bool more = (kt + 1 < ktmax);
        if (more) FLOAD((kt + 1) & 1, kt + 1);
        if (more) cp_wait1(); else cp_wait0();
        __syncthreads();

        const uint32_t so = (kt & 1) * FSTG;
        const uint32_t uKh = uK + so, uVh = uV + so;

        {
            const bool needmask = (kt * 64 + 63 > qrow0);

            float s[8][4];
#pragma unroll
            for (int nt = 0; nt < 8; nt++)
#pragma unroll
                for (int j = 0; j < 4; j++) s[nt][j] = 0.0f;

#pragma unroll
            for (int kc = 0; kc < 8; kc++) {
                uint32_t bt[4][4];
#pragma unroll
                for (int nt2 = 0; nt2 < 4; nt2++)
                    ldsm4(bt[nt2], uKh + kfrag + (nt2 * 16 * SKP + kc * 16) * 2);
#pragma unroll
                for (int nt = 0; nt < 8; nt++)
                    mma16816h(s[nt], qh[kc], &bt[nt >> 1][(nt & 1) * 2]);
            }

#pragma unroll
            for (int nt = 0; nt < 8; nt++) {
#pragma unroll
                for (int j = 0; j < 4; j++) s[nt][j] *= cscale;
                if (needmask) {
                    int c0 = kt * 64 + nt * 8 + tg * 2;
                    if (c0 > rg0)     s[nt][0] = -1e30f;
                    if (c0 + 1 > rg0) s[nt][1] = -1e30f;
                    if (c0 > rg1)     s[nt][2] = -1e30f;
                    if (c0 + 1 > rg1) s[nt][3] = -1e30f;
                }
            }

            float mn0 = m0, mn1 = m1;
#pragma unroll
            for (int nt = 0; nt < 8; nt++) {
                mn0 = fmaxf(mn0, fmaxf(s[nt][0], s[nt][1]));
                mn1 = fmaxf(mn1, fmaxf(s[nt][2], s[nt][3]));
            }
            mn0 = fmaxf(mn0, __shfl_xor_sync(0xffffffffu, mn0, 1));
            mn0 = fmaxf(mn0, __shfl_xor_sync(0xffffffffu, mn0, 2));
            mn1 = fmaxf(mn1, __shfl_xor_sync(0xffffffffu, mn1, 1));
            mn1 = fmaxf(mn1, __shfl_xor_sync(0xffffffffu, mn1, 2));
            float fac0 = __expf(m0 - mn0), fac1 = __expf(m1 - mn1);
            m0 = mn0; m1 = mn1;

            uint32_t pa[4][4];
            float ps0 = 0.0f, ps1 = 0.0f;
#pragma unroll
            for (int kk = 0; kk < 4; kk++) {
                int nt = 2 * kk;
                float p00 = __expf(s[nt][0] - m0),     p01 = __expf(s[nt][1] - m0);
                float p02 = __expf(s[nt][2] - m1),     p03 = __expf(s[nt][3] - m1);
                float p10 = __expf(s[nt + 1][0] - m0), p11 = __expf(s[nt + 1][1] - m0);
                float p12 = __expf(s[nt + 1][2] - m1), p13 = __expf(s[nt + 1][3] - m1);
                ps0 += p00 + p01 + p10 + p11;
                ps1 += p02 + p03 + p12 + p13;
                __half2 a0 = __floats2half2_rn(p00, p01);
                __half2 a1 = __floats2half2_rn(p02, p03);
                __half2 a2 = __floats2half2_rn(p10, p11);
                __half2 a3 = __floats2half2_rn(p12, p13);
                pa[kk][0] = *(uint32_t*)&a0;
                pa[kk][1] = *(uint32_t*)&a1;
                pa[kk][2] = *(uint32_t*)&a2;
                pa[kk][3] = *(uint32_t*)&a3;
            }
            l0 = l0 * fac0 + ps0;
            l1 = l1 * fac1 + ps1;

#pragma unroll
            for (int nt = 0; nt < 16; nt++) {
                o[nt][0] *= fac0; o[nt][1] *= fac0;
                o[nt][2] *= fac1; o[nt][3] *= fac1;
            }

#pragma unroll
            for (int kk = 0; kk < 4; kk++) {
                uint32_t vb[8][4];
#pragma unroll
                for (int np = 0; np < 8; np++)
                    ldsm4t(vb[np], uVh + vfrag + (kk * 16 * SKP + np * 16) * 2);
#pragma unroll
                for (int nt = 0; nt < 16; nt++)
                    mma16816h(o[nt], pa[kk], &vb[nt >> 1][(nt & 1) * 2]);
            }
        }
        __syncthreads();
    }
#undef FLOAD

    l0 += __shfl_xor_sync(0xffffffffu, l0, 1);
    l0 += __shfl_xor_sync(0xffffffffu, l0, 2);
    l1 += __shfl_xor_sync(0xffffffffu, l1, 1);
    l1 += __shfl_xor_sync(0xffffffffu, l1, 2);
    float inv0 = 1.0f / l0, inv1 = 1.0f / l1;

    size_t row0 = (size_t)b * T_ + rg0;
    size_t row1 = (size_t)b * T_ + rg1;
#pragma unroll
    for (int nt = 0; nt < 16; nt++) {
        int col = h * HD + nt * 8 + tg * 2;
        __half2 h0 = __floats2half2_rn(o[nt][0] * inv0, o[nt][1] * inv0);
        __half2 h1 = __floats2half2_rn(o[nt][2] * inv1, o[nt][3] * inv1);
        *(uint32_t*)(Yh + row0 * C_ + col) = *(uint32_t*)&h0;
        *(uint32_t*)(Yh + row1 * C_ + col) = *(uint32_t*)&h1;
    }
}

// ---------------------------------------------------------------------------
extern "C" void kernel_launch(void* const* d_in, const int* in_sizes, int n_in,
                              void* d_out, int out_size)
{
    const float* x  = (const float*)d_in[0];
    const float* Wq = (const float*)d_in[1];
    const float* Wk = (const float*)d_in[2];
    const float* Wv = (const float*)d_in[3];
    const float* Wo = (const float*)d_in[4];
    const int*  pos = (const int*)d_in[5];
    float* out = (float*)d_out;

    __half *qh, *kh, *vh;
    cudaGetSymbolAddress((void**)&qh, s_qh);
    cudaGetSymbolAddress((void**)&kh, s_kh);
    cudaGetSymbolAddress((void**)&vh, s_vh);
    __half *xh, *yh, *wqh, *wkh, *wvh, *woh;
    cudaGetSymbolAddress((void**)&xh, s_xh);
    cudaGetSymbolAddress((void**)&yh, s_yh);
    cudaGetSymbolAddress((void**)&wqh, s_wqh);
    cudaGetSymbolAddress((void**)&wkh, s_wkh);
    cudaGetSymbolAddress((void**)&wvh, s_wvh);
    cudaGetSymbolAddress((void**)&woh, s_woh);

    cudaFuncSetAttribute(qkv_gemm, cudaFuncAttributeMaxDynamicSharedMemorySize,
                         GEMM_SMEM);
    cudaFuncSetAttribute(gemm_mma1, cudaFuncAttributeMaxDynamicSharedMemorySize,
                         GEMM_SMEM);
    cudaFuncSetAttribute(flash_mma, cudaFuncAttributeMaxDynamicSharedMemorySize,
                         FL_SMEM);

    {
        int n4 = M_ * C_ / 4;
        convert_kernel<<<(n4 + 255) / 256, 256>>>(x, xh, n4);
    }
    transpose_all_kernel<<<dim3(C_ / 32, C_ / 32, 4), dim3(32, 8)>>>(
        Wq, Wk, Wv, Wo, wqh, wkh, wvh, woh);

    qkv_gemm<<<dim3(24, M_ / 128), 256, GEMM_SMEM>>>(xh, wqh, wkh, wvh,
                                                     qh, kh, vh, pos);

    flash_mma<<<dim3(T_ / 64, NH, B_), 128, FL_SMEM>>>(qh, kh, vh, yh);

    gemm_mma1<<<dim3(C_ / 128, M_ / 128), 256, GEMM_SMEM>>>(yh, woh, out, C_, C_);
}